// round 10
// baseline (speedup 1.0000x reference)
#include <cuda_runtime.h>
#include <cuda_fp16.h>
#include <cstdint>
#include <math.h>

#define T_     8192
#define HID_   2048
#define NH_    16
#define HD_    128
#define QC_    512
#define NB_    512
#define MBLK_  16
#define TOPK_  64
#define NIH_   4
#define CI_    64
#define G_     4
#define DG_    512
#define WIN_   256
#define EPS_   1e-6f
#define NEG_   -1e30f
#define SCALE_ 0.08838834764831845f

#define BCATN_ 512   // packed smooth projection width: [swk|swv|kc|kz]
#define SCATN_ 256   // packed fp32 score projection width: [ic|iz|dqb|wih|pad]

#define NBW_   32          // T/WIN sliding-window blocks
#define KW_    (2*WIN_)    // 512 keys per window block
#define KTLD_  (T_ + WIN_) // 8448 padded key columns

typedef __half hlf;

// ---------------- scratch (device globals; no allocation allowed) ----------------
__device__ float g_ccat[T_*BCATN_];
__device__ float g_scatw[HID_*SCATN_];
__device__ float g_scat[T_*SCATN_];
__device__ float g_hc[T_*QC_];
__device__ float g_q[T_*NH_*HD_];
__device__ float g_qT[NH_*T_*HD_];
__device__ float g_qi[T_*NIH_*CI_];
__device__ float g_kcomp[NB_*CI_];
__device__ float g_ckv[NB_*HD_];
__device__ int   g_topidx[T_*TOPK_];
__device__ float g_topval[T_*TOPK_];
__device__ float g_attn[T_*NH_*HD_];
__device__ float g_o1[T_*G_*DG_];
__device__ float g_S[NH_*NBW_*WIN_*KW_];   // swin scores

// fp16 hi/lo preconverted operands
__device__ hlf g_hh[T_*HID_];
__device__ hlf g_hl[T_*HID_];
__device__ hlf g_hch[T_*QC_];
__device__ hlf g_hcl[T_*QC_];
__device__ hlf g_qTh[NH_*T_*HD_];
__device__ hlf g_qTl[NH_*T_*HD_];
__device__ hlf g_KTh[HD_*KTLD_];           // transposed padded swin K
__device__ hlf g_KTl[HD_*KTLD_];
__device__ hlf g_Vph[KTLD_*HD_];           // padded swin V
__device__ hlf g_Vpl[KTLD_*HD_];
__device__ hlf g_Ph[NH_*NBW_*WIN_*KW_];    // swin probs
__device__ hlf g_Pl[NH_*NBW_*WIN_*KW_];
__device__ hlf g_attnh[T_*NH_*HD_];
__device__ hlf g_attnl[T_*NH_*HD_];
__device__ hlf g_o1h[T_*G_*DG_];
__device__ hlf g_o1l[T_*G_*DG_];
__device__ hlf g_bcath[HID_*BCATN_];
__device__ hlf g_bcatl[HID_*BCATN_];
__device__ hlf g_wqch[HID_*QC_];
__device__ hlf g_wqcl[HID_*QC_];
__device__ hlf g_wquph[QC_*NH_*HD_];
__device__ hlf g_wqupl[QC_*NH_*HD_];
__device__ hlf g_gwh[G_*(NH_/G_)*HD_*DG_];
__device__ hlf g_gwl[G_*(NH_/G_)*HD_*DG_];
__device__ hlf g_fwh[G_*DG_*HID_];
__device__ hlf g_fwl[G_*DG_*HID_];

// ---------------- fp32 -> hi/lo fp16 conversion (float4-vectorized) ----------------
__global__ void cvt_hilo_k(const float* __restrict__ src, hlf* __restrict__ hi,
                           hlf* __restrict__ lo, int n4) {
    int i = blockIdx.x * 256 + threadIdx.x;
    if (i >= n4) return;
    float4 v = ((const float4*)src)[i];
    hlf hx = __float2half_rn(v.x);
    hlf hy = __float2half_rn(v.y);
    hlf hz = __float2half_rn(v.z);
    hlf hw = __float2half_rn(v.w);
    __half2 a, b;
    a.x = hx; a.y = hy;
    b.x = hz; b.y = hw;
    ((__half2*)hi)[2*i]     = a;
    ((__half2*)hi)[2*i + 1] = b;
    __half2 c2, d2;
    c2.x = __float2half_rn(v.x - __half2float(hx));
    c2.y = __float2half_rn(v.y - __half2float(hy));
    d2.x = __float2half_rn(v.z - __half2float(hz));
    d2.y = __float2half_rn(v.w - __half2float(hw));
    ((__half2*)lo)[2*i]     = c2;
    ((__half2*)lo)[2*i + 1] = d2;
}

// ================= fp32 SIMT tiled SGEMM (score path; top-k needs true fp32) =================
template<int BM,int BN,int BK,int TM,int TN>
__global__ void __launch_bounds__((BM/TM)*(BN/TN))
sgemm_k(const float* __restrict__ A, const float* __restrict__ B, float* __restrict__ C,
        int M, int N, int K, int lda, int ldb, int ldc) {
    constexpr int NT = (BM/TM)*(BN/TN);
    __shared__ float As[BK][BM];
    __shared__ float Bs[BK][BN];
    const int tid = threadIdx.x;
    const int bm = blockIdx.y * BM, bn = blockIdx.x * BN;
    const int tx = tid % (BN/TN), ty = tid / (BN/TN);
    float acc[TM][TN];
#pragma unroll
    for (int i = 0; i < TM; i++)
#pragma unroll
        for (int j = 0; j < TN; j++) acc[i][j] = 0.f;

    for (int k0 = 0; k0 < K; k0 += BK) {
        for (int i = tid; i < BM*BK; i += NT) {
            int r = i / BK, c = i % BK;
            As[c][r] = A[(size_t)(bm + r)*lda + k0 + c];
        }
        for (int i = tid; i < BK*BN; i += NT) {
            int r = i / BN, c = i % BN;
            Bs[r][c] = B[(size_t)(k0 + r)*ldb + bn + c];
        }
        __syncthreads();
#pragma unroll
        for (int kk = 0; kk < BK; kk++) {
            float ra[TM], rb[TN];
#pragma unroll
            for (int i = 0; i < TM; i++) ra[i] = As[kk][ty*TM + i];
#pragma unroll
            for (int j = 0; j < TN; j++) rb[j] = Bs[kk][tx*TN + j];
#pragma unroll
            for (int i = 0; i < TM; i++)
#pragma unroll
                for (int j = 0; j < TN; j++) acc[i][j] += ra[i]*rb[j];
        }
        __syncthreads();
    }
#pragma unroll
    for (int i = 0; i < TM; i++) {
        int row = bm + ty*TM + i;
#pragma unroll
        for (int j = 0; j < TN; j++) {
            C[(size_t)row*ldc + bn + tx*TN + j] = acc[i][j];
        }
    }
}

static void launch_score(const float* A, const float* B, float* C,
                         int M, int N, int K, int lda, int ldb, int ldc) {
    dim3 grid((N + 63)/64, (M + 63)/64);
    sgemm_k<64,64,16,4,4><<<grid, 256>>>(A, B, C, M, N, K, lda, ldb, ldc);
}

// ================= fp16-split tensor-core GEMM, preconverted hi/lo, cp.async 2-stage =================
// MODE 0: plain batched.  MODE 1: swin QK.  MODE 2: swin PV (C +=).

#define SA_  (128*40)
#define SB_  (32*136)
#define STG_ (2*SA_ + 2*SB_)
#define SMEMB_ (2*STG_*2)

__device__ __forceinline__ unsigned int smem_u32(const void* p) {
    return (unsigned int)__cvta_generic_to_shared(p);
}

__device__ __forceinline__ void cpa16(unsigned int dst, const void* src) {
    asm volatile("cp.async.cg.shared.global [%0], [%1], 16;" :: "r"(dst), "l"(src));
}

__device__ __forceinline__ void ldm4(unsigned int* r, unsigned int addr) {
    asm volatile("ldmatrix.sync.aligned.m8n8.x4.shared.b16 {%0,%1,%2,%3}, [%4];"
        : "=r"(r[0]), "=r"(r[1]), "=r"(r[2]), "=r"(r[3]) : "r"(addr));
}

__device__ __forceinline__ void ldm4t(unsigned int* r, unsigned int addr) {
    asm volatile("ldmatrix.sync.aligned.m8n8.x4.trans.shared.b16 {%0,%1,%2,%3}, [%4];"
        : "=r"(r[0]), "=r"(r[1]), "=r"(r[2]), "=r"(r[3]) : "r"(addr));
}

__device__ __forceinline__ void mma_f16(float* c, const unsigned int* a,
                                        unsigned int b0, unsigned int b1) {
    asm volatile("mma.sync.aligned.m16n8k16.row.col.f32.f16.f16.f32 "
        "{%0,%1,%2,%3}, {%4,%5,%6,%7}, {%8,%9}, {%0,%1,%2,%3};"
        : "+f"(c[0]), "+f"(c[1]), "+f"(c[2]), "+f"(c[3])
        : "r"(a[0]), "r"(a[1]), "r"(a[2]), "r"(a[3]), "r"(b0), "r"(b1));
}

template<int MODE>
__global__ void __launch_bounds__(256, 1)
mma2_k(const hlf* __restrict__ Ah, const hlf* __restrict__ Al,
       const hlf* __restrict__ Bh, const hlf* __restrict__ Bl,
       float* __restrict__ C, int K, int lda, int ldb, int ldc,
       long aOff, long bOff, long cOff) {
    long z = blockIdx.z;
    long ao, bo, co;
    if (MODE == 0) { ao = z*aOff; bo = z*bOff; co = z*cOff; }
    else if (MODE == 1) {  // QK: A=qT [h][t][d], B=KT [d][pad+t], C=S
        ao = z * (long)(WIN_*HD_);
        bo = (z & (NBW_-1)) * (long)WIN_;
        co = z * (long)(WIN_*KW_);
    } else {               // PV: A=P, B=Vp [pad+t][d], C=attn (+=)
        ao = z * (long)(WIN_*KW_);
        bo = (z & (NBW_-1)) * (long)(WIN_*HD_);
        co = (z & (NBW_-1)) * (long)(WIN_*NH_*HD_) + (z >> 5) * (long)HD_;
    }
    Ah += ao; Al += ao;
    Bh += bo; Bl += bo;
    C  += co;
    extern __shared__ hlf sm[];
    const int tid  = threadIdx.x;
    const int bm   = blockIdx.y * 128;
    const int bn   = blockIdx.x * 128;
    const int warp = tid >> 5;
    const int lane = tid & 31;
    const int wm   = (warp & 1) * 64;
    const int wn   = (warp >> 1) * 32;
    const int lrow = lane & 15;
    const int lb8  = (lane >> 4) << 3;

    float acc[4][4][4];
#pragma unroll
    for (int mi = 0; mi < 4; mi++)
#pragma unroll
        for (int nj = 0; nj < 4; nj++)
#pragma unroll
            for (int e = 0; e < 4; e++) acc[mi][nj][e] = 0.f;

    const int nst = K >> 5;

    auto load_stage = [&](int st, int k0) {
        hlf* sa_h = sm + st*STG_;
        hlf* sa_l = sa_h + SA_;
        hlf* sb_h = sa_l + SA_;
        hlf* sb_l = sb_h + SB_;
#pragma unroll
        for (int j = 0; j < 2; j++) {
            int ci = tid + j*256;
            int r = ci >> 2;
            int col = (ci & 3) << 3;
            cpa16(smem_u32(sa_h + r*40 + col), Ah + (size_t)(bm + r)*lda + k0 + col);
            cpa16(smem_u32(sa_l + r*40 + col), Al + (size_t)(bm + r)*lda + k0 + col);
        }
#pragma unroll
        for (int j = 0; j < 2; j++) {
            int ci = tid + j*256;
            int r = ci >> 4;
            int col = (ci & 15) << 3;
            cpa16(smem_u32(sb_h + r*136 + col), Bh + (size_t)(k0 + r)*ldb + bn + col);
            cpa16(smem_u32(sb_l + r*136 + col), Bl + (size_t)(k0 + r)*ldb + bn + col);
        }
    };

    load_stage(0, 0);
    asm volatile("cp.async.commit_group;");

    for (int s = 0; s < nst; s++) {
        if (s + 1 < nst) load_stage((s + 1) & 1, (s + 1) << 5);
        asm volatile("cp.async.commit_group;");
        asm volatile("cp.async.wait_group 1;");
        __syncthreads();

        hlf* sa_h = sm + (s & 1)*STG_;
        hlf* sa_l = sa_h + SA_;
        hlf* sb_h = sa_l + SA_;
        hlf* sb_l = sb_h + SB_;

#pragma unroll
        for (int kk = 0; kk < 32; kk += 16) {
            unsigned int ah[4][4], al[4][4], bh[2][4], bl[2][4];
#pragma unroll
            for (int mi = 0; mi < 4; mi++) {
                ldm4(ah[mi], smem_u32(sa_h + (wm + mi*16 + lrow)*40 + kk + lb8));
                ldm4(al[mi], smem_u32(sa_l + (wm + mi*16 + lrow)*40 + kk + lb8));
            }
#pragma unroll
            for (int nh = 0; nh < 2; nh++) {
                ldm4t(bh[nh], smem_u32(sb_h + (kk + lrow)*136 + wn + nh*16 + lb8));
                ldm4t(bl[nh], smem_u32(sb_l + (kk + lrow)*136 + wn + nh*16 + lb8));
            }
#pragma unroll
            for (int mi = 0; mi < 4; mi++) {
#pragma unroll
                for (int nj = 0; nj < 4; nj++) {
                    int nh = nj >> 1;
                    int p = (nj & 1) << 1;
                    mma_f16(acc[mi][nj], ah[mi], bh[nh][p], bh[nh][p+1]);
                    mma_f16(acc[mi][nj], ah[mi], bl[nh][p], bl[nh][p+1]);
                    mma_f16(acc[mi][nj], al[mi], bh[nh][p], bh[nh][p+1]);
                }
            }
        }
        __syncthreads();
    }

    const int cr = lane >> 2;
    const int cc = (lane & 3) << 1;
#pragma unroll
    for (int mi = 0; mi < 4; mi++) {
#pragma unroll
        for (int nj = 0; nj < 4; nj++) {
            size_t r0 = (size_t)(bm + wm + mi*16 + cr);
            int col = bn + wn + nj*8 + cc;
            float2 v0; v0.x = acc[mi][nj][0]; v0.y = acc[mi][nj][1];
            float2 v1; v1.x = acc[mi][nj][2]; v1.y = acc[mi][nj][3];
            if (MODE == 2) {
                float2 o0 = *(float2*)(C + r0*ldc + col);
                float2 o1 = *(float2*)(C + (r0 + 8)*ldc + col);
                v0.x += o0.x; v0.y += o0.y;
                v1.x += o1.x; v1.y += o1.y;
            }
            *(float2*)(C + r0*ldc + col)       = v0;
            *(float2*)(C + (r0 + 8)*ldc + col) = v1;
        }
    }
}

static void launch_mma(const hlf* Ah, const hlf* Al, const hlf* Bh, const hlf* Bl,
                       float* C, int M, int N, int K, int lda, int ldb, int ldc,
                       int batch, long aOff, long bOff, long cOff) {
    cudaFuncSetAttribute(mma2_k<0>, cudaFuncAttributeMaxDynamicSharedMemorySize, SMEMB_);
    dim3 grid(N / 128, M / 128, batch);
    mma2_k<0><<<grid, 256, SMEMB_>>>(Ah, Al, Bh, Bl, C, K, lda, ldb, ldc, aOff, bOff, cOff);
}

static void launch_mma1(const hlf* Ah, const hlf* Al, const hlf* Bh, const hlf* Bl,
                        float* C, int M, int N, int K, int lda, int ldb, int ldc) {
    launch_mma(Ah, Al, Bh, Bl, C, M, N, K, lda, ldb, ldc, 1, 0, 0, 0);
}

// ---------------- pack fused smooth weights -> hi/lo fp16 [HID][512] ----------------
__global__ void pack_bcat_k(const float* __restrict__ kp, const float* __restrict__ vp,
                            const float* __restrict__ kw, const float* __restrict__ kz,
                            hlf* __restrict__ oh, hlf* __restrict__ ol) {
    int i = blockIdx.x * 256 + threadIdx.x;
    if (i >= HID_ * BCATN_) return;
    int r = i / BCATN_;
    int c = i % BCATN_;
    float v;
    if      (c < 128) v = kp[r*128 + c];
    else if (c < 256) v = vp[r*128 + c - 128];
    else if (c < 384) v = kw[r*128 + c - 256];
    else              v = kz[r*128 + c - 384];
    hlf h = __float2half_rn(v);
    oh[i] = h;
    ol[i] = __float2half_rn(v - __half2float(h));
}

// ---------------- pack fp32 score weights into ScatW [HID][256] (zero-padded) ----------------
__global__ void pack_scatw_k(const float* __restrict__ iw, const float* __restrict__ iz,
                             const float* __restrict__ dq, const float* __restrict__ ww,
                             float* __restrict__ out) {
    int i = blockIdx.x * 256 + threadIdx.x;
    if (i >= HID_ * SCATN_) return;
    int r = i / SCATN_;
    int c = i % SCATN_;
    float v;
    if      (c < 64)  v = iw[r*64 + c];
    else if (c < 128) v = iz[r*64 + c - 64];
    else if (c < 192) v = dq[r*64 + c - 128];
    else if (c < 196) v = ww[r*4  + c - 192];
    else              v = 0.f;
    out[i] = v;
}

// ---------------- q transform: rope+rmsnorm; writes qT [h][t][d] fp32 + hi/lo fp16 ----------------
__global__ void q_transform_k(const float* __restrict__ q, const float* __restrict__ qnw,
                              float* __restrict__ qT, hlf* __restrict__ qTh, hlf* __restrict__ qTl) {
    int t = blockIdx.y;
    int h = blockIdx.x;
    int d = threadIdx.x;  // 128 threads
    const float* row = q + ((size_t)t*NH_ + h)*HD_;
    float v = row[d];
    float nb = (d < 64) ? row[(d < 32) ? d + 32 : d - 32] : 0.f;
    float ss = v*v;
#pragma unroll
    for (int o = 16; o; o >>= 1) ss += __shfl_xor_sync(0xffffffffu, ss, o);
    __shared__ float red[4];
    if ((d & 31) == 0) red[d >> 5] = ss;
    __syncthreads();
    float tot = red[0] + red[1] + red[2] + red[3];
    float r = rsqrtf(tot * (1.f/HD_) + EPS_);
    float outv;
    if (d < 32) {
        float inv = 1.f / powf(10000.f, (float)d * (1.f/32.f));
        float sn, cs;
        sincosf((float)t * inv, &sn, &cs);
        outv = v*cs - nb*sn;
    } else if (d < 64) {
        int i = d - 32;
        float inv = 1.f / powf(10000.f, (float)i * (1.f/32.f));
        float sn, cs;
        sincosf((float)t * inv, &sn, &cs);
        outv = nb*sn + v*cs;
    } else {
        outv = v;
    }
    outv = outv * r * qnw[d];
    size_t idx = (size_t)h*(T_*HD_) + (size_t)t*HD_ + d;
    qT[idx] = outv;
    hlf hi = __float2half_rn(outv);
    qTh[idx] = hi;
    qTl[idx] = __float2half_rn(outv - __half2float(hi));
}

// ---------------- sw_k transform: rmsnorm+rope -> transposed padded KT hi/lo ----------------
__global__ void k_transform_k(const float* __restrict__ kx, int ld, const float* __restrict__ knw,
                              hlf* __restrict__ KTh, hlf* __restrict__ KTl) {
    int t = blockIdx.x;
    int d = threadIdx.x;  // 128 threads
    const float* row = kx + (size_t)t*ld;
    float v = row[d];
    float ss = v*v;
#pragma unroll
    for (int o = 16; o; o >>= 1) ss += __shfl_xor_sync(0xffffffffu, ss, o);
    __shared__ float red[4];
    __shared__ float buf[HD_];
    if ((d & 31) == 0) red[d >> 5] = ss;
    __syncthreads();
    float tot = red[0] + red[1] + red[2] + red[3];
    float nv = v * rsqrtf(tot * (1.f/HD_) + EPS_) * knw[d];
    buf[d] = nv;
    __syncthreads();
    float outv;
    if (d < 32) {
        float inv = 1.f / powf(10000.f, (float)d * (1.f/32.f));
        float sn, cs;
        sincosf((float)t * inv, &sn, &cs);
        outv = buf[d]*cs - buf[d + 32]*sn;
    } else if (d < 64) {
        int i = d - 32;
        float inv = 1.f / powf(10000.f, (float)i * (1.f/32.f));
        float sn, cs;
        sincosf((float)t * inv, &sn, &cs);
        outv = buf[d - 32]*sn + buf[d]*cs;
    } else {
        outv = nv;
    }
    size_t idx = (size_t)d*KTLD_ + (WIN_ + t);
    hlf hi = __float2half_rn(outv);
    KTh[idx] = hi;
    KTl[idx] = __float2half_rn(outv - __half2float(hi));
}

// ---------------- sw_v: Ccat col 128..255 -> padded Vp hi/lo ----------------
__global__ void vpad_k(const float* __restrict__ ccat, hlf* __restrict__ Vph, hlf* __restrict__ Vpl) {
    int i = blockIdx.x * 256 + threadIdx.x;
    if (i >= T_*HD_) return;
    int t = i >> 7;
    int d = i & 127;
    float v = ccat[(size_t)t*BCATN_ + 128 + d];
    size_t idx = (size_t)(WIN_ + t)*HD_ + d;
    hlf hi = __float2half_rn(v);
    Vph[idx] = hi;
    Vpl[idx] = __float2half_rn(v - __half2float(hi));
}

// ---------------- swin masked softmax: S row (512) -> P hi/lo ----------------
__global__ void swin_softmax_k(const float* __restrict__ S, hlf* __restrict__ Ph, hlf* __restrict__ Pl) {
    int rowid = blockIdx.x;
    int tid = threadIdx.x;               // 128 threads
    int q = rowid & (WIN_-1);
    int blk = (rowid >> 8) & (NBW_-1);
    const float* srow = S + (size_t)rowid * KW_;
    float sv[4];
#pragma unroll
    for (int c = 0; c < 4; c++) {
        int j = tid + c*128;
        bool valid = (j > q) && (j - q <= WIN_) && (blk > 0 || j >= WIN_);
        sv[c] = valid ? srow[j]*SCALE_ : NEG_;
    }
    float m = fmaxf(fmaxf(sv[0], sv[1]), fmaxf(sv[2], sv[3]));
#pragma unroll
    for (int o = 16; o; o >>= 1) m = fmaxf(m, __shfl_xor_sync(0xffffffffu, m, o));
    __shared__ float red[4];
    if ((tid & 31) == 0) red[tid >> 5] = m;
    __syncthreads();
    m = fmaxf(fmaxf(red[0], red[1]), fmaxf(red[2], red[3]));
    float e[4];
    float sum = 0.f;
#pragma unroll
    for (int c = 0; c < 4; c++) { e[c] = expf(sv[c] - m); sum += e[c]; }
#pragma unroll
    for (int o = 16; o; o >>= 1) sum += __shfl_xor_sync(0xffffffffu, sum, o);
    __shared__ float red2[4];
    if ((tid & 31) == 0) red2[tid >> 5] = sum;
    __syncthreads();
    sum = red2[0] + red2[1] + red2[2] + red2[3];
    float inv = 1.f / sum;
#pragma unroll
    for (int c = 0; c < 4; c++) {
        int j = tid + c*128;
        float p = e[c] * inv;
        hlf hi = __float2half_rn(p);
        Ph[(size_t)rowid*KW_ + j] = hi;
        Pl[(size_t)rowid*KW_ + j] = __float2half_rn(p - __half2float(hi));
    }
}

// ---------------- compression ----------------
__global__ void compress64_k(const float* __restrict__ cin, const float* __restrict__ zin,
                             int ld, const float* __restrict__ bias, float* __restrict__ out) {
    int n = blockIdx.x;
    int c = threadIdx.x;  // 64 threads
    float z[MBLK_];
    float mx = -INFINITY;
#pragma unroll
    for (int m = 0; m < MBLK_; m++) {
        float v = zin[(size_t)(n*MBLK_ + m)*ld + c] + bias[m*CI_ + c];
        z[m] = v;
        mx = fmaxf(mx, v);
    }
    float sm = 0.f;
#pragma unroll
    for (int m = 0; m < MBLK_; m++) { float e = expf(z[m] - mx); z[m] = e; sm += e; }
    float acc = 0.f;
#pragma unroll
    for (int m = 0; m < MBLK_; m++) acc += z[m] * cin[(size_t)(n*MBLK_ + m)*ld + c];
    out[n*CI_ + c] = acc / sm;
}

__global__ void compress128_norm_k(const float* __restrict__ cin, const float* __restrict__ zin,
                                   int ld, const float* __restrict__ bias,
                                   const float* __restrict__ knw, float* __restrict__ out) {
    int n = blockIdx.x;
    int c = threadIdx.x;  // 128 threads
    float z[MBLK_];
    float mx = -INFINITY;
#pragma unroll
    for (int m = 0; m < MBLK_; m++) {
        float v = zin[(size_t)(n*MBLK_ + m)*ld + c] + bias[m*HD_ + c];
        z[m] = v;
        mx = fmaxf(mx, v);
    }
    float sm = 0.f;
#pragma unroll
    for (int m = 0; m < MBLK_; m++) { float e = expf(z[m] - mx); z[m] = e; sm += e; }
    float acc = 0.f;
#pragma unroll
    for (int m = 0; m < MBLK_; m++) acc += z[m] * cin[(size_t)(n*MBLK_ + m)*ld + c];
    float o = acc / sm;
    float ss = o*o;
#pragma unroll
    for (int oo = 16; oo; oo >>= 1) ss += __shfl_xor_sync(0xffffffffu, ss, oo);
    __shared__ float red[4];
    if ((c & 31) == 0) red[c >> 5] = ss;
    __syncthreads();
    float tot = red[0] + red[1] + red[2] + red[3];
    out[n*HD_ + c] = o * rsqrtf(tot * (1.f/HD_) + EPS_) * knw[c];
}

// ---------------- index scores + top-64 (JAX tie-break: smallest index) ----------------
__global__ void topk_k(const float* __restrict__ qi, const float* __restrict__ wih, int ldw,
                       const float* __restrict__ kcomp,
                       int* __restrict__ topidx, float* __restrict__ topval) {
    int t = blockIdx.x;
    int tid = threadIdx.x;  // 256 threads
    __shared__ float sc[NB_];
    __shared__ float qis[NIH_*CI_];
    __shared__ float wihs[NIH_];
    if (tid < NIH_*CI_) qis[tid] = qi[(size_t)t*NIH_*CI_ + tid];
    if (tid < NIH_)     wihs[tid] = wih[(size_t)t*ldw + tid];
    __syncthreads();
    int nvalid = (t >= MBLK_) ? ((t - MBLK_)/MBLK_ + 1) : 0;
    if (nvalid > NB_) nvalid = NB_;
    for (int n = tid; n < NB_; n += 256) {
        float s;
        if (n < nvalid) {
            s = 0.f;
            const float* kr = kcomp + n*CI_;
#pragma unroll
            for (int h = 0; h < NIH_; h++) {
                const float* qr = qis + h*CI_;
                float dsum = 0.f;
#pragma unroll 8
                for (int cc = 0; cc < CI_; cc++) dsum += qr[cc]*kr[cc];
                s += wihs[h] * fmaxf(dsum, 0.f);
            }
        } else {
            s = -INFINITY;
        }
        sc[n] = s;
    }
    __syncthreads();
    if (tid < 32) {
        for (int j = 0; j < TOPK_; j++) {
            float bv = -INFINITY;
            int bi = NB_;
            for (int n = tid; n < NB_; n += 32) {
                float v = sc[n];
                if (v > bv || (v == bv && n < bi)) { bv = v; bi = n; }
            }
#pragma unroll
            for (int o = 16; o; o >>= 1) {
                float ov = __shfl_xor_sync(0xffffffffu, bv, o);
                int   oi = __shfl_xor_sync(0xffffffffu, bi, o);
                if (ov > bv || (ov == bv && oi < bi)) { bv = ov; bi = oi; }
            }
            if (tid == 0) {
                if (bi >= NB_) { bi = 0; bv = -INFINITY; }
                else sc[bi] = __int_as_float(0x7fc00000);
                topidx[(size_t)t*TOPK_ + j] = bi;
                topval[(size_t)t*TOPK_ + j] = bv;
            }
            __syncwarp();
        }
    }
}

// ---------------- sparse attention over the 64 selected compressed blocks (256 thr, 8 warps) ----------------
__global__ void __launch_bounds__(256)
sparse_attn_k(const float* __restrict__ qT, const float* __restrict__ ckv,
              const int* __restrict__ topidx, const float* __restrict__ topval,
              float* __restrict__ attn) {
    int t = blockIdx.x;
    int tid = threadIdx.x;  // 256 threads, 8 warps
    __shared__ float skv[TOPK_][HD_ + 1];
    __shared__ float qs[NH_][HD_];
    __shared__ float ps[8][TOPK_];
    __shared__ int   sidx[TOPK_];
    __shared__ float svalid[TOPK_];
    __shared__ int   s_any;
    if (tid == 0) s_any = 0;
    __syncthreads();
    if (tid < TOPK_) {
        float v = topval[(size_t)t*TOPK_ + tid];
        int idx = topidx[(size_t)t*TOPK_ + tid];
        bool ok = (v > -1.0e38f);
        sidx[tid] = ok ? idx : 0;
        svalid[tid] = ok ? 1.f : 0.f;
        if (ok) s_any = 1;
    }
    __syncthreads();
    for (int i = tid; i < TOPK_*HD_; i += 256) {
        int r = i >> 7;
        int d = i & 127;
        skv[r][d] = ckv[(size_t)sidx[r]*HD_ + d];
    }
    for (int i = tid; i < NH_*HD_; i += 256) {
        int hh = i >> 7;
        int dd = i & 127;
        qs[hh][dd] = qT[(size_t)hh*(T_*HD_) + (size_t)t*HD_ + dd];
    }
    __syncthreads();
    int w = tid >> 5;
    int lane = tid & 31;
    int any = s_any;
#pragma unroll
    for (int e = 0; e < 2; e++) {
        int hh = e*8 + w;
        float s0 = 0.f, s1 = 0.f;
        for (int d = 0; d < HD_; d++) {
            float qv = qs[hh][d];
            s0 += qv * skv[lane][d];
            s1 += qv * skv[lane + 32][d];
        }
        s0 = (svalid[lane]      > 0.f) ? s0*SCALE_ : NEG_;
        s1 = (svalid[lane + 32] > 0.f) ? s1*SCALE_ : NEG_;
        float mx = fmaxf(s0, s1);
#pragma unroll
        for (int o = 16; o; o >>= 1) mx = fmaxf(mx, __shfl_xor_sync(0xffffffffu, mx, o));
        float e0 = expf(s0 - mx);
        float e1 = expf(s1 - mx);
        float sum = e0 + e1;
#pragma unroll
        for (int o = 16; o; o >>= 1) sum += __shfl_xor_sync(0xffffffffu, sum, o);
        float inv = any ? (1.f/sum) : 0.f;
        ps[w][lane] = e0*inv;
        ps[w][lane + 32] = e1*inv;
        __syncwarp();
        float o0 = 0.f, o1 = 0.f, o2 = 0.f, o3 = 0.f;
        for (int k = 0; k < TOPK_; k++) {
            float p = ps[w][k];
            o0 += p*skv[k][lane];
            o1 += p*skv[k][lane + 32];
            o2 += p*skv[k][lane + 64];
            o3 += p*skv[k][lane + 96];
        }
        size_t base = (size_t)t*(NH_*HD_) + hh*HD_;
        attn[base + lane]      = o0;
        attn[base + lane + 32] = o1;
        attn[base + lane + 64] = o2;
        attn[base + lane + 96] = o3;
        __syncwarp();
    }
}

// ---------------- launch ----------------
static void cvt(const float* src, hlf* hi, hlf* lo, int n) {
    int n4 = n / 4;
    cvt_hilo_k<<<(n4 + 255)/256, 256>>>(src, hi, lo, n4);
}

extern "C" void kernel_launch(void* const* d_in, const int* in_sizes, int n_in,
                              void* d_out, int out_size) {
    const float* h_        = (const float*)d_in[0];
    const float* w_qc      = (const float*)d_in[1];
    const float* w_qup     = (const float*)d_in[2];
    const float* kvc_w     = (const float*)d_in[3];
    const float* kvc_wz    = (const float*)d_in[4];
    const float* kvc_bias  = (const float*)d_in[5];
    const float* k_proj_w  = (const float*)d_in[6];
    const float* v_proj_w  = (const float*)d_in[7];
    const float* idx_c_w   = (const float*)d_in[8];
    const float* idx_c_wz  = (const float*)d_in[9];
    const float* idx_c_bias= (const float*)d_in[10];
    const float* w_dq      = (const float*)d_in[11];
    const float* w_iuq     = (const float*)d_in[12];
    const float* w_w       = (const float*)d_in[13];
    const float* q_norm_w  = (const float*)d_in[14];
    const float* k_norm_w  = (const float*)d_in[15];
    const float* group_w   = (const float*)d_in[16];
    const float* final_w   = (const float*)d_in[17];
    float* out = (float*)d_out;

    float *ccat, *scatw, *scat, *hc, *q, *qT, *qi, *kcomp, *ckv, *topval, *attn, *o1, *S;
    int* topidx;
    hlf *hh, *hl, *hch, *hcl, *qTh, *qTl, *KTh, *KTl, *Vph, *Vpl, *Ph, *Pl;
    hlf *attnh, *attnl, *o1h, *o1l;
    hlf *bcath, *bcatl, *wqch, *wqcl, *wquph, *wqupl, *gwh, *gwl, *fwh, *fwl;
    cudaGetSymbolAddress((void**)&ccat,   g_ccat);
    cudaGetSymbolAddress((void**)&scatw,  g_scatw);
    cudaGetSymbolAddress((void**)&scat,   g_scat);
    cudaGetSymbolAddress((void**)&hc,     g_hc);
    cudaGetSymbolAddress((void**)&q,      g_q);
    cudaGetSymbolAddress((void**)&qT,     g_qT);
    cudaGetSymbolAddress((void**)&qi,     g_qi);
    cudaGetSymbolAddress((void**)&kcomp,  g_kcomp);
    cudaGetSymbolAddress((void**)&ckv,    g_ckv);
    cudaGetSymbolAddress((void**)&topidx, g_topidx);
    cudaGetSymbolAddress((void**)&topval, g_topval);
    cudaGetSymbolAddress((void**)&attn,   g_attn);
    cudaGetSymbolAddress((void**)&o1,     g_o1);
    cudaGetSymbolAddress((void**)&S,      g_S);
    cudaGetSymbolAddress((void**)&hh,     g_hh);
    cudaGetSymbolAddress((void**)&hl,     g_hl);
    cudaGetSymbolAddress((void**)&hch,    g_hch);
    cudaGetSymbolAddress((void**)&hcl,    g_hcl);
    cudaGetSymbolAddress((void**)&qTh,    g_qTh);
    cudaGetSymbolAddress((void**)&qTl,    g_qTl);
    cudaGetSymbolAddress((void**)&KTh,    g_KTh);
    cudaGetSymbolAddress((void**)&KTl,    g_KTl);
    cudaGetSymbolAddress((void**)&Vph,    g_Vph);
    cudaGetSymbolAddress((void**)&Vpl,    g_Vpl);
    cudaGetSymbolAddress((void**)&Ph,     g_Ph);
    cudaGetSymbolAddress((void**)&Pl,     g_Pl);
    cudaGetSymbolAddress((void**)&attnh,  g_attnh);
    cudaGetSymbolAddress((void**)&attnl,  g_attnl);
    cudaGetSymbolAddress((void**)&o1h,    g_o1h);
    cudaGetSymbolAddress((void**)&o1l,    g_o1l);
    cudaGetSymbolAddress((void**)&bcath,  g_bcath);
    cudaGetSymbolAddress((void**)&bcatl,  g_bcatl);
    cudaGetSymbolAddress((void**)&wqch,   g_wqch);
    cudaGetSymbolAddress((void**)&wqcl,   g_wqcl);
    cudaGetSymbolAddress((void**)&wquph,  g_wquph);
    cudaGetSymbolAddress((void**)&wqupl,  g_wqupl);
    cudaGetSymbolAddress((void**)&gwh,    g_gwh);
    cudaGetSymbolAddress((void**)&gwl,    g_gwl);
    cudaGetSymbolAddress((void**)&fwh,    g_fwh);
    cudaGetSymbolAddress((void**)&fwl,    g_fwl);

    // launches 1-5 (ncu -s 5 -c 1 profiles the big packed MMA at #6)
    pack_bcat_k<<<(HID_*BCATN_ + 255)/256, 256>>>(k_proj_w, v_proj_w, kvc_w, kvc_wz, bcath, bcatl);
    cvt(h_,    hh,    hl,    T_*HID_);
    cvt(w_qc,  wqch,  wqcl,  HID_*QC_);
    cvt(w_qup, wquph, wqupl, QC_*NH_*HD_);
    pack_scatw_k<<<(HID_*SCATN_ + 255)/256, 256>>>(idx_c_w, idx_c_wz, w_dq, w_w, scatw);

    // #6: fused smooth projections (tensor): Ccat = [swk|swv|kc|kz]
    launch_mma1(hh, hl, bcath, bcatl, ccat, T_, BCATN_, HID_, HID_, BCATN_, BCATN_);

    // fp32 score projections: Scat = [ic|iz|dqb|wih|pad]
    launch_score(h_, scatw, scat, T_, SCATN_, HID_, HID_, SCATN_, SCATN_);

    // q pipeline
    launch_mma1(hh, hl, wqch, wqcl, hc, T_, QC_, HID_, HID_, QC_, QC_);
    cvt(hc, hch, hcl, T_*QC_);
    launch_mma1(hch, hcl, wquph, wqupl, q, T_, NH_*HD_, QC_, QC_, NH_*HD_, NH_*HD_);
    q_transform_k<<<dim3(NH_, T_), 128>>>(q, q_norm_w, qT, qTh, qTl);

    // swin K/V prep
    k_transform_k<<<T_, 128>>>(ccat, BCATN_, k_norm_w, KTh, KTl);
    vpad_k<<<(T_*HD_ + 255)/256, 256>>>(ccat, Vph, Vpl);

    // kv compression (normalized once)
    compress128_norm_k<<<NB_, 128>>>(ccat + 256, ccat + 384, BCATN_, kvc_bias, k_norm_w, ckv);

    // index compression + index queries (fp32)
    compress64_k<<<NB_, 64>>>(scat, scat + 64, SCATN_, idx_c_bias, kcomp);
    launch_score(scat + 128, w_iuq, qi, T_, NIH_*CI_, CI_, SCATN_, NIH_*CI_, NIH_*CI_);

    // top-64 block selection
    topk_k<<<T_, 256>>>(qi, scat + 192, SCATN_, kcomp, topidx, topval);

    // sparse attention (writes attn)
    sparse_attn_k<<<T_, 256>>>(qT, ckv, topidx, topval, attn);

    // sliding-window attention: QK -> masked softmax -> PV (+= attn)
    {
        cudaFuncSetAttribute(mma2_k<1>, cudaFuncAttributeMaxDynamicSharedMemorySize, SMEMB_);
        cudaFuncSetAttribute(mma2_k<2>, cudaFuncAttributeMaxDynamicSharedMemorySize, SMEMB_);
        dim3 gqk(KW_/128, WIN_/128, NH_*NBW_);
        mma2_k<1><<<gqk, 256, SMEMB_>>>(qTh, qTl, KTh, KTl, S, HD_, HD_, KTLD_, KW_, 0, 0, 0);
        swin_softmax_k<<<NH_*NBW_*WIN_, 128>>>(S, Ph, Pl);
        dim3 gpv(HD_/128, WIN_/128, NH_*NBW_);
        mma2_k<2><<<gpv, 256, SMEMB_>>>(Ph, Pl, Vph, Vpl, attn, KW_, KW_, HD_, NH_*HD_, 0, 0, 0);
    }

    // output projections
    cvt(attn, attnh, attnl, T_*NH_*HD_);
    cvt(group_w, gwh, gwl, G_*(NH_/G_)*HD_*DG_);
    launch_mma(attnh, attnl, gwh, gwl, o1, T_, DG_, (NH_/G_)*HD_, NH_*HD_, DG_, G_*DG_,
               G_, 512, (long)512*512, 512);
    cvt(o1, o1h, o1l, T_*G_*DG_);
    cvt(final_w, fwh, fwl, G_*DG_*HID_);
    launch_mma1(o1h, o1l, fwh, fwl, out, T_, HID_, G_*DG_, G_*DG_, HID_, HID_);
}

// round 12
// speedup vs baseline: 1.0460x; 1.0460x over previous
#include <cuda_runtime.h>
#include <cuda_fp16.h>
#include <cstdint>
#include <math.h>

#define T_     8192
#define HID_   2048
#define NH_    16
#define HD_    128
#define QC_    512
#define NB_    512
#define MBLK_  16
#define TOPK_  64
#define NIH_   4
#define CI_    64
#define G_     4
#define DG_    512
#define WIN_   256
#define EPS_   1e-6f
#define NEG_   -1e30f
#define SCALE_ 0.08838834764831845f

#define BCATN_ 512   // packed smooth projection width: [swk|swv|kc|kz]
#define SCATN_ 256   // packed fp32 score projection width: [ic|iz|dqb|wih|pad]

#define NBW_   32          // T/WIN sliding-window blocks
#define KW_    (2*WIN_)    // 512 keys per window block
#define KTLD_  (T_ + WIN_) // 8448 padded key columns

typedef __half hlf;

// ---------------- scratch (device globals; no allocation allowed) ----------------
__device__ float g_ccat[T_*BCATN_];
__device__ float g_scatw[HID_*SCATN_];
__device__ float g_scat[T_*SCATN_];
__device__ float g_q[T_*NH_*HD_];
__device__ float g_qT[NH_*T_*HD_];
__device__ float g_qi[T_*NIH_*CI_];
__device__ float g_kcomp[NB_*CI_];
__device__ float g_ckv[NB_*HD_];
__device__ int   g_topidx[T_*TOPK_];
__device__ float g_topval[T_*TOPK_];
__device__ float g_attn[T_*NH_*HD_];
__device__ float g_S[NH_*NBW_*WIN_*KW_];   // swin scores

// fp16 hi/lo preconverted operands
__device__ hlf g_hh[T_*HID_];
__device__ hlf g_hl[T_*HID_];
__device__ hlf g_hch[T_*QC_];
__device__ hlf g_hcl[T_*QC_];
__device__ hlf g_qTh[NH_*T_*HD_];
__device__ hlf g_qTl[NH_*T_*HD_];
__device__ hlf g_KTh[HD_*KTLD_];           // transposed padded swin K
__device__ hlf g_KTl[HD_*KTLD_];
__device__ hlf g_Vph[KTLD_*HD_];           // padded swin V
__device__ hlf g_Vpl[KTLD_*HD_];
__device__ hlf g_Ph[NH_*NBW_*WIN_*KW_];    // swin probs
__device__ hlf g_Pl[NH_*NBW_*WIN_*KW_];
__device__ hlf g_attnh[T_*NH_*HD_];
__device__ hlf g_attnl[T_*NH_*HD_];
__device__ hlf g_bcath[HID_*BCATN_];
__device__ hlf g_bcatl[HID_*BCATN_];
__device__ hlf g_wqch[HID_*QC_];
__device__ hlf g_wqcl[HID_*QC_];
__device__ hlf g_wquph[QC_*NH_*HD_];
__device__ hlf g_wqupl[QC_*NH_*HD_];
__device__ hlf g_gwh[G_*(NH_/G_)*HD_*DG_];
__device__ hlf g_gwl[G_*(NH_/G_)*HD_*DG_];
__device__ hlf g_fwh[G_*DG_*HID_];
__device__ hlf g_fwl[G_*DG_*HID_];
__device__ hlf g_wcath[HID_*HID_];         // fused (group @ final) weight hi/lo
__device__ hlf g_wcatl[HID_*HID_];

// ---------------- fp32 -> hi/lo fp16 conversion (float4-vectorized) ----------------
__global__ void cvt_hilo_k(const float* __restrict__ src, hlf* __restrict__ hi,
                           hlf* __restrict__ lo, int n4) {
    int i = blockIdx.x * 256 + threadIdx.x;
    if (i >= n4) return;
    float4 v = ((const float4*)src)[i];
    hlf hx = __float2half_rn(v.x);
    hlf hy = __float2half_rn(v.y);
    hlf hz = __float2half_rn(v.z);
    hlf hw = __float2half_rn(v.w);
    __half2 a, b;
    a.x = hx; a.y = hy;
    b.x = hz; b.y = hw;
    ((__half2*)hi)[2*i]     = a;
    ((__half2*)hi)[2*i + 1] = b;
    __half2 c2, d2;
    c2.x = __float2half_rn(v.x - __half2float(hx));
    c2.y = __float2half_rn(v.y - __half2float(hy));
    d2.x = __float2half_rn(v.z - __half2float(hz));
    d2.y = __float2half_rn(v.w - __half2float(hw));
    ((__half2*)lo)[2*i]     = c2;
    ((__half2*)lo)[2*i + 1] = d2;
}

// ================= fp32 SIMT tiled SGEMM (score path; top-k needs true fp32) =================
template<int BM,int BN,int BK,int TM,int TN>
__global__ void __launch_bounds__((BM/TM)*(BN/TN))
sgemm_k(const float* __restrict__ A, const float* __restrict__ B, float* __restrict__ C,
        int M, int N, int K, int lda, int ldb, int ldc) {
    constexpr int NT = (BM/TM)*(BN/TN);
    __shared__ float As[BK][BM];
    __shared__ float Bs[BK][BN];
    const int tid = threadIdx.x;
    const int bm = blockIdx.y * BM, bn = blockIdx.x * BN;
    const int tx = tid % (BN/TN), ty = tid / (BN/TN);
    float acc[TM][TN];
#pragma unroll
    for (int i = 0; i < TM; i++)
#pragma unroll
        for (int j = 0; j < TN; j++) acc[i][j] = 0.f;

    for (int k0 = 0; k0 < K; k0 += BK) {
        for (int i = tid; i < BM*BK; i += NT) {
            int r = i / BK, c = i % BK;
            As[c][r] = A[(size_t)(bm + r)*lda + k0 + c];
        }
        for (int i = tid; i < BK*BN; i += NT) {
            int r = i / BN, c = i % BN;
            Bs[r][c] = B[(size_t)(k0 + r)*ldb + bn + c];
        }
        __syncthreads();
#pragma unroll
        for (int kk = 0; kk < BK; kk++) {
            float ra[TM], rb[TN];
#pragma unroll
            for (int i = 0; i < TM; i++) ra[i] = As[kk][ty*TM + i];
#pragma unroll
            for (int j = 0; j < TN; j++) rb[j] = Bs[kk][tx*TN + j];
#pragma unroll
            for (int i = 0; i < TM; i++)
#pragma unroll
                for (int j = 0; j < TN; j++) acc[i][j] += ra[i]*rb[j];
        }
        __syncthreads();
    }
#pragma unroll
    for (int i = 0; i < TM; i++) {
        int row = bm + ty*TM + i;
#pragma unroll
        for (int j = 0; j < TN; j++) {
            C[(size_t)row*ldc + bn + tx*TN + j] = acc[i][j];
        }
    }
}

static void launch_score(const float* A, const float* B, float* C,
                         int M, int N, int K, int lda, int ldb, int ldc) {
    dim3 grid((N + 63)/64, (M + 127)/128);
    sgemm_k<128,64,16,8,4><<<grid, 256>>>(A, B, C, M, N, K, lda, ldb, ldc);
}

// ================= fp16-split tensor-core GEMM, preconverted hi/lo, cp.async 2-stage =================
// MODE 0: plain batched.  MODE 1: swin QK.  MODE 2: swin PV.
// EPI  0: store fp32 C.   EPI 1: store hi/lo only.  EPI 2: read fp32 C, add, store hi/lo only.

#define SA_  (128*40)
#define SB_  (32*136)
#define STG_ (2*SA_ + 2*SB_)
#define SMEMB_ (2*STG_*2)

__device__ __forceinline__ unsigned int smem_u32(const void* p) {
    return (unsigned int)__cvta_generic_to_shared(p);
}

__device__ __forceinline__ void cpa16(unsigned int dst, const void* src) {
    asm volatile("cp.async.cg.shared.global [%0], [%1], 16;" :: "r"(dst), "l"(src));
}

__device__ __forceinline__ void ldm4(unsigned int* r, unsigned int addr) {
    asm volatile("ldmatrix.sync.aligned.m8n8.x4.shared.b16 {%0,%1,%2,%3}, [%4];"
        : "=r"(r[0]), "=r"(r[1]), "=r"(r[2]), "=r"(r[3]) : "r"(addr));
}

__device__ __forceinline__ void ldm4t(unsigned int* r, unsigned int addr) {
    asm volatile("ldmatrix.sync.aligned.m8n8.x4.trans.shared.b16 {%0,%1,%2,%3}, [%4];"
        : "=r"(r[0]), "=r"(r[1]), "=r"(r[2]), "=r"(r[3]) : "r"(addr));
}

__device__ __forceinline__ void mma_f16(float* c, const unsigned int* a,
                                        unsigned int b0, unsigned int b1) {
    asm volatile("mma.sync.aligned.m16n8k16.row.col.f32.f16.f16.f32 "
        "{%0,%1,%2,%3}, {%4,%5,%6,%7}, {%8,%9}, {%0,%1,%2,%3};"
        : "+f"(c[0]), "+f"(c[1]), "+f"(c[2]), "+f"(c[3])
        : "r"(a[0]), "r"(a[1]), "r"(a[2]), "r"(a[3]), "r"(b0), "r"(b1));
}

template<int MODE, int EPI>
__global__ void __launch_bounds__(256, 1)
mma2_k(const hlf* __restrict__ Ah, const hlf* __restrict__ Al,
       const hlf* __restrict__ Bh, const hlf* __restrict__ Bl,
       float* __restrict__ C, hlf* __restrict__ Ch, hlf* __restrict__ Cl,
       int K, int lda, int ldb, int ldc,
       long aOff, long bOff, long cOff) {
    long z = blockIdx.z;
    long ao, bo, co;
    if (MODE == 0) { ao = z*aOff; bo = z*bOff; co = z*cOff; }
    else if (MODE == 1) {  // QK: A=qT [h][t][d], B=KT [d][pad+t], C=S
        ao = z * (long)(WIN_*HD_);
        bo = (z & (NBW_-1)) * (long)WIN_;
        co = z * (long)(WIN_*KW_);
    } else {               // PV: A=P, B=Vp [pad+t][d], C=attn
        ao = z * (long)(WIN_*KW_);
        bo = (z & (NBW_-1)) * (long)(WIN_*HD_);
        co = (z & (NBW_-1)) * (long)(WIN_*NH_*HD_) + (z >> 5) * (long)HD_;
    }
    Ah += ao; Al += ao;
    Bh += bo; Bl += bo;
    C  += co;
    if (EPI != 0) { Ch += co; Cl += co; }
    extern __shared__ hlf sm[];
    const int tid  = threadIdx.x;
    const int bm   = blockIdx.y * 128;
    const int bn   = blockIdx.x * 128;
    const int warp = tid >> 5;
    const int lane = tid & 31;
    const int wm   = (warp & 1) * 64;
    const int wn   = (warp >> 1) * 32;
    const int lrow = lane & 15;
    const int lb8  = (lane >> 4) << 3;

    float acc[4][4][4];
#pragma unroll
    for (int mi = 0; mi < 4; mi++)
#pragma unroll
        for (int nj = 0; nj < 4; nj++)
#pragma unroll
            for (int e = 0; e < 4; e++) acc[mi][nj][e] = 0.f;

    const int nst = K >> 5;

    auto load_stage = [&](int st, int k0) {
        hlf* sa_h = sm + st*STG_;
        hlf* sa_l = sa_h + SA_;
        hlf* sb_h = sa_l + SA_;
        hlf* sb_l = sb_h + SB_;
#pragma unroll
        for (int j = 0; j < 2; j++) {
            int ci = tid + j*256;
            int r = ci >> 2;
            int col = (ci & 3) << 3;
            cpa16(smem_u32(sa_h + r*40 + col), Ah + (size_t)(bm + r)*lda + k0 + col);
            cpa16(smem_u32(sa_l + r*40 + col), Al + (size_t)(bm + r)*lda + k0 + col);
        }
#pragma unroll
        for (int j = 0; j < 2; j++) {
            int ci = tid + j*256;
            int r = ci >> 4;
            int col = (ci & 15) << 3;
            cpa16(smem_u32(sb_h + r*136 + col), Bh + (size_t)(k0 + r)*ldb + bn + col);
            cpa16(smem_u32(sb_l + r*136 + col), Bl + (size_t)(k0 + r)*ldb + bn + col);
        }
    };

    load_stage(0, 0);
    asm volatile("cp.async.commit_group;");

    for (int s = 0; s < nst; s++) {
        if (s + 1 < nst) load_stage((s + 1) & 1, (s + 1) << 5);
        asm volatile("cp.async.commit_group;");
        asm volatile("cp.async.wait_group 1;");
        __syncthreads();

        hlf* sa_h = sm + (s & 1)*STG_;
        hlf* sa_l = sa_h + SA_;
        hlf* sb_h = sa_l + SA_;
        hlf* sb_l = sb_h + SB_;

#pragma unroll
        for (int kk = 0; kk < 32; kk += 16) {
            unsigned int ah[4][4], al[4][4], bh[2][4], bl[2][4];
#pragma unroll
            for (int mi = 0; mi < 4; mi++) {
                ldm4(ah[mi], smem_u32(sa_h + (wm + mi*16 + lrow)*40 + kk + lb8));
                ldm4(al[mi], smem_u32(sa_l + (wm + mi*16 + lrow)*40 + kk + lb8));
            }
#pragma unroll
            for (int nh = 0; nh < 2; nh++) {
                ldm4t(bh[nh], smem_u32(sb_h + (kk + lrow)*136 + wn + nh*16 + lb8));
                ldm4t(bl[nh], smem_u32(sb_l + (kk + lrow)*136 + wn + nh*16 + lb8));
            }
#pragma unroll
            for (int mi = 0; mi < 4; mi++) {
#pragma unroll
                for (int nj = 0; nj < 4; nj++) {
                    int nh = nj >> 1;
                    int p = (nj & 1) << 1;
                    mma_f16(acc[mi][nj], ah[mi], bh[nh][p], bh[nh][p+1]);
                    mma_f16(acc[mi][nj], ah[mi], bl[nh][p], bl[nh][p+1]);
                    mma_f16(acc[mi][nj], al[mi], bh[nh][p], bh[nh][p+1]);
                }
            }
        }
        __syncthreads();
    }

    const int cr = lane >> 2;
    const int cc = (lane & 3) << 1;
#pragma unroll
    for (int mi = 0; mi < 4; mi++) {
#pragma unroll
        for (int nj = 0; nj < 4; nj++) {
            size_t r0 = (size_t)(bm + wm + mi*16 + cr);
            int col = bn + wn + nj*8 + cc;
            float2 v0; v0.x = acc[mi][nj][0]; v0.y = acc[mi][nj][1];
            float2 v1; v1.x = acc[mi][nj][2]; v1.y = acc[mi][nj][3];
            if (EPI == 2) {
                float2 o0 = *(float2*)(C + r0*ldc + col);
                float2 o1 = *(float2*)(C + (r0 + 8)*ldc + col);
                v0.x += o0.x; v0.y += o0.y;
                v1.x += o1.x; v1.y += o1.y;
            }
            if (EPI == 0) {
                *(float2*)(C + r0*ldc + col)       = v0;
                *(float2*)(C + (r0 + 8)*ldc + col) = v1;
            } else {
                __half2 h2, l2;
                h2.x = __float2half_rn(v0.x);
                h2.y = __float2half_rn(v0.y);
                l2.x = __float2half_rn(v0.x - __half2float(h2.x));
                l2.y = __float2half_rn(v0.y - __half2float(h2.y));
                *(__half2*)(Ch + r0*ldc + col) = h2;
                *(__half2*)(Cl + r0*ldc + col) = l2;
                h2.x = __float2half_rn(v1.x);
                h2.y = __float2half_rn(v1.y);
                l2.x = __float2half_rn(v1.x - __half2float(h2.x));
                l2.y = __float2half_rn(v1.y - __half2float(h2.y));
                *(__half2*)(Ch + (r0 + 8)*ldc + col) = h2;
                *(__half2*)(Cl + (r0 + 8)*ldc + col) = l2;
            }
        }
    }
}

template<int MODE, int EPI>
static void launch_mma_t(const hlf* Ah, const hlf* Al, const hlf* Bh, const hlf* Bl,
                         float* C, hlf* Ch, hlf* Cl,
                         int M, int N, int K, int lda, int ldb, int ldc,
                         int batch, long aOff, long bOff, long cOff) {
    cudaFuncSetAttribute(mma2_k<MODE,EPI>, cudaFuncAttributeMaxDynamicSharedMemorySize, SMEMB_);
    dim3 grid(N / 128, M / 128, batch);
    mma2_k<MODE,EPI><<<grid, 256, SMEMB_>>>(Ah, Al, Bh, Bl, C, Ch, Cl,
                                            K, lda, ldb, ldc, aOff, bOff, cOff);
}

// ---------------- pack fused smooth weights -> hi/lo fp16 [HID][512] ----------------
__global__ void pack_bcat_k(const float* __restrict__ kp, const float* __restrict__ vp,
                            const float* __restrict__ kw, const float* __restrict__ kz,
                            hlf* __restrict__ oh, hlf* __restrict__ ol) {
    int i = blockIdx.x * 256 + threadIdx.x;
    if (i >= HID_ * BCATN_) return;
    int r = i / BCATN_;
    int c = i % BCATN_;
    float v;
    if      (c < 128) v = kp[r*128 + c];
    else if (c < 256) v = vp[r*128 + c - 128];
    else if (c < 384) v = kw[r*128 + c - 256];
    else              v = kz[r*128 + c - 384];
    hlf h = __float2half_rn(v);
    oh[i] = h;
    ol[i] = __float2half_rn(v - __half2float(h));
}

// ---------------- pack fp32 score weights into ScatW [HID][256] (zero-padded) ----------------
__global__ void pack_scatw_k(const float* __restrict__ iw, const float* __restrict__ iz,
                             const float* __restrict__ dq, const float* __restrict__ ww,
                             float* __restrict__ out) {
    int i = blockIdx.x * 256 + threadIdx.x;
    if (i >= HID_ * SCATN_) return;
    int r = i / SCATN_;
    int c = i % SCATN_;
    float v;
    if      (c < 64)  v = iw[r*64 + c];
    else if (c < 128) v = iz[r*64 + c - 64];
    else if (c < 192) v = dq[r*64 + c - 128];
    else if (c < 196) v = ww[r*4  + c - 192];
    else              v = 0.f;
    out[i] = v;
}

// ---------------- q transform: rope+rmsnorm; writes qT [h][t][d] fp32 + hi/lo fp16 ----------------
__global__ void q_transform_k(const float* __restrict__ q, const float* __restrict__ qnw,
                              float* __restrict__ qT, hlf* __restrict__ qTh, hlf* __restrict__ qTl) {
    int t = blockIdx.y;
    int h = blockIdx.x;
    int d = threadIdx.x;  // 128 threads
    const float* row = q + ((size_t)t*NH_ + h)*HD_;
    float v = row[d];
    float nb = (d < 64) ? row[(d < 32) ? d + 32 : d - 32] : 0.f;
    float ss = v*v;
#pragma unroll
    for (int o = 16; o; o >>= 1) ss += __shfl_xor_sync(0xffffffffu, ss, o);
    __shared__ float red[4];
    if ((d & 31) == 0) red[d >> 5] = ss;
    __syncthreads();
    float tot = red[0] + red[1] + red[2] + red[3];
    float r = rsqrtf(tot * (1.f/HD_) + EPS_);
    float outv;
    if (d < 32) {
        float inv = 1.f / powf(10000.f, (float)d * (1.f/32.f));
        float sn, cs;
        sincosf((float)t * inv, &sn, &cs);
        outv = v*cs - nb*sn;
    } else if (d < 64) {
        int i = d - 32;
        float inv = 1.f / powf(10000.f, (float)i * (1.f/32.f));
        float sn, cs;
        sincosf((float)t * inv, &sn, &cs);
        outv = nb*sn + v*cs;
    } else {
        outv = v;
    }
    outv = outv * r * qnw[d];
    size_t idx = (size_t)h*(T_*HD_) + (size_t)t*HD_ + d;
    qT[idx] = outv;
    hlf hi = __float2half_rn(outv);
    qTh[idx] = hi;
    qTl[idx] = __float2half_rn(outv - __half2float(hi));
}

// ---------------- sw_k transform: rmsnorm+rope -> transposed padded KT hi/lo ----------------
__global__ void k_transform_k(const float* __restrict__ kx, int ld, const float* __restrict__ knw,
                              hlf* __restrict__ KTh, hlf* __restrict__ KTl) {
    int t = blockIdx.x;
    int d = threadIdx.x;  // 128 threads
    const float* row = kx + (size_t)t*ld;
    float v = row[d];
    float ss = v*v;
#pragma unroll
    for (int o = 16; o; o >>= 1) ss += __shfl_xor_sync(0xffffffffu, ss, o);
    __shared__ float red[4];
    __shared__ float buf[HD_];
    if ((d & 31) == 0) red[d >> 5] = ss;
    __syncthreads();
    float tot = red[0] + red[1] + red[2] + red[3];
    float nv = v * rsqrtf(tot * (1.f/HD_) + EPS_) * knw[d];
    buf[d] = nv;
    __syncthreads();
    float outv;
    if (d < 32) {
        float inv = 1.f / powf(10000.f, (float)d * (1.f/32.f));
        float sn, cs;
        sincosf((float)t * inv, &sn, &cs);
        outv = buf[d]*cs - buf[d + 32]*sn;
    } else if (d < 64) {
        int i = d - 32;
        float inv = 1.f / powf(10000.f, (float)i * (1.f/32.f));
        float sn, cs;
        sincosf((float)t * inv, &sn, &cs);
        outv = buf[d - 32]*sn + buf[d]*cs;
    } else {
        outv = nv;
    }
    size_t idx = (size_t)d*KTLD_ + (WIN_ + t);
    hlf hi = __float2half_rn(outv);
    KTh[idx] = hi;
    KTl[idx] = __float2half_rn(outv - __half2float(hi));
}

// ---------------- sw_v: Ccat col 128..255 -> padded Vp hi/lo ----------------
__global__ void vpad_k(const float* __restrict__ ccat, hlf* __restrict__ Vph, hlf* __restrict__ Vpl) {
    int i = blockIdx.x * 256 + threadIdx.x;
    if (i >= T_*HD_) return;
    int t = i >> 7;
    int d = i & 127;
    float v = ccat[(size_t)t*BCATN_ + 128 + d];
    size_t idx = (size_t)(WIN_ + t)*HD_ + d;
    hlf hi = __float2half_rn(v);
    Vph[idx] = hi;
    Vpl[idx] = __float2half_rn(v - __half2float(hi));
}

// ---------------- swin masked softmax: S row (512) -> P hi/lo ----------------
__global__ void swin_softmax_k(const float* __restrict__ S, hlf* __restrict__ Ph, hlf* __restrict__ Pl) {
    int rowid = blockIdx.x;
    int tid = threadIdx.x;               // 128 threads
    int q = rowid & (WIN_-1);
    int blk = (rowid >> 8) & (NBW_-1);
    const float* srow = S + (size_t)rowid * KW_;
    float sv[4];
#pragma unroll
    for (int c = 0; c < 4; c++) {
        int j = tid + c*128;
        bool valid = (j > q) && (j - q <= WIN_) && (blk > 0 || j >= WIN_);
        sv[c] = valid ? srow[j]*SCALE_ : NEG_;
    }
    float m = fmaxf(fmaxf(sv[0], sv[1]), fmaxf(sv[2], sv[3]));
#pragma unroll
    for (int o = 16; o; o >>= 1) m = fmaxf(m, __shfl_xor_sync(0xffffffffu, m, o));
    __shared__ float red[4];
    if ((tid & 31) == 0) red[tid >> 5] = m;
    __syncthreads();
    m = fmaxf(fmaxf(red[0], red[1]), fmaxf(red[2], red[3]));
    float e[4];
    float sum = 0.f;
#pragma unroll
    for (int c = 0; c < 4; c++) { e[c] = expf(sv[c] - m); sum += e[c]; }
#pragma unroll
    for (int o = 16; o; o >>= 1) sum += __shfl_xor_sync(0xffffffffu, sum, o);
    __shared__ float red2[4];
    if ((tid & 31) == 0) red2[tid >> 5] = sum;
    __syncthreads();
    sum = red2[0] + red2[1] + red2[2] + red2[3];
    float inv = 1.f / sum;
#pragma unroll
    for (int c = 0; c < 4; c++) {
        int j = tid + c*128;
        float p = e[c] * inv;
        hlf hi = __float2half_rn(p);
        Ph[(size_t)rowid*KW_ + j] = hi;
        Pl[(size_t)rowid*KW_ + j] = __float2half_rn(p - __half2float(hi));
    }
}

// ---------------- compression ----------------
__global__ void compress64_k(const float* __restrict__ cin, const float* __restrict__ zin,
                             int ld, const float* __restrict__ bias, float* __restrict__ out) {
    int n = blockIdx.x;
    int c = threadIdx.x;  // 64 threads
    float z[MBLK_];
    float mx = -INFINITY;
#pragma unroll
    for (int m = 0; m < MBLK_; m++) {
        float v = zin[(size_t)(n*MBLK_ + m)*ld + c] + bias[m*CI_ + c];
        z[m] = v;
        mx = fmaxf(mx, v);
    }
    float sm = 0.f;
#pragma unroll
    for (int m = 0; m < MBLK_; m++) { float e = expf(z[m] - mx); z[m] = e; sm += e; }
    float acc = 0.f;
#pragma unroll
    for (int m = 0; m < MBLK_; m++) acc += z[m] * cin[(size_t)(n*MBLK_ + m)*ld + c];
    out[n*CI_ + c] = acc / sm;
}

__global__ void compress128_norm_k(const float* __restrict__ cin, const float* __restrict__ zin,
                                   int ld, const float* __restrict__ bias,
                                   const float* __restrict__ knw, float* __restrict__ out) {
    int n = blockIdx.x;
    int c = threadIdx.x;  // 128 threads
    float z[MBLK_];
    float mx = -INFINITY;
#pragma unroll
    for (int m = 0; m < MBLK_; m++) {
        float v = zin[(size_t)(n*MBLK_ + m)*ld + c] + bias[m*HD_ + c];
        z[m] = v;
        mx = fmaxf(mx, v);
    }
    float sm = 0.f;
#pragma unroll
    for (int m = 0; m < MBLK_; m++) { float e = expf(z[m] - mx); z[m] = e; sm += e; }
    float acc = 0.f;
#pragma unroll
    for (int m = 0; m < MBLK_; m++) acc += z[m] * cin[(size_t)(n*MBLK_ + m)*ld + c];
    float o = acc / sm;
    float ss = o*o;
#pragma unroll
    for (int oo = 16; oo; oo >>= 1) ss += __shfl_xor_sync(0xffffffffu, ss, oo);
    __shared__ float red[4];
    if ((c & 31) == 0) red[c >> 5] = ss;
    __syncthreads();
    float tot = red[0] + red[1] + red[2] + red[3];
    out[n*HD_ + c] = o * rsqrtf(tot * (1.f/HD_) + EPS_) * knw[c];
}

// ---------------- index scores + top-64 (JAX tie-break: smallest index) ----------------
__global__ void topk_k(const float* __restrict__ qi, const float* __restrict__ wih, int ldw,
                       const float* __restrict__ kcomp,
                       int* __restrict__ topidx, float* __restrict__ topval) {
    int t = blockIdx.x;
    int tid = threadIdx.x;  // 256 threads
    __shared__ float sc[NB_];
    __shared__ float qis[NIH_*CI_];
    __shared__ float wihs[NIH_];
    if (tid < NIH_*CI_) qis[tid] = qi[(size_t)t*NIH_*CI_ + tid];
    if (tid < NIH_)     wihs[tid] = wih[(size_t)t*ldw + tid];
    __syncthreads();
    int nvalid = (t >= MBLK_) ? ((t - MBLK_)/MBLK_ + 1) : 0;
    if (nvalid > NB_) nvalid = NB_;
    for (int n = tid; n < NB_; n += 256) {
        float s;
        if (n < nvalid) {
            s = 0.f;
            const float* kr = kcomp + n*CI_;
#pragma unroll
            for (int h = 0; h < NIH_; h++) {
                const float* qr = qis + h*CI_;
                float dsum = 0.f;
#pragma unroll 8
                for (int cc = 0; cc < CI_; cc++) dsum += qr[cc]*kr[cc];
                s += wihs[h] * fmaxf(dsum, 0.f);
            }
        } else {
            s = -INFINITY;
        }
        sc[n] = s;
    }
    __syncthreads();
    if (tid < 32) {
        for (int j = 0; j < TOPK_; j++) {
            float bv = -INFINITY;
            int bi = NB_;
            for (int n = tid; n < NB_; n += 32) {
                float v = sc[n];
                if (v > bv || (v == bv && n < bi)) { bv = v; bi = n; }
            }
#pragma unroll
            for (int o = 16; o; o >>= 1) {
                float ov = __shfl_xor_sync(0xffffffffu, bv, o);
                int   oi = __shfl_xor_sync(0xffffffffu, bi, o);
                if (ov > bv || (ov == bv && oi < bi)) { bv = ov; bi = oi; }
            }
            if (tid == 0) {
                if (bi >= NB_) { bi = 0; bv = -INFINITY; }
                else sc[bi] = __int_as_float(0x7fc00000);
                topidx[(size_t)t*TOPK_ + j] = bi;
                topval[(size_t)t*TOPK_ + j] = bv;
            }
            __syncwarp();
        }
    }
}

// ---------------- sparse attention over the 64 selected compressed blocks ----------------
__global__ void sparse_attn_k(const float* __restrict__ qT, const float* __restrict__ ckv,
                              const int* __restrict__ topidx, const float* __restrict__ topval,
                              float* __restrict__ attn) {
    int t = blockIdx.x;
    int tid = threadIdx.x;  // 128 threads, 4 warps
    __shared__ float skv[TOPK_][HD_ + 1];
    __shared__ float qs[NH_][HD_];
    __shared__ float ps[4][TOPK_];
    __shared__ int   sidx[TOPK_];
    __shared__ float svalid[TOPK_];
    __shared__ int   s_any;
    if (tid == 0) s_any = 0;
    __syncthreads();
    if (tid < TOPK_) {
        float v = topval[(size_t)t*TOPK_ + tid];
        int idx = topidx[(size_t)t*TOPK_ + tid];
        bool ok = (v > -1.0e38f);
        sidx[tid] = ok ? idx : 0;
        svalid[tid] = ok ? 1.f : 0.f;
        if (ok) s_any = 1;
    }
    __syncthreads();
    for (int k = 0; k < TOPK_; k++)
        skv[k][tid] = ckv[(size_t)sidx[k]*HD_ + tid];
    for (int i = tid; i < NH_*HD_; i += 128) {
        int hh = i >> 7;
        int dd = i & 127;
        qs[hh][dd] = qT[(size_t)hh*(T_*HD_) + (size_t)t*HD_ + dd];
    }
    __syncthreads();
    int w = tid >> 5;
    int lane = tid & 31;
    int any = s_any;
#pragma unroll
    for (int e = 0; e < 4; e++) {
        int hh = e*4 + w;
        float s0 = 0.f, s1 = 0.f;
        for (int d = 0; d < HD_; d++) {
            float qv = qs[hh][d];
            s0 += qv * skv[lane][d];
            s1 += qv * skv[lane + 32][d];
        }
        s0 = (svalid[lane]      > 0.f) ? s0*SCALE_ : NEG_;
        s1 = (svalid[lane + 32] > 0.f) ? s1*SCALE_ : NEG_;
        float mx = fmaxf(s0, s1);
#pragma unroll
        for (int o = 16; o; o >>= 1) mx = fmaxf(mx, __shfl_xor_sync(0xffffffffu, mx, o));
        float e0 = expf(s0 - mx);
        float e1 = expf(s1 - mx);
        float sum = e0 + e1;
#pragma unroll
        for (int o = 16; o; o >>= 1) sum += __shfl_xor_sync(0xffffffffu, sum, o);
        float inv = any ? (1.f/sum) : 0.f;
        ps[w][lane] = e0*inv;
        ps[w][lane + 32] = e1*inv;
        __syncwarp();
        float o0 = 0.f, o1 = 0.f, o2 = 0.f, o3 = 0.f;
        for (int k = 0; k < TOPK_; k++) {
            float p = ps[w][k];
            o0 += p*skv[k][lane];
            o1 += p*skv[k][lane + 32];
            o2 += p*skv[k][lane + 64];
            o3 += p*skv[k][lane + 96];
        }
        size_t base = (size_t)t*(NH_*HD_) + hh*HD_;
        attn[base + lane]      = o0;
        attn[base + lane + 32] = o1;
        attn[base + lane + 64] = o2;
        attn[base + lane + 96] = o3;
        __syncwarp();
    }
}

// ---------------- launch ----------------
static void cvt(const float* src, hlf* hi, hlf* lo, int n) {
    int n4 = n / 4;
    cvt_hilo_k<<<(n4 + 255)/256, 256>>>(src, hi, lo, n4);
}

extern "C" void kernel_launch(void* const* d_in, const int* in_sizes, int n_in,
                              void* d_out, int out_size) {
    const float* h_        = (const float*)d_in[0];
    const float* w_qc      = (const float*)d_in[1];
    const float* w_qup     = (const float*)d_in[2];
    const float* kvc_w     = (const float*)d_in[3];
    const float* kvc_wz    = (const float*)d_in[4];
    const float* kvc_bias  = (const float*)d_in[5];
    const float* k_proj_w  = (const float*)d_in[6];
    const float* v_proj_w  = (const float*)d_in[7];
    const float* idx_c_w   = (const float*)d_in[8];
    const float* idx_c_wz  = (const float*)d_in[9];
    const float* idx_c_bias= (const float*)d_in[10];
    const float* w_dq      = (const float*)d_in[11];
    const float* w_iuq     = (const float*)d_in[12];
    const float* w_w       = (const float*)d_in[13];
    const float* q_norm_w  = (const float*)d_in[14];
    const float* k_norm_w  = (const float*)d_in[15];
    const float* group_w   = (const float*)d_in[16];
    const float* final_w   = (const float*)d_in[17];
    float* out = (float*)d_out;

    float *ccat, *scatw, *scat, *q, *qT, *qi, *kcomp, *ckv, *topval, *attn, *S;
    int* topidx;
    hlf *hh, *hl, *hch, *hcl, *qTh, *qTl, *KTh, *KTl, *Vph, *Vpl, *Ph, *Pl;
    hlf *attnh, *attnl;
    hlf *bcath, *bcatl, *wqch, *wqcl, *wquph, *wqupl, *gwh, *gwl, *fwh, *fwl, *wcath, *wcatl;
    cudaGetSymbolAddress((void**)&ccat,   g_ccat);
    cudaGetSymbolAddress((void**)&scatw,  g_scatw);
    cudaGetSymbolAddress((void**)&scat,   g_scat);
    cudaGetSymbolAddress((void**)&q,      g_q);
    cudaGetSymbolAddress((void**)&qT,     g_qT);
    cudaGetSymbolAddress((void**)&qi,     g_qi);
    cudaGetSymbolAddress((void**)&kcomp,  g_kcomp);
    cudaGetSymbolAddress((void**)&ckv,    g_ckv);
    cudaGetSymbolAddress((void**)&topidx, g_topidx);
    cudaGetSymbolAddress((void**)&topval, g_topval);
    cudaGetSymbolAddress((void**)&attn,   g_attn);
    cudaGetSymbolAddress((void**)&S,      g_S);
    cudaGetSymbolAddress((void**)&hh,     g_hh);
    cudaGetSymbolAddress((void**)&hl,     g_hl);
    cudaGetSymbolAddress((void**)&hch,    g_hch);
    cudaGetSymbolAddress((void**)&hcl,    g_hcl);
    cudaGetSymbolAddress((void**)&qTh,    g_qTh);
    cudaGetSymbolAddress((void**)&qTl,    g_qTl);
    cudaGetSymbolAddress((void**)&KTh,    g_KTh);
    cudaGetSymbolAddress((void**)&KTl,    g_KTl);
    cudaGetSymbolAddress((void**)&Vph,    g_Vph);
    cudaGetSymbolAddress((void**)&Vpl,    g_Vpl);
    cudaGetSymbolAddress((void**)&Ph,     g_Ph);
    cudaGetSymbolAddress((void**)&Pl,     g_Pl);
    cudaGetSymbolAddress((void**)&attnh,  g_attnh);
    cudaGetSymbolAddress((void**)&attnl,  g_attnl);
    cudaGetSymbolAddress((void**)&bcath,  g_bcath);
    cudaGetSymbolAddress((void**)&bcatl,  g_bcatl);
    cudaGetSymbolAddress((void**)&wqch,   g_wqch);
    cudaGetSymbolAddress((void**)&wqcl,   g_wqcl);
    cudaGetSymbolAddress((void**)&wquph,  g_wquph);
    cudaGetSymbolAddress((void**)&wqupl,  g_wqupl);
    cudaGetSymbolAddress((void**)&gwh,    g_gwh);
    cudaGetSymbolAddress((void**)&gwl,    g_gwl);
    cudaGetSymbolAddress((void**)&fwh,    g_fwh);
    cudaGetSymbolAddress((void**)&fwl,    g_fwl);
    cudaGetSymbolAddress((void**)&wcath,  g_wcath);
    cudaGetSymbolAddress((void**)&wcatl,  g_wcatl);

    // weight prep
    pack_bcat_k<<<(HID_*BCATN_ + 255)/256, 256>>>(k_proj_w, v_proj_w, kvc_w, kvc_wz, bcath, bcatl);
    cvt(h_,      hh,   hl,   T_*HID_);
    cvt(w_qc,    wqch, wqcl, HID_*QC_);
    cvt(w_qup,   wquph, wqupl, QC_*NH_*HD_);
    pack_scatw_k<<<(HID_*SCATN_ + 255)/256, 256>>>(idx_c_w, idx_c_wz, w_dq, w_w, scatw);
    cvt(group_w, gwh, gwl, G_*(NH_/G_)*HD_*DG_);
    cvt(final_w, fwh, fwl, G_*DG_*HID_);

    // Wcat = stack_g (gw_g @ final_g)  [2048 x 2048], hi/lo written directly
    launch_mma_t<0,1>(gwh, gwl, fwh, fwl, S /*dummy*/, wcath, wcatl,
                      DG_, HID_, (NH_/G_)*HD_,
                      DG_, HID_, HID_,
                      G_, (long)512*512, (long)512*HID_, (long)512*HID_);

    // fused smooth projections (tensor): Ccat = [swk|swv|kc|kz]
    launch_mma_t<0,0>(hh, hl, bcath, bcatl, ccat, (hlf*)0, (hlf*)0,
                      T_, BCATN_, HID_, HID_, BCATN_, BCATN_, 1, 0, 0, 0);

    // fp32 score projections: Scat = [ic|iz|dqb|wih|pad]
    launch_score(h_, scatw, scat, T_, SCATN_, HID_, HID_, SCATN_, SCATN_);

    // q pipeline (hc written directly as hi/lo via EPI=1)
    launch_mma_t<0,1>(hh, hl, wqch, wqcl, S /*dummy*/, hch, hcl,
                      T_, QC_, HID_, HID_, QC_, QC_, 1, 0, 0, 0);
    launch_mma_t<0,0>(hch, hcl, wquph, wqupl, q, (hlf*)0, (hlf*)0,
                      T_, NH_*HD_, QC_, QC_, NH_*HD_, NH_*HD_, 1, 0, 0, 0);
    q_transform_k<<<dim3(NH_, T_), 128>>>(q, q_norm_w, qT, qTh, qTl);

    // swin K/V prep
    k_transform_k<<<T_, 128>>>(ccat, BCATN_, k_norm_w, KTh, KTl);
    vpad_k<<<(T_*HD_ + 255)/256, 256>>>(ccat, Vph, Vpl);

    // kv compression (normalized once)
    compress128_norm_k<<<NB_, 128>>>(ccat + 256, ccat + 384, BCATN_, kvc_bias, k_norm_w, ckv);

    // index compression + index queries (fp32)
    compress64_k<<<NB_, 64>>>(scat, scat + 64, SCATN_, idx_c_bias, kcomp);
    launch_score(scat + 128, w_iuq, qi, T_, NIH_*CI_, CI_, SCATN_, NIH_*CI_, NIH_*CI_);

    // top-64 block selection
    topk_k<<<T_, 256>>>(qi, scat + 192, SCATN_, kcomp, topidx, topval);

    // sparse attention (writes attn fp32)
    sparse_attn_k<<<T_, 128>>>(qT, ckv, topidx, topval, attn);

    // sliding-window attention: QK -> masked softmax -> PV (reads attn, writes attnh/attnl)
    {
        launch_mma_t<1,0>(qTh, qTl, KTh, KTl, S, (hlf*)0, (hlf*)0,
                          WIN_, KW_, HD_, HD_, KTLD_, KW_, NH_*NBW_, 0, 0, 0);
        swin_softmax_k<<<NH_*NBW_*WIN_, 128>>>(S, Ph, Pl);
        launch_mma_t<2,2>(Ph, Pl, Vph, Vpl, attn, attnh, attnl,
                          WIN_, HD_, KW_, KW_, HD_, NH_*HD_, NH_*NBW_, 0, 0, 0);
    }

    // fused output projection: out = attn @ Wcat
    launch_mma_t<0,0>(attnh, attnl, wcath, wcatl, out, (hlf*)0, (hlf*)0,
                      T_, HID_, NH_*HD_, NH_*HD_, HID_, HID_, 1, 0, 0, 0);
}

// round 14
// speedup vs baseline: 1.0466x; 1.0005x over previous
#include <cuda_runtime.h>
#include <cuda_fp16.h>
#include <cstdint>
#include <math.h>

#define T_     8192
#define HID_   2048
#define NH_    16
#define HD_    128
#define QC_    512
#define NB_    512
#define MBLK_  16
#define TOPK_  64
#define NIH_   4
#define CI_    64
#define G_     4
#define DG_    512
#define WIN_   256
#define EPS_   1e-6f
#define NEG_   -1e30f
#define SCALE_ 0.08838834764831845f

#define BCATN_ 512   // packed smooth projection width: [swk|swv|kc|kz]
#define SCATN_ 256   // packed fp32 score projection width: [ic|iz|dqb|wih|pad]

#define NBW_   32          // T/WIN sliding-window blocks
#define KW_    (2*WIN_)    // 512 keys per window block
#define KTLD_  (T_ + WIN_) // 8448 padded key columns

typedef __half hlf;

// ---------------- scratch (device globals; no allocation allowed) ----------------
__device__ float g_ccat[T_*BCATN_];
__device__ float g_scatw[HID_*SCATN_];
__device__ float g_scat[T_*SCATN_];
__device__ float g_q[T_*NH_*HD_];
__device__ float g_qT[NH_*T_*HD_];
__device__ float g_qi[T_*NIH_*CI_];
__device__ float g_kcomp[NB_*CI_];
__device__ float g_ckv[NB_*HD_];
__device__ int   g_topidx[T_*TOPK_];
__device__ float g_topval[T_*TOPK_];
__device__ float g_attn[T_*NH_*HD_];
__device__ float g_S[NH_*NBW_*WIN_*KW_];   // swin scores

// fp16 hi/lo preconverted operands
__device__ hlf g_hh[T_*HID_];
__device__ hlf g_hl[T_*HID_];
__device__ hlf g_hch[T_*QC_];
__device__ hlf g_hcl[T_*QC_];
__device__ hlf g_qTh[NH_*T_*HD_];
__device__ hlf g_qTl[NH_*T_*HD_];
__device__ hlf g_KTh[HD_*KTLD_];           // transposed padded swin K
__device__ hlf g_KTl[HD_*KTLD_];
__device__ hlf g_Vph[KTLD_*HD_];           // padded swin V
__device__ hlf g_Vpl[KTLD_*HD_];
__device__ hlf g_Ph[NH_*NBW_*WIN_*KW_];    // swin probs
__device__ hlf g_Pl[NH_*NBW_*WIN_*KW_];
__device__ hlf g_attnh[T_*NH_*HD_];
__device__ hlf g_attnl[T_*NH_*HD_];
__device__ hlf g_bcath[HID_*BCATN_];
__device__ hlf g_bcatl[HID_*BCATN_];
__device__ hlf g_wqch[HID_*QC_];
__device__ hlf g_wqcl[HID_*QC_];
__device__ hlf g_wquph[QC_*NH_*HD_];
__device__ hlf g_wqupl[QC_*NH_*HD_];
__device__ hlf g_gwh[G_*(NH_/G_)*HD_*DG_];
__device__ hlf g_gwl[G_*(NH_/G_)*HD_*DG_];
__device__ hlf g_fwh[G_*DG_*HID_];
__device__ hlf g_fwl[G_*DG_*HID_];
__device__ hlf g_wcath[HID_*HID_];         // fused (group @ final) weight hi/lo
__device__ hlf g_wcatl[HID_*HID_];

// ---------------- fp32 -> hi/lo fp16 conversion (float4-vectorized) ----------------
__global__ void cvt_hilo_k(const float* __restrict__ src, hlf* __restrict__ hi,
                           hlf* __restrict__ lo, int n4) {
    int i = blockIdx.x * 256 + threadIdx.x;
    if (i >= n4) return;
    float4 v = ((const float4*)src)[i];
    hlf hx = __float2half_rn(v.x);
    hlf hy = __float2half_rn(v.y);
    hlf hz = __float2half_rn(v.z);
    hlf hw = __float2half_rn(v.w);
    __half2 a, b;
    a.x = hx; a.y = hy;
    b.x = hz; b.y = hw;
    ((__half2*)hi)[2*i]     = a;
    ((__half2*)hi)[2*i + 1] = b;
    __half2 c2, d2;
    c2.x = __float2half_rn(v.x - __half2float(hx));
    c2.y = __float2half_rn(v.y - __half2float(hy));
    d2.x = __float2half_rn(v.z - __half2float(hz));
    d2.y = __float2half_rn(v.w - __half2float(hw));
    ((__half2*)lo)[2*i]     = c2;
    ((__half2*)lo)[2*i + 1] = d2;
}

// ================= fp32 SIMT tiled SGEMM (score path; top-k needs true fp32 — FROZEN) =================
template<int BM,int BN,int BK,int TM,int TN>
__global__ void __launch_bounds__((BM/TM)*(BN/TN))
sgemm_k(const float* __restrict__ A, const float* __restrict__ B, float* __restrict__ C,
        int M, int N, int K, int lda, int ldb, int ldc) {
    constexpr int NT = (BM/TM)*(BN/TN);
    __shared__ float As[BK][BM];
    __shared__ float Bs[BK][BN];
    const int tid = threadIdx.x;
    const int bm = blockIdx.y * BM, bn = blockIdx.x * BN;
    const int tx = tid % (BN/TN), ty = tid / (BN/TN);
    float acc[TM][TN];
#pragma unroll
    for (int i = 0; i < TM; i++)
#pragma unroll
        for (int j = 0; j < TN; j++) acc[i][j] = 0.f;

    for (int k0 = 0; k0 < K; k0 += BK) {
        for (int i = tid; i < BM*BK; i += NT) {
            int r = i / BK, c = i % BK;
            As[c][r] = A[(size_t)(bm + r)*lda + k0 + c];
        }
        for (int i = tid; i < BK*BN; i += NT) {
            int r = i / BN, c = i % BN;
            Bs[r][c] = B[(size_t)(k0 + r)*ldb + bn + c];
        }
        __syncthreads();
#pragma unroll
        for (int kk = 0; kk < BK; kk++) {
            float ra[TM], rb[TN];
#pragma unroll
            for (int i = 0; i < TM; i++) ra[i] = As[kk][ty*TM + i];
#pragma unroll
            for (int j = 0; j < TN; j++) rb[j] = Bs[kk][tx*TN + j];
#pragma unroll
            for (int i = 0; i < TM; i++)
#pragma unroll
                for (int j = 0; j < TN; j++) acc[i][j] += ra[i]*rb[j];
        }
        __syncthreads();
    }
#pragma unroll
    for (int i = 0; i < TM; i++) {
        int row = bm + ty*TM + i;
#pragma unroll
        for (int j = 0; j < TN; j++) {
            C[(size_t)row*ldc + bn + tx*TN + j] = acc[i][j];
        }
    }
}

static void launch_score(const float* A, const float* B, float* C,
                         int M, int N, int K, int lda, int ldb, int ldc) {
    dim3 grid((N + 63)/64, (M + 127)/128);
    sgemm_k<128,64,16,8,4><<<grid, 256>>>(A, B, C, M, N, K, lda, ldb, ldc);
}

// ================= fp16-split tensor-core GEMM, preconverted hi/lo, cp.async 2-stage =================
// MODE 0: plain batched.  MODE 1: swin QK.  MODE 2: swin PV.
// EPI  0: store fp32 C.   EPI 1: store hi/lo only.  EPI 2: read fp32 C, add, store hi/lo only.

#define SA_  (128*40)
#define SB_  (32*136)
#define STG_ (2*SA_ + 2*SB_)
#define SMEMB_ (2*STG_*2)

__device__ __forceinline__ unsigned int smem_u32(const void* p) {
    return (unsigned int)__cvta_generic_to_shared(p);
}

__device__ __forceinline__ void cpa16(unsigned int dst, const void* src) {
    asm volatile("cp.async.cg.shared.global [%0], [%1], 16;" :: "r"(dst), "l"(src));
}

__device__ __forceinline__ void ldm4(unsigned int* r, unsigned int addr) {
    asm volatile("ldmatrix.sync.aligned.m8n8.x4.shared.b16 {%0,%1,%2,%3}, [%4];"
        : "=r"(r[0]), "=r"(r[1]), "=r"(r[2]), "=r"(r[3]) : "r"(addr));
}

__device__ __forceinline__ void ldm4t(unsigned int* r, unsigned int addr) {
    asm volatile("ldmatrix.sync.aligned.m8n8.x4.trans.shared.b16 {%0,%1,%2,%3}, [%4];"
        : "=r"(r[0]), "=r"(r[1]), "=r"(r[2]), "=r"(r[3]) : "r"(addr));
}

__device__ __forceinline__ void mma_f16(float* c, const unsigned int* a,
                                        unsigned int b0, unsigned int b1) {
    asm volatile("mma.sync.aligned.m16n8k16.row.col.f32.f16.f16.f32 "
        "{%0,%1,%2,%3}, {%4,%5,%6,%7}, {%8,%9}, {%0,%1,%2,%3};"
        : "+f"(c[0]), "+f"(c[1]), "+f"(c[2]), "+f"(c[3])
        : "r"(a[0]), "r"(a[1]), "r"(a[2]), "r"(a[3]), "r"(b0), "r"(b1));
}

template<int MODE, int EPI>
__global__ void __launch_bounds__(256, 1)
mma2_k(const hlf* __restrict__ Ah, const hlf* __restrict__ Al,
       const hlf* __restrict__ Bh, const hlf* __restrict__ Bl,
       float* __restrict__ C, hlf* __restrict__ Ch, hlf* __restrict__ Cl,
       int K, int lda, int ldb, int ldc,
       long aOff, long bOff, long cOff) {
    long z = blockIdx.z;
    long ao, bo, co;
    if (MODE == 0) { ao = z*aOff; bo = z*bOff; co = z*cOff; }
    else if (MODE == 1) {  // QK: A=qT [h][t][d], B=KT [d][pad+t], C=S
        ao = z * (long)(WIN_*HD_);
        bo = (z & (NBW_-1)) * (long)WIN_;
        co = z * (long)(WIN_*KW_);
    } else {               // PV: A=P, B=Vp [pad+t][d], C=attn
        ao = z * (long)(WIN_*KW_);
        bo = (z & (NBW_-1)) * (long)(WIN_*HD_);
        co = (z & (NBW_-1)) * (long)(WIN_*NH_*HD_) + (z >> 5) * (long)HD_;
    }
    Ah += ao; Al += ao;
    Bh += bo; Bl += bo;
    C  += co;
    if (EPI != 0) { Ch += co; Cl += co; }
    extern __shared__ hlf sm[];
    const int tid  = threadIdx.x;
    const int bm   = blockIdx.y * 128;
    const int bn   = blockIdx.x * 128;
    const int warp = tid >> 5;
    const int lane = tid & 31;
    const int wm   = (warp & 1) * 64;
    const int wn   = (warp >> 1) * 32;
    const int lrow = lane & 15;
    const int lb8  = (lane >> 4) << 3;

    float acc[4][4][4];
#pragma unroll
    for (int mi = 0; mi < 4; mi++)
#pragma unroll
        for (int nj = 0; nj < 4; nj++)
#pragma unroll
            for (int e = 0; e < 4; e++) acc[mi][nj][e] = 0.f;

    const int nst = K >> 5;

    auto load_stage = [&](int st, int k0) {
        hlf* sa_h = sm + st*STG_;
        hlf* sa_l = sa_h + SA_;
        hlf* sb_h = sa_l + SA_;
        hlf* sb_l = sb_h + SB_;
#pragma unroll
        for (int j = 0; j < 2; j++) {
            int ci = tid + j*256;
            int r = ci >> 2;
            int col = (ci & 3) << 3;
            cpa16(smem_u32(sa_h + r*40 + col), Ah + (size_t)(bm + r)*lda + k0 + col);
            cpa16(smem_u32(sa_l + r*40 + col), Al + (size_t)(bm + r)*lda + k0 + col);
        }
#pragma unroll
        for (int j = 0; j < 2; j++) {
            int ci = tid + j*256;
            int r = ci >> 4;
            int col = (ci & 15) << 3;
            cpa16(smem_u32(sb_h + r*136 + col), Bh + (size_t)(k0 + r)*ldb + bn + col);
            cpa16(smem_u32(sb_l + r*136 + col), Bl + (size_t)(k0 + r)*ldb + bn + col);
        }
    };

    load_stage(0, 0);
    asm volatile("cp.async.commit_group;");

    for (int s = 0; s < nst; s++) {
        if (s + 1 < nst) load_stage((s + 1) & 1, (s + 1) << 5);
        asm volatile("cp.async.commit_group;");
        asm volatile("cp.async.wait_group 1;");
        __syncthreads();

        hlf* sa_h = sm + (s & 1)*STG_;
        hlf* sa_l = sa_h + SA_;
        hlf* sb_h = sa_l + SA_;
        hlf* sb_l = sb_h + SB_;

#pragma unroll
        for (int kk = 0; kk < 32; kk += 16) {
            unsigned int ah[4][4], al[4][4], bh[2][4], bl[2][4];
#pragma unroll
            for (int mi = 0; mi < 4; mi++) {
                ldm4(ah[mi], smem_u32(sa_h + (wm + mi*16 + lrow)*40 + kk + lb8));
                ldm4(al[mi], smem_u32(sa_l + (wm + mi*16 + lrow)*40 + kk + lb8));
            }
#pragma unroll
            for (int nh = 0; nh < 2; nh++) {
                ldm4t(bh[nh], smem_u32(sb_h + (kk + lrow)*136 + wn + nh*16 + lb8));
                ldm4t(bl[nh], smem_u32(sb_l + (kk + lrow)*136 + wn + nh*16 + lb8));
            }
#pragma unroll
            for (int mi = 0; mi < 4; mi++) {
#pragma unroll
                for (int nj = 0; nj < 4; nj++) {
                    int nh = nj >> 1;
                    int p = (nj & 1) << 1;
                    mma_f16(acc[mi][nj], ah[mi], bh[nh][p], bh[nh][p+1]);
                    mma_f16(acc[mi][nj], ah[mi], bl[nh][p], bl[nh][p+1]);
                    mma_f16(acc[mi][nj], al[mi], bh[nh][p], bh[nh][p+1]);
                }
            }
        }
        __syncthreads();
    }

    const int cr = lane >> 2;
    const int cc = (lane & 3) << 1;
#pragma unroll
    for (int mi = 0; mi < 4; mi++) {
#pragma unroll
        for (int nj = 0; nj < 4; nj++) {
            size_t r0 = (size_t)(bm + wm + mi*16 + cr);
            int col = bn + wn + nj*8 + cc;
            float2 v0; v0.x = acc[mi][nj][0]; v0.y = acc[mi][nj][1];
            float2 v1; v1.x = acc[mi][nj][2]; v1.y = acc[mi][nj][3];
            if (EPI == 2) {
                float2 o0 = *(float2*)(C + r0*ldc + col);
                float2 o1 = *(float2*)(C + (r0 + 8)*ldc + col);
                v0.x += o0.x; v0.y += o0.y;
                v1.x += o1.x; v1.y += o1.y;
            }
            if (EPI == 0) {
                *(float2*)(C + r0*ldc + col)       = v0;
                *(float2*)(C + (r0 + 8)*ldc + col) = v1;
            } else {
                __half2 h2, l2;
                h2.x = __float2half_rn(v0.x);
                h2.y = __float2half_rn(v0.y);
                l2.x = __float2half_rn(v0.x - __half2float(h2.x));
                l2.y = __float2half_rn(v0.y - __half2float(h2.y));
                *(__half2*)(Ch + r0*ldc + col) = h2;
                *(__half2*)(Cl + r0*ldc + col) = l2;
                h2.x = __float2half_rn(v1.x);
                h2.y = __float2half_rn(v1.y);
                l2.x = __float2half_rn(v1.x - __half2float(h2.x));
                l2.y = __float2half_rn(v1.y - __half2float(h2.y));
                *(__half2*)(Ch + (r0 + 8)*ldc + col) = h2;
                *(__half2*)(Cl + (r0 + 8)*ldc + col) = l2;
            }
        }
    }
}

template<int MODE, int EPI>
static void launch_mma_t(const hlf* Ah, const hlf* Al, const hlf* Bh, const hlf* Bl,
                         float* C, hlf* Ch, hlf* Cl,
                         int M, int N, int K, int lda, int ldb, int ldc,
                         int batch, long aOff, long bOff, long cOff) {
    cudaFuncSetAttribute(mma2_k<MODE,EPI>, cudaFuncAttributeMaxDynamicSharedMemorySize, SMEMB_);
    dim3 grid(N / 128, M / 128, batch);
    mma2_k<MODE,EPI><<<grid, 256, SMEMB_>>>(Ah, Al, Bh, Bl, C, Ch, Cl,
                                            K, lda, ldb, ldc, aOff, bOff, cOff);
}

// ---------------- pack fused smooth weights -> hi/lo fp16 [HID][512] ----------------
__global__ void pack_bcat_k(const float* __restrict__ kp, const float* __restrict__ vp,
                            const float* __restrict__ kw, const float* __restrict__ kz,
                            hlf* __restrict__ oh, hlf* __restrict__ ol) {
    int i = blockIdx.x * 256 + threadIdx.x;
    if (i >= HID_ * BCATN_) return;
    int r = i / BCATN_;
    int c = i % BCATN_;
    float v;
    if      (c < 128) v = kp[r*128 + c];
    else if (c < 256) v = vp[r*128 + c - 128];
    else if (c < 384) v = kw[r*128 + c - 256];
    else              v = kz[r*128 + c - 384];
    hlf h = __float2half_rn(v);
    oh[i] = h;
    ol[i] = __float2half_rn(v - __half2float(h));
}

// ---------------- pack fp32 score weights into ScatW [HID][256] (zero-padded) ----------------
__global__ void pack_scatw_k(const float* __restrict__ iw, const float* __restrict__ iz,
                             const float* __restrict__ dq, const float* __restrict__ ww,
                             float* __restrict__ out) {
    int i = blockIdx.x * 256 + threadIdx.x;
    if (i >= HID_ * SCATN_) return;
    int r = i / SCATN_;
    int c = i % SCATN_;
    float v;
    if      (c < 64)  v = iw[r*64 + c];
    else if (c < 128) v = iz[r*64 + c - 64];
    else if (c < 192) v = dq[r*64 + c - 128];
    else if (c < 196) v = ww[r*4  + c - 192];
    else              v = 0.f;
    out[i] = v;
}

// ---------------- q transform: rope+rmsnorm; writes qT [h][t][d] fp32 + hi/lo fp16 ----------------
__global__ void q_transform_k(const float* __restrict__ q, const float* __restrict__ qnw,
                              float* __restrict__ qT, hlf* __restrict__ qTh, hlf* __restrict__ qTl) {
    int t = blockIdx.y;
    int h = blockIdx.x;
    int d = threadIdx.x;  // 128 threads
    const float* row = q + ((size_t)t*NH_ + h)*HD_;
    float v = row[d];
    float nb = (d < 64) ? row[(d < 32) ? d + 32 : d - 32] : 0.f;
    float ss = v*v;
#pragma unroll
    for (int o = 16; o; o >>= 1) ss += __shfl_xor_sync(0xffffffffu, ss, o);
    __shared__ float red[4];
    if ((d & 31) == 0) red[d >> 5] = ss;
    __syncthreads();
    float tot = red[0] + red[1] + red[2] + red[3];
    float r = rsqrtf(tot * (1.f/HD_) + EPS_);
    float outv;
    if (d < 32) {
        float inv = 1.f / powf(10000.f, (float)d * (1.f/32.f));
        float sn, cs;
        sincosf((float)t * inv, &sn, &cs);
        outv = v*cs - nb*sn;
    } else if (d < 64) {
        int i = d - 32;
        float inv = 1.f / powf(10000.f, (float)i * (1.f/32.f));
        float sn, cs;
        sincosf((float)t * inv, &sn, &cs);
        outv = nb*sn + v*cs;
    } else {
        outv = v;
    }
    outv = outv * r * qnw[d];
    size_t idx = (size_t)h*(T_*HD_) + (size_t)t*HD_ + d;
    qT[idx] = outv;
    hlf hi = __float2half_rn(outv);
    qTh[idx] = hi;
    qTl[idx] = __float2half_rn(outv - __half2float(hi));
}

// ---------------- sw_k transform: rmsnorm+rope -> transposed padded KT hi/lo ----------------
__global__ void k_transform_k(const float* __restrict__ kx, int ld, const float* __restrict__ knw,
                              hlf* __restrict__ KTh, hlf* __restrict__ KTl) {
    int t = blockIdx.x;
    int d = threadIdx.x;  // 128 threads
    const float* row = kx + (size_t)t*ld;
    float v = row[d];
    float ss = v*v;
#pragma unroll
    for (int o = 16; o; o >>= 1) ss += __shfl_xor_sync(0xffffffffu, ss, o);
    __shared__ float red[4];
    __shared__ float buf[HD_];
    if ((d & 31) == 0) red[d >> 5] = ss;
    __syncthreads();
    float tot = red[0] + red[1] + red[2] + red[3];
    float nv = v * rsqrtf(tot * (1.f/HD_) + EPS_) * knw[d];
    buf[d] = nv;
    __syncthreads();
    float outv;
    if (d < 32) {
        float inv = 1.f / powf(10000.f, (float)d * (1.f/32.f));
        float sn, cs;
        sincosf((float)t * inv, &sn, &cs);
        outv = buf[d]*cs - buf[d + 32]*sn;
    } else if (d < 64) {
        int i = d - 32;
        float inv = 1.f / powf(10000.f, (float)i * (1.f/32.f));
        float sn, cs;
        sincosf((float)t * inv, &sn, &cs);
        outv = buf[d - 32]*sn + buf[d]*cs;
    } else {
        outv = nv;
    }
    size_t idx = (size_t)d*KTLD_ + (WIN_ + t);
    hlf hi = __float2half_rn(outv);
    KTh[idx] = hi;
    KTl[idx] = __float2half_rn(outv - __half2float(hi));
}

// ---------------- sw_v: Ccat col 128..255 -> padded Vp hi/lo ----------------
__global__ void vpad_k(const float* __restrict__ ccat, hlf* __restrict__ Vph, hlf* __restrict__ Vpl) {
    int i = blockIdx.x * 256 + threadIdx.x;
    if (i >= T_*HD_) return;
    int t = i >> 7;
    int d = i & 127;
    float v = ccat[(size_t)t*BCATN_ + 128 + d];
    size_t idx = (size_t)(WIN_ + t)*HD_ + d;
    hlf hi = __float2half_rn(v);
    Vph[idx] = hi;
    Vpl[idx] = __float2half_rn(v - __half2float(hi));
}

// ---------------- swin masked softmax: S row (512) -> P hi/lo ----------------
__global__ void swin_softmax_k(const float* __restrict__ S, hlf* __restrict__ Ph, hlf* __restrict__ Pl) {
    int rowid = blockIdx.x;
    int tid = threadIdx.x;               // 128 threads
    int q = rowid & (WIN_-1);
    int blk = (rowid >> 8) & (NBW_-1);
    const float* srow = S + (size_t)rowid * KW_;
    float sv[4];
#pragma unroll
    for (int c = 0; c < 4; c++) {
        int j = tid + c*128;
        bool valid = (j > q) && (j - q <= WIN_) && (blk > 0 || j >= WIN_);
        sv[c] = valid ? srow[j]*SCALE_ : NEG_;
    }
    float m = fmaxf(fmaxf(sv[0], sv[1]), fmaxf(sv[2], sv[3]));
#pragma unroll
    for (int o = 16; o; o >>= 1) m = fmaxf(m, __shfl_xor_sync(0xffffffffu, m, o));
    __shared__ float red[4];
    if ((tid & 31) == 0) red[tid >> 5] = m;
    __syncthreads();
    m = fmaxf(fmaxf(red[0], red[1]), fmaxf(red[2], red[3]));
    float e[4];
    float sum = 0.f;
#pragma unroll
    for (int c = 0; c < 4; c++) { e[c] = expf(sv[c] - m); sum += e[c]; }
#pragma unroll
    for (int o = 16; o; o >>= 1) sum += __shfl_xor_sync(0xffffffffu, sum, o);
    __shared__ float red2[4];
    if ((tid & 31) == 0) red2[tid >> 5] = sum;
    __syncthreads();
    sum = red2[0] + red2[1] + red2[2] + red2[3];
    float inv = 1.f / sum;
#pragma unroll
    for (int c = 0; c < 4; c++) {
        int j = tid + c*128;
        float p = e[c] * inv;
        hlf hi = __float2half_rn(p);
        Ph[(size_t)rowid*KW_ + j] = hi;
        Pl[(size_t)rowid*KW_ + j] = __float2half_rn(p - __half2float(hi));
    }
}

// ---------------- compression ----------------
__global__ void compress64_k(const float* __restrict__ cin, const float* __restrict__ zin,
                             int ld, const float* __restrict__ bias, float* __restrict__ out) {
    int n = blockIdx.x;
    int c = threadIdx.x;  // 64 threads
    float z[MBLK_];
    float mx = -INFINITY;
#pragma unroll
    for (int m = 0; m < MBLK_; m++) {
        float v = zin[(size_t)(n*MBLK_ + m)*ld + c] + bias[m*CI_ + c];
        z[m] = v;
        mx = fmaxf(mx, v);
    }
    float sm = 0.f;
#pragma unroll
    for (int m = 0; m < MBLK_; m++) { float e = expf(z[m] - mx); z[m] = e; sm += e; }
    float acc = 0.f;
#pragma unroll
    for (int m = 0; m < MBLK_; m++) acc += z[m] * cin[(size_t)(n*MBLK_ + m)*ld + c];
    out[n*CI_ + c] = acc / sm;
}

__global__ void compress128_norm_k(const float* __restrict__ cin, const float* __restrict__ zin,
                                   int ld, const float* __restrict__ bias,
                                   const float* __restrict__ knw, float* __restrict__ out) {
    int n = blockIdx.x;
    int c = threadIdx.x;  // 128 threads
    float z[MBLK_];
    float mx = -INFINITY;
#pragma unroll
    for (int m = 0; m < MBLK_; m++) {
        float v = zin[(size_t)(n*MBLK_ + m)*ld + c] + bias[m*HD_ + c];
        z[m] = v;
        mx = fmaxf(mx, v);
    }
    float sm = 0.f;
#pragma unroll
    for (int m = 0; m < MBLK_; m++) { float e = expf(z[m] - mx); z[m] = e; sm += e; }
    float acc = 0.f;
#pragma unroll
    for (int m = 0; m < MBLK_; m++) acc += z[m] * cin[(size_t)(n*MBLK_ + m)*ld + c];
    float o = acc / sm;
    float ss = o*o;
#pragma unroll
    for (int oo = 16; oo; oo >>= 1) ss += __shfl_xor_sync(0xffffffffu, ss, oo);
    __shared__ float red[4];
    if ((c & 31) == 0) red[c >> 5] = ss;
    __syncthreads();
    float tot = red[0] + red[1] + red[2] + red[3];
    out[n*HD_ + c] = o * rsqrtf(tot * (1.f/HD_) + EPS_) * knw[c];
}

// ---------------- index scores + top-64 (JAX tie-break: smallest index) ----------------
__global__ void topk_k(const float* __restrict__ qi, const float* __restrict__ wih, int ldw,
                       const float* __restrict__ kcomp,
                       int* __restrict__ topidx, float* __restrict__ topval) {
    int t = blockIdx.x;
    int tid = threadIdx.x;  // 256 threads
    __shared__ float sc[NB_];
    __shared__ float qis[NIH_*CI_];
    __shared__ float wihs[NIH_];
    if (tid < NIH_*CI_) qis[tid] = qi[(size_t)t*NIH_*CI_ + tid];
    if (tid < NIH_)     wihs[tid] = wih[(size_t)t*ldw + tid];
    __syncthreads();
    int nvalid = (t >= MBLK_) ? ((t - MBLK_)/MBLK_ + 1) : 0;
    if (nvalid > NB_) nvalid = NB_;
    for (int n = tid; n < NB_; n += 256) {
        float s;
        if (n < nvalid) {
            s = 0.f;
            const float* kr = kcomp + n*CI_;
#pragma unroll
            for (int h = 0; h < NIH_; h++) {
                const float* qr = qis + h*CI_;
                float dsum = 0.f;
#pragma unroll 8
                for (int cc = 0; cc < CI_; cc++) dsum += qr[cc]*kr[cc];
                s += wihs[h] * fmaxf(dsum, 0.f);
            }
        } else {
            s = -INFINITY;
        }
        sc[n] = s;
    }
    __syncthreads();
    if (tid < 32) {
        for (int j = 0; j < TOPK_; j++) {
            float bv = -INFINITY;
            int bi = NB_;
            for (int n = tid; n < NB_; n += 32) {
                float v = sc[n];
                if (v > bv || (v == bv && n < bi)) { bv = v; bi = n; }
            }
#pragma unroll
            for (int o = 16; o; o >>= 1) {
                float ov = __shfl_xor_sync(0xffffffffu, bv, o);
                int   oi = __shfl_xor_sync(0xffffffffu, bi, o);
                if (ov > bv || (ov == bv && oi < bi)) { bv = ov; bi = oi; }
            }
            if (tid == 0) {
                if (bi >= NB_) { bi = 0; bv = -INFINITY; }
                else sc[bi] = __int_as_float(0x7fc00000);
                topidx[(size_t)t*TOPK_ + j] = bi;
                topval[(size_t)t*TOPK_ + j] = bv;
            }
            __syncwarp();
        }
    }
}

// ---------------- sparse attention over the 64 selected compressed blocks ----------------
__global__ void sparse_attn_k(const float* __restrict__ qT, const float* __restrict__ ckv,
                              const int* __restrict__ topidx, const float* __restrict__ topval,
                              float* __restrict__ attn) {
    int t = blockIdx.x;
    int tid = threadIdx.x;  // 128 threads, 4 warps
    __shared__ float skv[TOPK_][HD_ + 1];
    __shared__ float qs[NH_][HD_];
    __shared__ float ps[4][TOPK_];
    __shared__ int   sidx[TOPK_];
    __shared__ float svalid[TOPK_];
    __shared__ int   s_any;
    if (tid == 0) s_any = 0;
    __syncthreads();
    if (tid < TOPK_) {
        float v = topval[(size_t)t*TOPK_ + tid];
        int idx = topidx[(size_t)t*TOPK_ + tid];
        bool ok = (v > -1.0e38f);
        sidx[tid] = ok ? idx : 0;
        svalid[tid] = ok ? 1.f : 0.f;
        if (ok) s_any = 1;
    }
    __syncthreads();
    for (int k = 0; k < TOPK_; k++)
        skv[k][tid] = ckv[(size_t)sidx[k]*HD_ + tid];
    for (int i = tid; i < NH_*HD_; i += 128) {
        int hh = i >> 7;
        int dd = i & 127;
        qs[hh][dd] = qT[(size_t)hh*(T_*HD_) + (size_t)t*HD_ + dd];
    }
    __syncthreads();
    int w = tid >> 5;
    int lane = tid & 31;
    int any = s_any;
#pragma unroll
    for (int e = 0; e < 4; e++) {
        int hh = e*4 + w;
        float s0 = 0.f, s1 = 0.f;
        for (int d = 0; d < HD_; d++) {
            float qv = qs[hh][d];
            s0 += qv * skv[lane][d];
            s1 += qv * skv[lane + 32][d];
        }
        s0 = (svalid[lane]      > 0.f) ? s0*SCALE_ : NEG_;
        s1 = (svalid[lane + 32] > 0.f) ? s1*SCALE_ : NEG_;
        float mx = fmaxf(s0, s1);
#pragma unroll
        for (int o = 16; o; o >>= 1) mx = fmaxf(mx, __shfl_xor_sync(0xffffffffu, mx, o));
        float e0 = expf(s0 - mx);
        float e1 = expf(s1 - mx);
        float sum = e0 + e1;
#pragma unroll
        for (int o = 16; o; o >>= 1) sum += __shfl_xor_sync(0xffffffffu, sum, o);
        float inv = any ? (1.f/sum) : 0.f;
        ps[w][lane] = e0*inv;
        ps[w][lane + 32] = e1*inv;
        __syncwarp();
        float o0 = 0.f, o1 = 0.f, o2 = 0.f, o3 = 0.f;
        for (int k = 0; k < TOPK_; k++) {
            float p = ps[w][k];
            o0 += p*skv[k][lane];
            o1 += p*skv[k][lane + 32];
            o2 += p*skv[k][lane + 64];
            o3 += p*skv[k][lane + 96];
        }
        size_t base = (size_t)t*(NH_*HD_) + hh*HD_;
        attn[base + lane]      = o0;
        attn[base + lane + 32] = o1;
        attn[base + lane + 64] = o2;
        attn[base + lane + 96] = o3;
        __syncwarp();
    }
}

// ---------------- launch ----------------
static void cvt(const float* src, hlf* hi, hlf* lo, int n) {
    int n4 = n / 4;
    cvt_hilo_k<<<(n4 + 255)/256, 256>>>(src, hi, lo, n4);
}

extern "C" void kernel_launch(void* const* d_in, const int* in_sizes, int n_in,
                              void* d_out, int out_size) {
    const float* h_        = (const float*)d_in[0];
    const float* w_qc      = (const float*)d_in[1];
    const float* w_qup     = (const float*)d_in[2];
    const float* kvc_w     = (const float*)d_in[3];
    const float* kvc_wz    = (const float*)d_in[4];
    const float* kvc_bias  = (const float*)d_in[5];
    const float* k_proj_w  = (const float*)d_in[6];
    const float* v_proj_w  = (const float*)d_in[7];
    const float* idx_c_w   = (const float*)d_in[8];
    const float* idx_c_wz  = (const float*)d_in[9];
    const float* idx_c_bias= (const float*)d_in[10];
    const float* w_dq      = (const float*)d_in[11];
    const float* w_iuq     = (const float*)d_in[12];
    const float* w_w       = (const float*)d_in[13];
    const float* q_norm_w  = (const float*)d_in[14];
    const float* k_norm_w  = (const float*)d_in[15];
    const float* group_w   = (const float*)d_in[16];
    const float* final_w   = (const float*)d_in[17];
    float* out = (float*)d_out;

    float *ccat, *scatw, *scat, *q, *qT, *qi, *kcomp, *ckv, *topval, *attn, *S;
    int* topidx;
    hlf *hh, *hl, *hch, *hcl, *qTh, *qTl, *KTh, *KTl, *Vph, *Vpl, *Ph, *Pl;
    hlf *attnh, *attnl;
    hlf *bcath, *bcatl, *wqch, *wqcl, *wquph, *wqupl, *gwh, *gwl, *fwh, *fwl, *wcath, *wcatl;
    cudaGetSymbolAddress((void**)&ccat,   g_ccat);
    cudaGetSymbolAddress((void**)&scatw,  g_scatw);
    cudaGetSymbolAddress((void**)&scat,   g_scat);
    cudaGetSymbolAddress((void**)&q,      g_q);
    cudaGetSymbolAddress((void**)&qT,     g_qT);
    cudaGetSymbolAddress((void**)&qi,     g_qi);
    cudaGetSymbolAddress((void**)&kcomp,  g_kcomp);
    cudaGetSymbolAddress((void**)&ckv,    g_ckv);
    cudaGetSymbolAddress((void**)&topidx, g_topidx);
    cudaGetSymbolAddress((void**)&topval, g_topval);
    cudaGetSymbolAddress((void**)&attn,   g_attn);
    cudaGetSymbolAddress((void**)&S,      g_S);
    cudaGetSymbolAddress((void**)&hh,     g_hh);
    cudaGetSymbolAddress((void**)&hl,     g_hl);
    cudaGetSymbolAddress((void**)&hch,    g_hch);
    cudaGetSymbolAddress((void**)&hcl,    g_hcl);
    cudaGetSymbolAddress((void**)&qTh,    g_qTh);
    cudaGetSymbolAddress((void**)&qTl,    g_qTl);
    cudaGetSymbolAddress((void**)&KTh,    g_KTh);
    cudaGetSymbolAddress((void**)&KTl,    g_KTl);
    cudaGetSymbolAddress((void**)&Vph,    g_Vph);
    cudaGetSymbolAddress((void**)&Vpl,    g_Vpl);
    cudaGetSymbolAddress((void**)&Ph,     g_Ph);
    cudaGetSymbolAddress((void**)&Pl,     g_Pl);
    cudaGetSymbolAddress((void**)&attnh,  g_attnh);
    cudaGetSymbolAddress((void**)&attnl,  g_attnl);
    cudaGetSymbolAddress((void**)&bcath,  g_bcath);
    cudaGetSymbolAddress((void**)&bcatl,  g_bcatl);
    cudaGetSymbolAddress((void**)&wqch,   g_wqch);
    cudaGetSymbolAddress((void**)&wqcl,   g_wqcl);
    cudaGetSymbolAddress((void**)&wquph,  g_wquph);
    cudaGetSymbolAddress((void**)&wqupl,  g_wqupl);
    cudaGetSymbolAddress((void**)&gwh,    g_gwh);
    cudaGetSymbolAddress((void**)&gwl,    g_gwl);
    cudaGetSymbolAddress((void**)&fwh,    g_fwh);
    cudaGetSymbolAddress((void**)&fwl,    g_fwl);
    cudaGetSymbolAddress((void**)&wcath,  g_wcath);
    cudaGetSymbolAddress((void**)&wcatl,  g_wcatl);

    // launches 1-5 (so ncu -s 5 -c 1 profiles the big packed GEMM at #6)
    pack_bcat_k<<<(HID_*BCATN_ + 255)/256, 256>>>(k_proj_w, v_proj_w, kvc_w, kvc_wz, bcath, bcatl);
    cvt(h_,    hh,   hl,   T_*HID_);
    cvt(w_qc,  wqch, wqcl, HID_*QC_);
    cvt(w_qup, wquph, wqupl, QC_*NH_*HD_);
    pack_scatw_k<<<(HID_*SCATN_ + 255)/256, 256>>>(idx_c_w, idx_c_wz, w_dq, w_w, scatw);

    // #6: fused smooth projections (tensor): Ccat = [swk|swv|kc|kz]
    launch_mma_t<0,0>(hh, hl, bcath, bcatl, ccat, (hlf*)0, (hlf*)0,
                      T_, BCATN_, HID_, HID_, BCATN_, BCATN_, 1, 0, 0, 0);

    // output-weight prep + Wcat = stack_g (gw_g @ final_g) [2048 x 2048], hi/lo direct
    cvt(group_w, gwh, gwl, G_*(NH_/G_)*HD_*DG_);
    cvt(final_w, fwh, fwl, G_*DG_*HID_);
    launch_mma_t<0,1>(gwh, gwl, fwh, fwl, S /*dummy*/, wcath, wcatl,
                      DG_, HID_, (NH_/G_)*HD_,
                      DG_, HID_, HID_,
                      G_, (long)512*512, (long)512*HID_, (long)512*HID_);

    // fp32 score projections (FROZEN fp32 SIMT): Scat = [ic|iz|dqb|wih|pad]
    launch_score(h_, scatw, scat, T_, SCATN_, HID_, HID_, SCATN_, SCATN_);

    // q pipeline (hc written directly as hi/lo via EPI=1)
    launch_mma_t<0,1>(hh, hl, wqch, wqcl, S /*dummy*/, hch, hcl,
                      T_, QC_, HID_, HID_, QC_, QC_, 1, 0, 0, 0);
    launch_mma_t<0,0>(hch, hcl, wquph, wqupl, q, (hlf*)0, (hlf*)0,
                      T_, NH_*HD_, QC_, QC_, NH_*HD_, NH_*HD_, 1, 0, 0, 0);
    q_transform_k<<<dim3(NH_, T_), 128>>>(q, q_norm_w, qT, qTh, qTl);

    // swin K/V prep
    k_transform_k<<<T_, 128>>>(ccat, BCATN_, k_norm_w, KTh, KTl);
    vpad_k<<<(T_*HD_ + 255)/256, 256>>>(ccat, Vph, Vpl);

    // kv compression (normalized once)
    compress128_norm_k<<<NB_, 128>>>(ccat + 256, ccat + 384, BCATN_, kvc_bias, k_norm_w, ckv);

    // index compression + index queries (fp32)
    compress64_k<<<NB_, 64>>>(scat, scat + 64, SCATN_, idx_c_bias, kcomp);
    launch_score(scat + 128, w_iuq, qi, T_, NIH_*CI_, CI_, SCATN_, NIH_*CI_, NIH_*CI_);

    // top-64 block selection
    topk_k<<<T_, 256>>>(qi, scat + 192, SCATN_, kcomp, topidx, topval);

    // sparse attention (writes attn fp32)
    sparse_attn_k<<<T_, 128>>>(qT, ckv, topidx, topval, attn);

    // sliding-window attention: QK -> masked softmax -> PV (reads attn, writes attnh/attnl)
    {
        launch_mma_t<1,0>(qTh, qTl, KTh, KTl, S, (hlf*)0, (hlf*)0,
                          WIN_, KW_, HD_, HD_, KTLD_, KW_, NH_*NBW_, 0, 0, 0);
        swin_softmax_k<<<NH_*NBW_*WIN_, 128>>>(S, Ph, Pl);
        launch_mma_t<2,2>(Ph, Pl, Vph, Vpl, attn, attnh, attnl,
                          WIN_, HD_, KW_, KW_, HD_, NH_*HD_, NH_*NBW_, 0, 0, 0);
    }

    // fused output projection: out = attn @ Wcat
    launch_mma_t<0,0>(attnh, attnl, wcath, wcatl, out, (hlf*)0, (hlf*)0,
                      T_, HID_, NH_*HD_, NH_*HD_, HID_, HID_, 1, 0, 0, 0);
}

// round 15
// speedup vs baseline: 1.1119x; 1.0625x over previous
#include <cuda_runtime.h>
#include <cuda_fp16.h>
#include <cstdint>
#include <math.h>

#define T_     8192
#define HID_   2048
#define NH_    16
#define HD_    128
#define QC_    512
#define NB_    512
#define MBLK_  16
#define TOPK_  64
#define NIH_   4
#define CI_    64
#define G_     4
#define DG_    512
#define WIN_   256
#define EPS_   1e-6f
#define NEG_   -1e30f
#define SCALE_ 0.08838834764831845f

#define BCATN_ 512   // packed smooth projection width: [swk|swv|kc|kz]
#define SCATN_ 256   // packed fp32 score projection width: [ic|iz|dqb|wih|pad]

#define NBW_   32          // T/WIN sliding-window blocks
#define KW_    (2*WIN_)    // 512 keys per window block
#define KTLD_  (T_ + WIN_) // 8448 padded key columns

typedef __half hlf;

// ---------------- scratch (device globals; no allocation allowed) ----------------
__device__ float g_ccat[T_*BCATN_];
__device__ float g_scatw[HID_*SCATN_];
__device__ float g_scat[T_*SCATN_];
__device__ float g_q[T_*NH_*HD_];
__device__ float g_qT[NH_*T_*HD_];
__device__ float g_qi[T_*NIH_*CI_];
__device__ float g_kcomp[NB_*CI_];
__device__ float g_ckv[NB_*HD_];
__device__ int   g_topidx[T_*TOPK_];
__device__ float g_topval[T_*TOPK_];
__device__ float g_attn[T_*NH_*HD_];
__device__ float g_S[NH_*NBW_*WIN_*KW_];   // swin scores

// fp16 hi/lo preconverted operands
__device__ hlf g_hh[T_*HID_];
__device__ hlf g_hl[T_*HID_];
__device__ hlf g_hch[T_*QC_];
__device__ hlf g_hcl[T_*QC_];
__device__ hlf g_qTh[NH_*T_*HD_];
__device__ hlf g_qTl[NH_*T_*HD_];
__device__ hlf g_KTh[HD_*KTLD_];           // transposed padded swin K
__device__ hlf g_KTl[HD_*KTLD_];
__device__ hlf g_Vph[KTLD_*HD_];           // padded swin V
__device__ hlf g_Vpl[KTLD_*HD_];
__device__ hlf g_Ph[NH_*NBW_*WIN_*KW_];    // swin probs
__device__ hlf g_Pl[NH_*NBW_*WIN_*KW_];
__device__ hlf g_attnh[T_*NH_*HD_];
__device__ hlf g_attnl[T_*NH_*HD_];
__device__ hlf g_bcath[HID_*BCATN_];
__device__ hlf g_bcatl[HID_*BCATN_];
__device__ hlf g_wqch[HID_*QC_];
__device__ hlf g_wqcl[HID_*QC_];
__device__ hlf g_wquph[QC_*NH_*HD_];
__device__ hlf g_wqupl[QC_*NH_*HD_];
__device__ hlf g_gwh[G_*(NH_/G_)*HD_*DG_];
__device__ hlf g_gwl[G_*(NH_/G_)*HD_*DG_];
__device__ hlf g_fwh[G_*DG_*HID_];
__device__ hlf g_fwl[G_*DG_*HID_];
__device__ hlf g_wcath[HID_*HID_];         // fused (group @ final) weight hi/lo
__device__ hlf g_wcatl[HID_*HID_];

// ---------------- fp32 -> hi/lo fp16 conversion (float4-vectorized) ----------------
__global__ void cvt_hilo_k(const float* __restrict__ src, hlf* __restrict__ hi,
                           hlf* __restrict__ lo, int n4) {
    int i = blockIdx.x * 256 + threadIdx.x;
    if (i >= n4) return;
    float4 v = ((const float4*)src)[i];
    hlf hx = __float2half_rn(v.x);
    hlf hy = __float2half_rn(v.y);
    hlf hz = __float2half_rn(v.z);
    hlf hw = __float2half_rn(v.w);
    __half2 a, b;
    a.x = hx; a.y = hy;
    b.x = hz; b.y = hw;
    ((__half2*)hi)[2*i]     = a;
    ((__half2*)hi)[2*i + 1] = b;
    __half2 c2, d2;
    c2.x = __float2half_rn(v.x - __half2float(hx));
    c2.y = __float2half_rn(v.y - __half2float(hy));
    d2.x = __float2half_rn(v.z - __half2float(hz));
    d2.y = __float2half_rn(v.w - __half2float(hw));
    ((__half2*)lo)[2*i]     = c2;
    ((__half2*)lo)[2*i + 1] = d2;
}

// ================= fp32 SIMT tiled SGEMM (score path; top-k needs true fp32 — FROZEN) =================
template<int BM,int BN,int BK,int TM,int TN>
__global__ void __launch_bounds__((BM/TM)*(BN/TN))
sgemm_k(const float* __restrict__ A, const float* __restrict__ B, float* __restrict__ C,
        int M, int N, int K, int lda, int ldb, int ldc) {
    constexpr int NT = (BM/TM)*(BN/TN);
    __shared__ float As[BK][BM];
    __shared__ float Bs[BK][BN];
    const int tid = threadIdx.x;
    const int bm = blockIdx.y * BM, bn = blockIdx.x * BN;
    const int tx = tid % (BN/TN), ty = tid / (BN/TN);
    float acc[TM][TN];
#pragma unroll
    for (int i = 0; i < TM; i++)
#pragma unroll
        for (int j = 0; j < TN; j++) acc[i][j] = 0.f;

    for (int k0 = 0; k0 < K; k0 += BK) {
        for (int i = tid; i < BM*BK; i += NT) {
            int r = i / BK, c = i % BK;
            As[c][r] = A[(size_t)(bm + r)*lda + k0 + c];
        }
        for (int i = tid; i < BK*BN; i += NT) {
            int r = i / BN, c = i % BN;
            Bs[r][c] = B[(size_t)(k0 + r)*ldb + bn + c];
        }
        __syncthreads();
#pragma unroll
        for (int kk = 0; kk < BK; kk++) {
            float ra[TM], rb[TN];
#pragma unroll
            for (int i = 0; i < TM; i++) ra[i] = As[kk][ty*TM + i];
#pragma unroll
            for (int j = 0; j < TN; j++) rb[j] = Bs[kk][tx*TN + j];
#pragma unroll
            for (int i = 0; i < TM; i++)
#pragma unroll
                for (int j = 0; j < TN; j++) acc[i][j] += ra[i]*rb[j];
        }
        __syncthreads();
    }
#pragma unroll
    for (int i = 0; i < TM; i++) {
        int row = bm + ty*TM + i;
#pragma unroll
        for (int j = 0; j < TN; j++) {
            C[(size_t)row*ldc + bn + tx*TN + j] = acc[i][j];
        }
    }
}

static void launch_score(const float* A, const float* B, float* C,
                         int M, int N, int K, int lda, int ldb, int ldc,
                         cudaStream_t st) {
    dim3 grid((N + 63)/64, (M + 127)/128);
    sgemm_k<128,64,16,8,4><<<grid, 256, 0, st>>>(A, B, C, M, N, K, lda, ldb, ldc);
}

// ================= fp16-split tensor-core GEMM, preconverted hi/lo, cp.async 2-stage =================
// MODE 0: plain batched.  MODE 1: swin QK.  MODE 2: swin PV.
// EPI  0: store fp32 C.   EPI 1: store hi/lo only.  EPI 2: read fp32 C, add, store hi/lo only.

#define SA_  (128*40)
#define SB_  (32*136)
#define STG_ (2*SA_ + 2*SB_)
#define SMEMB_ (2*STG_*2)

__device__ __forceinline__ unsigned int smem_u32(const void* p) {
    return (unsigned int)__cvta_generic_to_shared(p);
}

__device__ __forceinline__ void cpa16(unsigned int dst, const void* src) {
    asm volatile("cp.async.cg.shared.global [%0], [%1], 16;" :: "r"(dst), "l"(src));
}

__device__ __forceinline__ void ldm4(unsigned int* r, unsigned int addr) {
    asm volatile("ldmatrix.sync.aligned.m8n8.x4.shared.b16 {%0,%1,%2,%3}, [%4];"
        : "=r"(r[0]), "=r"(r[1]), "=r"(r[2]), "=r"(r[3]) : "r"(addr));
}

__device__ __forceinline__ void ldm4t(unsigned int* r, unsigned int addr) {
    asm volatile("ldmatrix.sync.aligned.m8n8.x4.trans.shared.b16 {%0,%1,%2,%3}, [%4];"
        : "=r"(r[0]), "=r"(r[1]), "=r"(r[2]), "=r"(r[3]) : "r"(addr));
}

__device__ __forceinline__ void mma_f16(float* c, const unsigned int* a,
                                        unsigned int b0, unsigned int b1) {
    asm volatile("mma.sync.aligned.m16n8k16.row.col.f32.f16.f16.f32 "
        "{%0,%1,%2,%3}, {%4,%5,%6,%7}, {%8,%9}, {%0,%1,%2,%3};"
        : "+f"(c[0]), "+f"(c[1]), "+f"(c[2]), "+f"(c[3])
        : "r"(a[0]), "r"(a[1]), "r"(a[2]), "r"(a[3]), "r"(b0), "r"(b1));
}

template<int MODE, int EPI>
__global__ void __launch_bounds__(256, 1)
mma2_k(const hlf* __restrict__ Ah, const hlf* __restrict__ Al,
       const hlf* __restrict__ Bh, const hlf* __restrict__ Bl,
       float* __restrict__ C, hlf* __restrict__ Ch, hlf* __restrict__ Cl,
       int K, int lda, int ldb, int ldc,
       long aOff, long bOff, long cOff) {
    long z = blockIdx.z;
    long ao, bo, co;
    if (MODE == 0) { ao = z*aOff; bo = z*bOff; co = z*cOff; }
    else if (MODE == 1) {  // QK: A=qT [h][t][d], B=KT [d][pad+t], C=S
        ao = z * (long)(WIN_*HD_);
        bo = (z & (NBW_-1)) * (long)WIN_;
        co = z * (long)(WIN_*KW_);
    } else {               // PV: A=P, B=Vp [pad+t][d], C=attn
        ao = z * (long)(WIN_*KW_);
        bo = (z & (NBW_-1)) * (long)(WIN_*HD_);
        co = (z & (NBW_-1)) * (long)(WIN_*NH_*HD_) + (z >> 5) * (long)HD_;
    }
    Ah += ao; Al += ao;
    Bh += bo; Bl += bo;
    C  += co;
    if (EPI != 0) { Ch += co; Cl += co; }
    extern __shared__ hlf sm[];
    const int tid  = threadIdx.x;
    const int bm   = blockIdx.y * 128;
    const int bn   = blockIdx.x * 128;
    const int warp = tid >> 5;
    const int lane = tid & 31;
    const int wm   = (warp & 1) * 64;
    const int wn   = (warp >> 1) * 32;
    const int lrow = lane & 15;
    const int lb8  = (lane >> 4) << 3;

    float acc[4][4][4];
#pragma unroll
    for (int mi = 0; mi < 4; mi++)
#pragma unroll
        for (int nj = 0; nj < 4; nj++)
#pragma unroll
            for (int e = 0; e < 4; e++) acc[mi][nj][e] = 0.f;

    const int nst = K >> 5;

    auto load_stage = [&](int st, int k0) {
        hlf* sa_h = sm + st*STG_;
        hlf* sa_l = sa_h + SA_;
        hlf* sb_h = sa_l + SA_;
        hlf* sb_l = sb_h + SB_;
#pragma unroll
        for (int j = 0; j < 2; j++) {
            int ci = tid + j*256;
            int r = ci >> 2;
            int col = (ci & 3) << 3;
            cpa16(smem_u32(sa_h + r*40 + col), Ah + (size_t)(bm + r)*lda + k0 + col);
            cpa16(smem_u32(sa_l + r*40 + col), Al + (size_t)(bm + r)*lda + k0 + col);
        }
#pragma unroll
        for (int j = 0; j < 2; j++) {
            int ci = tid + j*256;
            int r = ci >> 4;
            int col = (ci & 15) << 3;
            cpa16(smem_u32(sb_h + r*136 + col), Bh + (size_t)(k0 + r)*ldb + bn + col);
            cpa16(smem_u32(sb_l + r*136 + col), Bl + (size_t)(k0 + r)*ldb + bn + col);
        }
    };

    load_stage(0, 0);
    asm volatile("cp.async.commit_group;");

    for (int s = 0; s < nst; s++) {
        if (s + 1 < nst) load_stage((s + 1) & 1, (s + 1) << 5);
        asm volatile("cp.async.commit_group;");
        asm volatile("cp.async.wait_group 1;");
        __syncthreads();

        hlf* sa_h = sm + (s & 1)*STG_;
        hlf* sa_l = sa_h + SA_;
        hlf* sb_h = sa_l + SA_;
        hlf* sb_l = sb_h + SB_;

#pragma unroll
        for (int kk = 0; kk < 32; kk += 16) {
            unsigned int ah[4][4], al[4][4], bh[2][4], bl[2][4];
#pragma unroll
            for (int mi = 0; mi < 4; mi++) {
                ldm4(ah[mi], smem_u32(sa_h + (wm + mi*16 + lrow)*40 + kk + lb8));
                ldm4(al[mi], smem_u32(sa_l + (wm + mi*16 + lrow)*40 + kk + lb8));
            }
#pragma unroll
            for (int nh = 0; nh < 2; nh++) {
                ldm4t(bh[nh], smem_u32(sb_h + (kk + lrow)*136 + wn + nh*16 + lb8));
                ldm4t(bl[nh], smem_u32(sb_l + (kk + lrow)*136 + wn + nh*16 + lb8));
            }
#pragma unroll
            for (int mi = 0; mi < 4; mi++) {
#pragma unroll
                for (int nj = 0; nj < 4; nj++) {
                    int nh = nj >> 1;
                    int p = (nj & 1) << 1;
                    mma_f16(acc[mi][nj], ah[mi], bh[nh][p], bh[nh][p+1]);
                    mma_f16(acc[mi][nj], ah[mi], bl[nh][p], bl[nh][p+1]);
                    mma_f16(acc[mi][nj], al[mi], bh[nh][p], bh[nh][p+1]);
                }
            }
        }
        __syncthreads();
    }

    const int cr = lane >> 2;
    const int cc = (lane & 3) << 1;
#pragma unroll
    for (int mi = 0; mi < 4; mi++) {
#pragma unroll
        for (int nj = 0; nj < 4; nj++) {
            size_t r0 = (size_t)(bm + wm + mi*16 + cr);
            int col = bn + wn + nj*8 + cc;
            float2 v0; v0.x = acc[mi][nj][0]; v0.y = acc[mi][nj][1];
            float2 v1; v1.x = acc[mi][nj][2]; v1.y = acc[mi][nj][3];
            if (EPI == 2) {
                float2 o0 = *(float2*)(C + r0*ldc + col);
                float2 o1 = *(float2*)(C + (r0 + 8)*ldc + col);
                v0.x += o0.x; v0.y += o0.y;
                v1.x += o1.x; v1.y += o1.y;
            }
            if (EPI == 0) {
                *(float2*)(C + r0*ldc + col)       = v0;
                *(float2*)(C + (r0 + 8)*ldc + col) = v1;
            } else {
                __half2 h2, l2;
                h2.x = __float2half_rn(v0.x);
                h2.y = __float2half_rn(v0.y);
                l2.x = __float2half_rn(v0.x - __half2float(h2.x));
                l2.y = __float2half_rn(v0.y - __half2float(h2.y));
                *(__half2*)(Ch + r0*ldc + col) = h2;
                *(__half2*)(Cl + r0*ldc + col) = l2;
                h2.x = __float2half_rn(v1.x);
                h2.y = __float2half_rn(v1.y);
                l2.x = __float2half_rn(v1.x - __half2float(h2.x));
                l2.y = __float2half_rn(v1.y - __half2float(h2.y));
                *(__half2*)(Ch + (r0 + 8)*ldc + col) = h2;
                *(__half2*)(Cl + (r0 + 8)*ldc + col) = l2;
            }
        }
    }
}

template<int MODE, int EPI>
static void launch_mma_t(const hlf* Ah, const hlf* Al, const hlf* Bh, const hlf* Bl,
                         float* C, hlf* Ch, hlf* Cl,
                         int M, int N, int K, int lda, int ldb, int ldc,
                         int batch, long aOff, long bOff, long cOff) {
    cudaFuncSetAttribute(mma2_k<MODE,EPI>, cudaFuncAttributeMaxDynamicSharedMemorySize, SMEMB_);
    dim3 grid(N / 128, M / 128, batch);
    mma2_k<MODE,EPI><<<grid, 256, SMEMB_>>>(Ah, Al, Bh, Bl, C, Ch, Cl,
                                            K, lda, ldb, ldc, aOff, bOff, cOff);
}

// ---------------- pack fused smooth weights -> hi/lo fp16 [HID][512] ----------------
__global__ void pack_bcat_k(const float* __restrict__ kp, const float* __restrict__ vp,
                            const float* __restrict__ kw, const float* __restrict__ kz,
                            hlf* __restrict__ oh, hlf* __restrict__ ol) {
    int i = blockIdx.x * 256 + threadIdx.x;
    if (i >= HID_ * BCATN_) return;
    int r = i / BCATN_;
    int c = i % BCATN_;
    float v;
    if      (c < 128) v = kp[r*128 + c];
    else if (c < 256) v = vp[r*128 + c - 128];
    else if (c < 384) v = kw[r*128 + c - 256];
    else              v = kz[r*128 + c - 384];
    hlf h = __float2half_rn(v);
    oh[i] = h;
    ol[i] = __float2half_rn(v - __half2float(h));
}

// ---------------- pack fp32 score weights into ScatW [HID][256] (zero-padded) ----------------
__global__ void pack_scatw_k(const float* __restrict__ iw, const float* __restrict__ iz,
                             const float* __restrict__ dq, const float* __restrict__ ww,
                             float* __restrict__ out) {
    int i = blockIdx.x * 256 + threadIdx.x;
    if (i >= HID_ * SCATN_) return;
    int r = i / SCATN_;
    int c = i % SCATN_;
    float v;
    if      (c < 64)  v = iw[r*64 + c];
    else if (c < 128) v = iz[r*64 + c - 64];
    else if (c < 192) v = dq[r*64 + c - 128];
    else if (c < 196) v = ww[r*4  + c - 192];
    else              v = 0.f;
    out[i] = v;
}

// ---------------- q transform: rope+rmsnorm; writes qT [h][t][d] fp32 + hi/lo fp16 ----------------
__global__ void q_transform_k(const float* __restrict__ q, const float* __restrict__ qnw,
                              float* __restrict__ qT, hlf* __restrict__ qTh, hlf* __restrict__ qTl) {
    int t = blockIdx.y;
    int h = blockIdx.x;
    int d = threadIdx.x;  // 128 threads
    const float* row = q + ((size_t)t*NH_ + h)*HD_;
    float v = row[d];
    float nb = (d < 64) ? row[(d < 32) ? d + 32 : d - 32] : 0.f;
    float ss = v*v;
#pragma unroll
    for (int o = 16; o; o >>= 1) ss += __shfl_xor_sync(0xffffffffu, ss, o);
    __shared__ float red[4];
    if ((d & 31) == 0) red[d >> 5] = ss;
    __syncthreads();
    float tot = red[0] + red[1] + red[2] + red[3];
    float r = rsqrtf(tot * (1.f/HD_) + EPS_);
    float outv;
    if (d < 32) {
        float inv = 1.f / powf(10000.f, (float)d * (1.f/32.f));
        float sn, cs;
        sincosf((float)t * inv, &sn, &cs);
        outv = v*cs - nb*sn;
    } else if (d < 64) {
        int i = d - 32;
        float inv = 1.f / powf(10000.f, (float)i * (1.f/32.f));
        float sn, cs;
        sincosf((float)t * inv, &sn, &cs);
        outv = nb*sn + v*cs;
    } else {
        outv = v;
    }
    outv = outv * r * qnw[d];
    size_t idx = (size_t)h*(T_*HD_) + (size_t)t*HD_ + d;
    qT[idx] = outv;
    hlf hi = __float2half_rn(outv);
    qTh[idx] = hi;
    qTl[idx] = __float2half_rn(outv - __half2float(hi));
}

// ---------------- sw_k transform: rmsnorm+rope -> transposed padded KT hi/lo ----------------
__global__ void k_transform_k(const float* __restrict__ kx, int ld, const float* __restrict__ knw,
                              hlf* __restrict__ KTh, hlf* __restrict__ KTl) {
    int t = blockIdx.x;
    int d = threadIdx.x;  // 128 threads
    const float* row = kx + (size_t)t*ld;
    float v = row[d];
    float ss = v*v;
#pragma unroll
    for (int o = 16; o; o >>= 1) ss += __shfl_xor_sync(0xffffffffu, ss, o);
    __shared__ float red[4];
    __shared__ float buf[HD_];
    if ((d & 31) == 0) red[d >> 5] = ss;
    __syncthreads();
    float tot = red[0] + red[1] + red[2] + red[3];
    float nv = v * rsqrtf(tot * (1.f/HD_) + EPS_) * knw[d];
    buf[d] = nv;
    __syncthreads();
    float outv;
    if (d < 32) {
        float inv = 1.f / powf(10000.f, (float)d * (1.f/32.f));
        float sn, cs;
        sincosf((float)t * inv, &sn, &cs);
        outv = buf[d]*cs - buf[d + 32]*sn;
    } else if (d < 64) {
        int i = d - 32;
        float inv = 1.f / powf(10000.f, (float)i * (1.f/32.f));
        float sn, cs;
        sincosf((float)t * inv, &sn, &cs);
        outv = buf[d - 32]*sn + buf[d]*cs;
    } else {
        outv = nv;
    }
    size_t idx = (size_t)d*KTLD_ + (WIN_ + t);
    hlf hi = __float2half_rn(outv);
    KTh[idx] = hi;
    KTl[idx] = __float2half_rn(outv - __half2float(hi));
}

// ---------------- sw_v: Ccat col 128..255 -> padded Vp hi/lo ----------------
__global__ void vpad_k(const float* __restrict__ ccat, hlf* __restrict__ Vph, hlf* __restrict__ Vpl) {
    int i = blockIdx.x * 256 + threadIdx.x;
    if (i >= T_*HD_) return;
    int t = i >> 7;
    int d = i & 127;
    float v = ccat[(size_t)t*BCATN_ + 128 + d];
    size_t idx = (size_t)(WIN_ + t)*HD_ + d;
    hlf hi = __float2half_rn(v);
    Vph[idx] = hi;
    Vpl[idx] = __float2half_rn(v - __half2float(hi));
}

// ---------------- swin masked softmax: S row (512) -> P hi/lo ----------------
__global__ void swin_softmax_k(const float* __restrict__ S, hlf* __restrict__ Ph, hlf* __restrict__ Pl) {
    int rowid = blockIdx.x;
    int tid = threadIdx.x;               // 128 threads
    int q = rowid & (WIN_-1);
    int blk = (rowid >> 8) & (NBW_-1);
    const float* srow = S + (size_t)rowid * KW_;
    float sv[4];
#pragma unroll
    for (int c = 0; c < 4; c++) {
        int j = tid + c*128;
        bool valid = (j > q) && (j - q <= WIN_) && (blk > 0 || j >= WIN_);
        sv[c] = valid ? srow[j]*SCALE_ : NEG_;
    }
    float m = fmaxf(fmaxf(sv[0], sv[1]), fmaxf(sv[2], sv[3]));
#pragma unroll
    for (int o = 16; o; o >>= 1) m = fmaxf(m, __shfl_xor_sync(0xffffffffu, m, o));
    __shared__ float red[4];
    if ((tid & 31) == 0) red[tid >> 5] = m;
    __syncthreads();
    m = fmaxf(fmaxf(red[0], red[1]), fmaxf(red[2], red[3]));
    float e[4];
    float sum = 0.f;
#pragma unroll
    for (int c = 0; c < 4; c++) { e[c] = expf(sv[c] - m); sum += e[c]; }
#pragma unroll
    for (int o = 16; o; o >>= 1) sum += __shfl_xor_sync(0xffffffffu, sum, o);
    __shared__ float red2[4];
    if ((tid & 31) == 0) red2[tid >> 5] = sum;
    __syncthreads();
    sum = red2[0] + red2[1] + red2[2] + red2[3];
    float inv = 1.f / sum;
#pragma unroll
    for (int c = 0; c < 4; c++) {
        int j = tid + c*128;
        float p = e[c] * inv;
        hlf hi = __float2half_rn(p);
        Ph[(size_t)rowid*KW_ + j] = hi;
        Pl[(size_t)rowid*KW_ + j] = __float2half_rn(p - __half2float(hi));
    }
}

// ---------------- compression ----------------
__global__ void compress64_k(const float* __restrict__ cin, const float* __restrict__ zin,
                             int ld, const float* __restrict__ bias, float* __restrict__ out) {
    int n = blockIdx.x;
    int c = threadIdx.x;  // 64 threads
    float z[MBLK_];
    float mx = -INFINITY;
#pragma unroll
    for (int m = 0; m < MBLK_; m++) {
        float v = zin[(size_t)(n*MBLK_ + m)*ld + c] + bias[m*CI_ + c];
        z[m] = v;
        mx = fmaxf(mx, v);
    }
    float sm = 0.f;
#pragma unroll
    for (int m = 0; m < MBLK_; m++) { float e = expf(z[m] - mx); z[m] = e; sm += e; }
    float acc = 0.f;
#pragma unroll
    for (int m = 0; m < MBLK_; m++) acc += z[m] * cin[(size_t)(n*MBLK_ + m)*ld + c];
    out[n*CI_ + c] = acc / sm;
}

__global__ void compress128_norm_k(const float* __restrict__ cin, const float* __restrict__ zin,
                                   int ld, const float* __restrict__ bias,
                                   const float* __restrict__ knw, float* __restrict__ out) {
    int n = blockIdx.x;
    int c = threadIdx.x;  // 128 threads
    float z[MBLK_];
    float mx = -INFINITY;
#pragma unroll
    for (int m = 0; m < MBLK_; m++) {
        float v = zin[(size_t)(n*MBLK_ + m)*ld + c] + bias[m*HD_ + c];
        z[m] = v;
        mx = fmaxf(mx, v);
    }
    float sm = 0.f;
#pragma unroll
    for (int m = 0; m < MBLK_; m++) { float e = expf(z[m] - mx); z[m] = e; sm += e; }
    float acc = 0.f;
#pragma unroll
    for (int m = 0; m < MBLK_; m++) acc += z[m] * cin[(size_t)(n*MBLK_ + m)*ld + c];
    float o = acc / sm;
    float ss = o*o;
#pragma unroll
    for (int oo = 16; oo; oo >>= 1) ss += __shfl_xor_sync(0xffffffffu, ss, oo);
    __shared__ float red[4];
    if ((c & 31) == 0) red[c >> 5] = ss;
    __syncthreads();
    float tot = red[0] + red[1] + red[2] + red[3];
    out[n*HD_ + c] = o * rsqrtf(tot * (1.f/HD_) + EPS_) * knw[c];
}

// ---------------- index scores + top-64 (JAX tie-break: smallest index) ----------------
__global__ void topk_k(const float* __restrict__ qi, const float* __restrict__ wih, int ldw,
                       const float* __restrict__ kcomp,
                       int* __restrict__ topidx, float* __restrict__ topval) {
    int t = blockIdx.x;
    int tid = threadIdx.x;  // 256 threads
    __shared__ float sc[NB_];
    __shared__ float qis[NIH_*CI_];
    __shared__ float wihs[NIH_];
    if (tid < NIH_*CI_) qis[tid] = qi[(size_t)t*NIH_*CI_ + tid];
    if (tid < NIH_)     wihs[tid] = wih[(size_t)t*ldw + tid];
    __syncthreads();
    int nvalid = (t >= MBLK_) ? ((t - MBLK_)/MBLK_ + 1) : 0;
    if (nvalid > NB_) nvalid = NB_;
    for (int n = tid; n < NB_; n += 256) {
        float s;
        if (n < nvalid) {
            s = 0.f;
            const float* kr = kcomp + n*CI_;
#pragma unroll
            for (int h = 0; h < NIH_; h++) {
                const float* qr = qis + h*CI_;
                float dsum = 0.f;
#pragma unroll 8
                for (int cc = 0; cc < CI_; cc++) dsum += qr[cc]*kr[cc];
                s += wihs[h] * fmaxf(dsum, 0.f);
            }
        } else {
            s = -INFINITY;
        }
        sc[n] = s;
    }
    __syncthreads();
    if (tid < 32) {
        for (int j = 0; j < TOPK_; j++) {
            float bv = -INFINITY;
            int bi = NB_;
            for (int n = tid; n < NB_; n += 32) {
                float v = sc[n];
                if (v > bv || (v == bv && n < bi)) { bv = v; bi = n; }
            }
#pragma unroll
            for (int o = 16; o; o >>= 1) {
                float ov = __shfl_xor_sync(0xffffffffu, bv, o);
                int   oi = __shfl_xor_sync(0xffffffffu, bi, o);
                if (ov > bv || (ov == bv && oi < bi)) { bv = ov; bi = oi; }
            }
            if (tid == 0) {
                if (bi >= NB_) { bi = 0; bv = -INFINITY; }
                else sc[bi] = __int_as_float(0x7fc00000);
                topidx[(size_t)t*TOPK_ + j] = bi;
                topval[(size_t)t*TOPK_ + j] = bv;
            }
            __syncwarp();
        }
    }
}

// ---------------- sparse attention over the 64 selected compressed blocks ----------------
__global__ void sparse_attn_k(const float* __restrict__ qT, const float* __restrict__ ckv,
                              const int* __restrict__ topidx, const float* __restrict__ topval,
                              float* __restrict__ attn) {
    int t = blockIdx.x;
    int tid = threadIdx.x;  // 128 threads, 4 warps
    __shared__ float skv[TOPK_][HD_ + 1];
    __shared__ float qs[NH_][HD_];
    __shared__ float ps[4][TOPK_];
    __shared__ int   sidx[TOPK_];
    __shared__ float svalid[TOPK_];
    __shared__ int   s_any;
    if (tid == 0) s_any = 0;
    __syncthreads();
    if (tid < TOPK_) {
        float v = topval[(size_t)t*TOPK_ + tid];
        int idx = topidx[(size_t)t*TOPK_ + tid];
        bool ok = (v > -1.0e38f);
        sidx[tid] = ok ? idx : 0;
        svalid[tid] = ok ? 1.f : 0.f;
        if (ok) s_any = 1;
    }
    __syncthreads();
    for (int k = 0; k < TOPK_; k++)
        skv[k][tid] = ckv[(size_t)sidx[k]*HD_ + tid];
    for (int i = tid; i < NH_*HD_; i += 128) {
        int hh = i >> 7;
        int dd = i & 127;
        qs[hh][dd] = qT[(size_t)hh*(T_*HD_) + (size_t)t*HD_ + dd];
    }
    __syncthreads();
    int w = tid >> 5;
    int lane = tid & 31;
    int any = s_any;
#pragma unroll
    for (int e = 0; e < 4; e++) {
        int hh = e*4 + w;
        float s0 = 0.f, s1 = 0.f;
        for (int d = 0; d < HD_; d++) {
            float qv = qs[hh][d];
            s0 += qv * skv[lane][d];
            s1 += qv * skv[lane + 32][d];
        }
        s0 = (svalid[lane]      > 0.f) ? s0*SCALE_ : NEG_;
        s1 = (svalid[lane + 32] > 0.f) ? s1*SCALE_ : NEG_;
        float mx = fmaxf(s0, s1);
#pragma unroll
        for (int o = 16; o; o >>= 1) mx = fmaxf(mx, __shfl_xor_sync(0xffffffffu, mx, o));
        float e0 = expf(s0 - mx);
        float e1 = expf(s1 - mx);
        float sum = e0 + e1;
#pragma unroll
        for (int o = 16; o; o >>= 1) sum += __shfl_xor_sync(0xffffffffu, sum, o);
        float inv = any ? (1.f/sum) : 0.f;
        ps[w][lane] = e0*inv;
        ps[w][lane + 32] = e1*inv;
        __syncwarp();
        float o0 = 0.f, o1 = 0.f, o2 = 0.f, o3 = 0.f;
        for (int k = 0; k < TOPK_; k++) {
            float p = ps[w][k];
            o0 += p*skv[k][lane];
            o1 += p*skv[k][lane + 32];
            o2 += p*skv[k][lane + 64];
            o3 += p*skv[k][lane + 96];
        }
        size_t base = (size_t)t*(NH_*HD_) + hh*HD_;
        attn[base + lane]      = o0;
        attn[base + lane + 32] = o1;
        attn[base + lane + 64] = o2;
        attn[base + lane + 96] = o3;
        __syncwarp();
    }
}

// ---------------- launch ----------------
static void cvt(const float* src, hlf* hi, hlf* lo, int n) {
    int n4 = n / 4;
    cvt_hilo_k<<<(n4 + 255)/256, 256>>>(src, hi, lo, n4);
}

extern "C" void kernel_launch(void* const* d_in, const int* in_sizes, int n_in,
                              void* d_out, int out_size) {
    static cudaStream_t sB = 0;
    static cudaEvent_t evRoot = 0, evA = 0, evB = 0;
    if (sB == 0) {
        cudaStreamCreateWithFlags(&sB, cudaStreamNonBlocking);
        cudaEventCreateWithFlags(&evRoot, cudaEventDisableTiming);
        cudaEventCreateWithFlags(&evA, cudaEventDisableTiming);
        cudaEventCreateWithFlags(&evB, cudaEventDisableTiming);
    }

    const float* h_        = (const float*)d_in[0];
    const float* w_qc      = (const float*)d_in[1];
    const float* w_qup     = (const float*)d_in[2];
    const float* kvc_w     = (const float*)d_in[3];
    const float* kvc_wz    = (const float*)d_in[4];
    const float* kvc_bias  = (const float*)d_in[5];
    const float* k_proj_w  = (const float*)d_in[6];
    const float* v_proj_w  = (const float*)d_in[7];
    const float* idx_c_w   = (const float*)d_in[8];
    const float* idx_c_wz  = (const float*)d_in[9];
    const float* idx_c_bias= (const float*)d_in[10];
    const float* w_dq      = (const float*)d_in[11];
    const float* w_iuq     = (const float*)d_in[12];
    const float* w_w       = (const float*)d_in[13];
    const float* q_norm_w  = (const float*)d_in[14];
    const float* k_norm_w  = (const float*)d_in[15];
    const float* group_w   = (const float*)d_in[16];
    const float* final_w   = (const float*)d_in[17];
    float* out = (float*)d_out;

    float *ccat, *scatw, *scat, *q, *qT, *qi, *kcomp, *ckv, *topval, *attn, *S;
    int* topidx;
    hlf *hh, *hl, *hch, *hcl, *qTh, *qTl, *KTh, *KTl, *Vph, *Vpl, *Ph, *Pl;
    hlf *attnh, *attnl;
    hlf *bcath, *bcatl, *wqch, *wqcl, *wquph, *wqupl, *gwh, *gwl, *fwh, *fwl, *wcath, *wcatl;
    cudaGetSymbolAddress((void**)&ccat,   g_ccat);
    cudaGetSymbolAddress((void**)&scatw,  g_scatw);
    cudaGetSymbolAddress((void**)&scat,   g_scat);
    cudaGetSymbolAddress((void**)&q,      g_q);
    cudaGetSymbolAddress((void**)&qT,     g_qT);
    cudaGetSymbolAddress((void**)&qi,     g_qi);
    cudaGetSymbolAddress((void**)&kcomp,  g_kcomp);
    cudaGetSymbolAddress((void**)&ckv,    g_ckv);
    cudaGetSymbolAddress((void**)&topidx, g_topidx);
    cudaGetSymbolAddress((void**)&topval, g_topval);
    cudaGetSymbolAddress((void**)&attn,   g_attn);
    cudaGetSymbolAddress((void**)&S,      g_S);
    cudaGetSymbolAddress((void**)&hh,     g_hh);
    cudaGetSymbolAddress((void**)&hl,     g_hl);
    cudaGetSymbolAddress((void**)&hch,    g_hch);
    cudaGetSymbolAddress((void**)&hcl,    g_hcl);
    cudaGetSymbolAddress((void**)&qTh,    g_qTh);
    cudaGetSymbolAddress((void**)&qTl,    g_qTl);
    cudaGetSymbolAddress((void**)&KTh,    g_KTh);
    cudaGetSymbolAddress((void**)&KTl,    g_KTl);
    cudaGetSymbolAddress((void**)&Vph,    g_Vph);
    cudaGetSymbolAddress((void**)&Vpl,    g_Vpl);
    cudaGetSymbolAddress((void**)&Ph,     g_Ph);
    cudaGetSymbolAddress((void**)&Pl,     g_Pl);
    cudaGetSymbolAddress((void**)&attnh,  g_attnh);
    cudaGetSymbolAddress((void**)&attnl,  g_attnl);
    cudaGetSymbolAddress((void**)&bcath,  g_bcath);
    cudaGetSymbolAddress((void**)&bcatl,  g_bcatl);
    cudaGetSymbolAddress((void**)&wqch,   g_wqch);
    cudaGetSymbolAddress((void**)&wqcl,   g_wqcl);
    cudaGetSymbolAddress((void**)&wquph,  g_wquph);
    cudaGetSymbolAddress((void**)&wqupl,  g_wqupl);
    cudaGetSymbolAddress((void**)&gwh,    g_gwh);
    cudaGetSymbolAddress((void**)&gwl,    g_gwl);
    cudaGetSymbolAddress((void**)&fwh,    g_fwh);
    cudaGetSymbolAddress((void**)&fwl,    g_fwl);
    cudaGetSymbolAddress((void**)&wcath,  g_wcath);
    cudaGetSymbolAddress((void**)&wcatl,  g_wcatl);

    // ===== fork stream B (fp32/FMA score chain) off the capture stream =====
    cudaEventRecord(evRoot, 0);
    cudaStreamWaitEvent(sB, evRoot, 0);

    // stream B: score projections -> compressions -> qi -> topk (FMA-bound)
    pack_scatw_k<<<(HID_*SCATN_ + 255)/256, 256, 0, sB>>>(idx_c_w, idx_c_wz, w_dq, w_w, scatw);
    launch_score(h_, scatw, scat, T_, SCATN_, HID_, HID_, SCATN_, SCATN_, sB);
    compress64_k<<<NB_, 64, 0, sB>>>(scat, scat + 64, SCATN_, idx_c_bias, kcomp);
    launch_score(scat + 128, w_iuq, qi, T_, NIH_*CI_, CI_, SCATN_, NIH_*CI_, NIH_*CI_, sB);
    topk_k<<<T_, 256, 0, sB>>>(qi, scat + 192, SCATN_, kcomp, topidx, topval);

    // stream A (capture stream): tensor chain
    pack_bcat_k<<<(HID_*BCATN_ + 255)/256, 256>>>(k_proj_w, v_proj_w, kvc_w, kvc_wz, bcath, bcatl);
    cvt(h_,    hh,   hl,   T_*HID_);
    cvt(w_qc,  wqch, wqcl, HID_*QC_);
    cvt(w_qup, wquph, wqupl, QC_*NH_*HD_);

    // fused smooth projections (tensor): Ccat = [swk|swv|kc|kz]
    launch_mma_t<0,0>(hh, hl, bcath, bcatl, ccat, (hlf*)0, (hlf*)0,
                      T_, BCATN_, HID_, HID_, BCATN_, BCATN_, 1, 0, 0, 0);

    // output-weight prep + Wcat = stack_g (gw_g @ final_g)
    cvt(group_w, gwh, gwl, G_*(NH_/G_)*HD_*DG_);
    cvt(final_w, fwh, fwl, G_*DG_*HID_);
    launch_mma_t<0,1>(gwh, gwl, fwh, fwl, S /*dummy*/, wcath, wcatl,
                      DG_, HID_, (NH_/G_)*HD_,
                      DG_, HID_, HID_,
                      G_, (long)512*512, (long)512*HID_, (long)512*HID_);

    // q pipeline
    launch_mma_t<0,1>(hh, hl, wqch, wqcl, S /*dummy*/, hch, hcl,
                      T_, QC_, HID_, HID_, QC_, QC_, 1, 0, 0, 0);
    launch_mma_t<0,0>(hch, hcl, wquph, wqupl, q, (hlf*)0, (hlf*)0,
                      T_, NH_*HD_, QC_, QC_, NH_*HD_, NH_*HD_, 1, 0, 0, 0);
    q_transform_k<<<dim3(NH_, T_), 128>>>(q, q_norm_w, qT, qTh, qTl);

    // swin K/V prep + kv compression
    k_transform_k<<<T_, 128>>>(ccat, BCATN_, k_norm_w, KTh, KTl);
    vpad_k<<<(T_*HD_ + 255)/256, 256>>>(ccat, Vph, Vpl);
    compress128_norm_k<<<NB_, 128>>>(ccat + 256, ccat + 384, BCATN_, kvc_bias, k_norm_w, ckv);

    // A has produced qT + ckv — let B run sparse attention while A does swin QK
    cudaEventRecord(evA, 0);
    cudaStreamWaitEvent(sB, evA, 0);
    sparse_attn_k<<<T_, 128, 0, sB>>>(qT, ckv, topidx, topval, attn);
    cudaEventRecord(evB, sB);

    // A: swin QK (tensor) + masked softmax, overlapping with B's sparse_attn
    launch_mma_t<1,0>(qTh, qTl, KTh, KTl, S, (hlf*)0, (hlf*)0,
                      WIN_, KW_, HD_, HD_, KTLD_, KW_, NH_*NBW_, 0, 0, 0);
    swin_softmax_k<<<NH_*NBW_*WIN_, 128>>>(S, Ph, Pl);

    // join B (PV reads attn written by sparse_attn)
    cudaStreamWaitEvent(0, evB, 0);
    launch_mma_t<2,2>(Ph, Pl, Vph, Vpl, attn, attnh, attnl,
                      WIN_, HD_, KW_, KW_, HD_, NH_*HD_, NH_*NBW_, 0, 0, 0);

    // fused output projection: out = attn @ Wcat
    launch_mma_t<0,0>(attnh, attnl, wcath, wcatl, out, (hlf*)0, (hlf*)0,
                      T_, HID_, NH_*HD_, NH_*HD_, HID_, HID_, 1, 0, 0, 0);
}

// round 16
// speedup vs baseline: 1.1616x; 1.0447x over previous
#include <cuda_runtime.h>
#include <cuda_fp16.h>
#include <cstdint>
#include <math.h>

#define T_     8192
#define HID_   2048
#define NH_    16
#define HD_    128
#define QC_    512
#define NB_    512
#define MBLK_  16
#define TOPK_  64
#define NIH_   4
#define CI_    64
#define G_     4
#define DG_    512
#define WIN_   256
#define EPS_   1e-6f
#define NEG_   -1e30f
#define SCALE_ 0.08838834764831845f

#define BCATN_ 512   // packed smooth projection width: [swk|swv|kc|kz]
#define SCATN_ 256   // packed fp32 score projection width: [ic|iz|dqb|wih|pad]

#define NBW_   32          // T/WIN sliding-window blocks
#define KW_    (2*WIN_)    // 512 keys per window block
#define KBAND_ 384         // valid key band per 128-query row tile
#define KTLD_  (T_ + WIN_) // 8448 padded key columns

typedef __half hlf;

// ---------------- scratch (device globals; no allocation allowed) ----------------
__device__ float g_ccat[T_*BCATN_];
__device__ float g_scatw[HID_*SCATN_];
__device__ float g_scat[T_*SCATN_];
__device__ float g_q[T_*NH_*HD_];
__device__ float g_qT[NH_*T_*HD_];
__device__ float g_qi[T_*NIH_*CI_];
__device__ float g_kcomp[NB_*CI_];
__device__ float g_ckv[NB_*HD_];
__device__ int   g_topidx[T_*TOPK_];
__device__ float g_topval[T_*TOPK_];
__device__ float g_attn[T_*NH_*HD_];
__device__ float g_S[NH_*NBW_*WIN_*KW_];   // swin scores

// fp16 hi/lo preconverted operands
__device__ hlf g_hh[T_*HID_];
__device__ hlf g_hl[T_*HID_];
__device__ hlf g_hch[T_*QC_];
__device__ hlf g_hcl[T_*QC_];
__device__ hlf g_qTh[NH_*T_*HD_];
__device__ hlf g_qTl[NH_*T_*HD_];
__device__ hlf g_KTh[HD_*KTLD_];           // transposed padded swin K
__device__ hlf g_KTl[HD_*KTLD_];
__device__ hlf g_Vph[KTLD_*HD_];           // padded swin V
__device__ hlf g_Vpl[KTLD_*HD_];
__device__ hlf g_Ph[NH_*NBW_*WIN_*KW_];    // swin probs
__device__ hlf g_Pl[NH_*NBW_*WIN_*KW_];
__device__ hlf g_attnh[T_*NH_*HD_];
__device__ hlf g_attnl[T_*NH_*HD_];
__device__ hlf g_bcath[HID_*BCATN_];
__device__ hlf g_bcatl[HID_*BCATN_];
__device__ hlf g_wqch[HID_*QC_];
__device__ hlf g_wqcl[HID_*QC_];
__device__ hlf g_wquph[QC_*NH_*HD_];
__device__ hlf g_wqupl[QC_*NH_*HD_];
__device__ hlf g_gwh[G_*(NH_/G_)*HD_*DG_];
__device__ hlf g_gwl[G_*(NH_/G_)*HD_*DG_];
__device__ hlf g_fwh[G_*DG_*HID_];
__device__ hlf g_fwl[G_*DG_*HID_];
__device__ hlf g_wcath[HID_*HID_];         // fused (group @ final) weight hi/lo
__device__ hlf g_wcatl[HID_*HID_];

// ---------------- fp32 -> hi/lo fp16 conversion (float4-vectorized) ----------------
__global__ void cvt_hilo_k(const float* __restrict__ src, hlf* __restrict__ hi,
                           hlf* __restrict__ lo, int n4) {
    int i = blockIdx.x * 256 + threadIdx.x;
    if (i >= n4) return;
    float4 v = ((const float4*)src)[i];
    hlf hx = __float2half_rn(v.x);
    hlf hy = __float2half_rn(v.y);
    hlf hz = __float2half_rn(v.z);
    hlf hw = __float2half_rn(v.w);
    __half2 a, b;
    a.x = hx; a.y = hy;
    b.x = hz; b.y = hw;
    ((__half2*)hi)[2*i]     = a;
    ((__half2*)hi)[2*i + 1] = b;
    __half2 c2, d2;
    c2.x = __float2half_rn(v.x - __half2float(hx));
    c2.y = __float2half_rn(v.y - __half2float(hy));
    d2.x = __float2half_rn(v.z - __half2float(hz));
    d2.y = __float2half_rn(v.w - __half2float(hw));
    ((__half2*)lo)[2*i]     = c2;
    ((__half2*)lo)[2*i + 1] = d2;
}

// ================= fp32 SIMT tiled SGEMM (score path; top-k needs true fp32 — FROZEN) =================
template<int BM,int BN,int BK,int TM,int TN>
__global__ void __launch_bounds__((BM/TM)*(BN/TN))
sgemm_k(const float* __restrict__ A, const float* __restrict__ B, float* __restrict__ C,
        int M, int N, int K, int lda, int ldb, int ldc) {
    constexpr int NT = (BM/TM)*(BN/TN);
    __shared__ float As[BK][BM];
    __shared__ float Bs[BK][BN];
    const int tid = threadIdx.x;
    const int bm = blockIdx.y * BM, bn = blockIdx.x * BN;
    const int tx = tid % (BN/TN), ty = tid / (BN/TN);
    float acc[TM][TN];
#pragma unroll
    for (int i = 0; i < TM; i++)
#pragma unroll
        for (int j = 0; j < TN; j++) acc[i][j] = 0.f;

    for (int k0 = 0; k0 < K; k0 += BK) {
        for (int i = tid; i < BM*BK; i += NT) {
            int r = i / BK, c = i % BK;
            As[c][r] = A[(size_t)(bm + r)*lda + k0 + c];
        }
        for (int i = tid; i < BK*BN; i += NT) {
            int r = i / BN, c = i % BN;
            Bs[r][c] = B[(size_t)(k0 + r)*ldb + bn + c];
        }
        __syncthreads();
#pragma unroll
        for (int kk = 0; kk < BK; kk++) {
            float ra[TM], rb[TN];
#pragma unroll
            for (int i = 0; i < TM; i++) ra[i] = As[kk][ty*TM + i];
#pragma unroll
            for (int j = 0; j < TN; j++) rb[j] = Bs[kk][tx*TN + j];
#pragma unroll
            for (int i = 0; i < TM; i++)
#pragma unroll
                for (int j = 0; j < TN; j++) acc[i][j] += ra[i]*rb[j];
        }
        __syncthreads();
    }
#pragma unroll
    for (int i = 0; i < TM; i++) {
        int row = bm + ty*TM + i;
#pragma unroll
        for (int j = 0; j < TN; j++) {
            C[(size_t)row*ldc + bn + tx*TN + j] = acc[i][j];
        }
    }
}

static void launch_score(const float* A, const float* B, float* C,
                         int M, int N, int K, int lda, int ldb, int ldc,
                         cudaStream_t st) {
    dim3 grid((N + 63)/64, (M + 127)/128);
    sgemm_k<128,64,16,8,4><<<grid, 256, 0, st>>>(A, B, C, M, N, K, lda, ldb, ldc);
}

// ================= fp16-split tensor-core GEMM, preconverted hi/lo, cp.async 2-stage =================
// MODE 0: plain batched.  MODE 1: swin QK (band-limited columns).
// MODE 2: swin PV (band-limited K reduction).
// EPI  0: store fp32 C.   EPI 1: store hi/lo only.  EPI 2: read fp32 C, add, store hi/lo only.
// P2   1: skip the Al*Bh pass (2-pass split; ~2^-11/sqrt(12) rel err).

#define SA_  (128*40)
#define SB_  (32*136)
#define STG_ (2*SA_ + 2*SB_)
#define SMEMB_ (2*STG_*2)

__device__ __forceinline__ unsigned int smem_u32(const void* p) {
    return (unsigned int)__cvta_generic_to_shared(p);
}

__device__ __forceinline__ void cpa16(unsigned int dst, const void* src) {
    asm volatile("cp.async.cg.shared.global [%0], [%1], 16;" :: "r"(dst), "l"(src));
}

__device__ __forceinline__ void ldm4(unsigned int* r, unsigned int addr) {
    asm volatile("ldmatrix.sync.aligned.m8n8.x4.shared.b16 {%0,%1,%2,%3}, [%4];"
        : "=r"(r[0]), "=r"(r[1]), "=r"(r[2]), "=r"(r[3]) : "r"(addr));
}

__device__ __forceinline__ void ldm4t(unsigned int* r, unsigned int addr) {
    asm volatile("ldmatrix.sync.aligned.m8n8.x4.trans.shared.b16 {%0,%1,%2,%3}, [%4];"
        : "=r"(r[0]), "=r"(r[1]), "=r"(r[2]), "=r"(r[3]) : "r"(addr));
}

__device__ __forceinline__ void mma_f16(float* c, const unsigned int* a,
                                        unsigned int b0, unsigned int b1) {
    asm volatile("mma.sync.aligned.m16n8k16.row.col.f32.f16.f16.f32 "
        "{%0,%1,%2,%3}, {%4,%5,%6,%7}, {%8,%9}, {%0,%1,%2,%3};"
        : "+f"(c[0]), "+f"(c[1]), "+f"(c[2]), "+f"(c[3])
        : "r"(a[0]), "r"(a[1]), "r"(a[2]), "r"(a[3]), "r"(b0), "r"(b1));
}

template<int MODE, int EPI, int P2 = 0>
__global__ void __launch_bounds__(256, 1)
mma2_k(const hlf* __restrict__ Ah, const hlf* __restrict__ Al,
       const hlf* __restrict__ Bh, const hlf* __restrict__ Bl,
       float* __restrict__ C, hlf* __restrict__ Ch, hlf* __restrict__ Cl,
       int K, int lda, int ldb, int ldc,
       long aOff, long bOff, long cOff) {
    long z = blockIdx.z;
    long ao, bo, co;
    if (MODE == 0) { ao = z*aOff; bo = z*bOff; co = z*cOff; }
    else if (MODE == 1) {  // QK: A=qT [h][t][d], B=KT [d][pad+t], C=S
        ao = z * (long)(WIN_*HD_);
        bo = (z & (NBW_-1)) * (long)WIN_;
        co = z * (long)(WIN_*KW_);
    } else {               // PV: A=P, B=Vp [pad+t][d], C=attn
        ao = z * (long)(WIN_*KW_);
        bo = (z & (NBW_-1)) * (long)(WIN_*HD_);
        co = (z & (NBW_-1)) * (long)(WIN_*NH_*HD_) + (z >> 5) * (long)HD_;
    }
    Ah += ao; Al += ao;
    Bh += bo; Bl += bo;
    C  += co;
    if (EPI != 0) { Ch += co; Cl += co; }
    if (MODE == 2 && blockIdx.y != 0) {   // band-limited PV: row tile 1 reads k in [128, 512)
        Ah += 128; Al += 128;
        Bh += (size_t)128 * ldb; Bl += (size_t)128 * ldb;
    }
    extern __shared__ hlf sm[];
    const int tid  = threadIdx.x;
    const int bm   = blockIdx.y * 128;
    int bn = blockIdx.x * 128;
    if (MODE == 1 && bm != 0) bn += 128;  // band-limited QK: row tile 1 covers cols [128, 512)
    const int warp = tid >> 5;
    const int lane = tid & 31;
    const int wm   = (warp & 1) * 64;
    const int wn   = (warp >> 1) * 32;
    const int lrow = lane & 15;
    const int lb8  = (lane >> 4) << 3;

    float acc[4][4][4];
#pragma unroll
    for (int mi = 0; mi < 4; mi++)
#pragma unroll
        for (int nj = 0; nj < 4; nj++)
#pragma unroll
            for (int e = 0; e < 4; e++) acc[mi][nj][e] = 0.f;

    const int nst = K >> 5;

    auto load_stage = [&](int st, int k0) {
        hlf* sa_h = sm + st*STG_;
        hlf* sa_l = sa_h + SA_;
        hlf* sb_h = sa_l + SA_;
        hlf* sb_l = sb_h + SB_;
#pragma unroll
        for (int j = 0; j < 2; j++) {
            int ci = tid + j*256;
            int r = ci >> 2;
            int col = (ci & 3) << 3;
            cpa16(smem_u32(sa_h + r*40 + col), Ah + (size_t)(bm + r)*lda + k0 + col);
            cpa16(smem_u32(sa_l + r*40 + col), Al + (size_t)(bm + r)*lda + k0 + col);
        }
#pragma unroll
        for (int j = 0; j < 2; j++) {
            int ci = tid + j*256;
            int r = ci >> 4;
            int col = (ci & 15) << 3;
            cpa16(smem_u32(sb_h + r*136 + col), Bh + (size_t)(k0 + r)*ldb + bn + col);
            cpa16(smem_u32(sb_l + r*136 + col), Bl + (size_t)(k0 + r)*ldb + bn + col);
        }
    };

    load_stage(0, 0);
    asm volatile("cp.async.commit_group;");

    for (int s = 0; s < nst; s++) {
        if (s + 1 < nst) load_stage((s + 1) & 1, (s + 1) << 5);
        asm volatile("cp.async.commit_group;");
        asm volatile("cp.async.wait_group 1;");
        __syncthreads();

        hlf* sa_h = sm + (s & 1)*STG_;
        hlf* sa_l = sa_h + SA_;
        hlf* sb_h = sa_l + SA_;
        hlf* sb_l = sb_h + SB_;

#pragma unroll
        for (int kk = 0; kk < 32; kk += 16) {
            unsigned int ah[4][4], al[4][4], bh[2][4], bl[2][4];
#pragma unroll
            for (int mi = 0; mi < 4; mi++) {
                ldm4(ah[mi], smem_u32(sa_h + (wm + mi*16 + lrow)*40 + kk + lb8));
                ldm4(al[mi], smem_u32(sa_l + (wm + mi*16 + lrow)*40 + kk + lb8));
            }
#pragma unroll
            for (int nh = 0; nh < 2; nh++) {
                ldm4t(bh[nh], smem_u32(sb_h + (kk + lrow)*136 + wn + nh*16 + lb8));
                ldm4t(bl[nh], smem_u32(sb_l + (kk + lrow)*136 + wn + nh*16 + lb8));
            }
#pragma unroll
            for (int mi = 0; mi < 4; mi++) {
#pragma unroll
                for (int nj = 0; nj < 4; nj++) {
                    int nh = nj >> 1;
                    int p = (nj & 1) << 1;
                    mma_f16(acc[mi][nj], ah[mi], bh[nh][p], bh[nh][p+1]);
                    mma_f16(acc[mi][nj], ah[mi], bl[nh][p], bl[nh][p+1]);
                    if (!P2) mma_f16(acc[mi][nj], al[mi], bh[nh][p], bh[nh][p+1]);
                }
            }
        }
        __syncthreads();
    }

    const int cr = lane >> 2;
    const int cc = (lane & 3) << 1;
#pragma unroll
    for (int mi = 0; mi < 4; mi++) {
#pragma unroll
        for (int nj = 0; nj < 4; nj++) {
            size_t r0 = (size_t)(bm + wm + mi*16 + cr);
            int col = bn + wn + nj*8 + cc;
            float2 v0; v0.x = acc[mi][nj][0]; v0.y = acc[mi][nj][1];
            float2 v1; v1.x = acc[mi][nj][2]; v1.y = acc[mi][nj][3];
            if (EPI == 2) {
                float2 o0 = *(float2*)(C + r0*ldc + col);
                float2 o1 = *(float2*)(C + (r0 + 8)*ldc + col);
                v0.x += o0.x; v0.y += o0.y;
                v1.x += o1.x; v1.y += o1.y;
            }
            if (EPI == 0) {
                *(float2*)(C + r0*ldc + col)       = v0;
                *(float2*)(C + (r0 + 8)*ldc + col) = v1;
            } else {
                __half2 h2, l2;
                h2.x = __float2half_rn(v0.x);
                h2.y = __float2half_rn(v0.y);
                l2.x = __float2half_rn(v0.x - __half2float(h2.x));
                l2.y = __float2half_rn(v0.y - __half2float(h2.y));
                *(__half2*)(Ch + r0*ldc + col) = h2;
                *(__half2*)(Cl + r0*ldc + col) = l2;
                h2.x = __float2half_rn(v1.x);
                h2.y = __float2half_rn(v1.y);
                l2.x = __float2half_rn(v1.x - __half2float(h2.x));
                l2.y = __float2half_rn(v1.y - __half2float(h2.y));
                *(__half2*)(Ch + (r0 + 8)*ldc + col) = h2;
                *(__half2*)(Cl + (r0 + 8)*ldc + col) = l2;
            }
        }
    }
}

template<int MODE, int EPI, int P2 = 0>
static void launch_mma_t(const hlf* Ah, const hlf* Al, const hlf* Bh, const hlf* Bl,
                         float* C, hlf* Ch, hlf* Cl,
                         int M, int N, int K, int lda, int ldb, int ldc,
                         int batch, long aOff, long bOff, long cOff) {
    cudaFuncSetAttribute(mma2_k<MODE,EPI,P2>, cudaFuncAttributeMaxDynamicSharedMemorySize, SMEMB_);
    dim3 grid(N / 128, M / 128, batch);
    mma2_k<MODE,EPI,P2><<<grid, 256, SMEMB_>>>(Ah, Al, Bh, Bl, C, Ch, Cl,
                                               K, lda, ldb, ldc, aOff, bOff, cOff);
}

// ---------------- pack fused smooth weights -> hi/lo fp16 [HID][512] ----------------
__global__ void pack_bcat_k(const float* __restrict__ kp, const float* __restrict__ vp,
                            const float* __restrict__ kw, const float* __restrict__ kz,
                            hlf* __restrict__ oh, hlf* __restrict__ ol) {
    int i = blockIdx.x * 256 + threadIdx.x;
    if (i >= HID_ * BCATN_) return;
    int r = i / BCATN_;
    int c = i % BCATN_;
    float v;
    if      (c < 128) v = kp[r*128 + c];
    else if (c < 256) v = vp[r*128 + c - 128];
    else if (c < 384) v = kw[r*128 + c - 256];
    else              v = kz[r*128 + c - 384];
    hlf h = __float2half_rn(v);
    oh[i] = h;
    ol[i] = __float2half_rn(v - __half2float(h));
}

// ---------------- pack fp32 score weights into ScatW [HID][256] (zero-padded) ----------------
__global__ void pack_scatw_k(const float* __restrict__ iw, const float* __restrict__ iz,
                             const float* __restrict__ dq, const float* __restrict__ ww,
                             float* __restrict__ out) {
    int i = blockIdx.x * 256 + threadIdx.x;
    if (i >= HID_ * SCATN_) return;
    int r = i / SCATN_;
    int c = i % SCATN_;
    float v;
    if      (c < 64)  v = iw[r*64 + c];
    else if (c < 128) v = iz[r*64 + c - 64];
    else if (c < 192) v = dq[r*64 + c - 128];
    else if (c < 196) v = ww[r*4  + c - 192];
    else              v = 0.f;
    out[i] = v;
}

// ---------------- q transform: rope+rmsnorm; writes qT [h][t][d] fp32 + hi/lo fp16 ----------------
__global__ void q_transform_k(const float* __restrict__ q, const float* __restrict__ qnw,
                              float* __restrict__ qT, hlf* __restrict__ qTh, hlf* __restrict__ qTl) {
    int t = blockIdx.y;
    int h = blockIdx.x;
    int d = threadIdx.x;  // 128 threads
    const float* row = q + ((size_t)t*NH_ + h)*HD_;
    float v = row[d];
    float nb = (d < 64) ? row[(d < 32) ? d + 32 : d - 32] : 0.f;
    float ss = v*v;
#pragma unroll
    for (int o = 16; o; o >>= 1) ss += __shfl_xor_sync(0xffffffffu, ss, o);
    __shared__ float red[4];
    if ((d & 31) == 0) red[d >> 5] = ss;
    __syncthreads();
    float tot = red[0] + red[1] + red[2] + red[3];
    float r = rsqrtf(tot * (1.f/HD_) + EPS_);
    float outv;
    if (d < 32) {
        float inv = 1.f / powf(10000.f, (float)d * (1.f/32.f));
        float sn, cs;
        sincosf((float)t * inv, &sn, &cs);
        outv = v*cs - nb*sn;
    } else if (d < 64) {
        int i = d - 32;
        float inv = 1.f / powf(10000.f, (float)i * (1.f/32.f));
        float sn, cs;
        sincosf((float)t * inv, &sn, &cs);
        outv = nb*sn + v*cs;
    } else {
        outv = v;
    }
    outv = outv * r * qnw[d];
    size_t idx = (size_t)h*(T_*HD_) + (size_t)t*HD_ + d;
    qT[idx] = outv;
    hlf hi = __float2half_rn(outv);
    qTh[idx] = hi;
    qTl[idx] = __float2half_rn(outv - __half2float(hi));
}

// ---------------- sw_k transform: rmsnorm+rope -> transposed padded KT hi/lo ----------------
__global__ void k_transform_k(const float* __restrict__ kx, int ld, const float* __restrict__ knw,
                              hlf* __restrict__ KTh, hlf* __restrict__ KTl) {
    int t = blockIdx.x;
    int d = threadIdx.x;  // 128 threads
    const float* row = kx + (size_t)t*ld;
    float v = row[d];
    float ss = v*v;
#pragma unroll
    for (int o = 16; o; o >>= 1) ss += __shfl_xor_sync(0xffffffffu, ss, o);
    __shared__ float red[4];
    __shared__ float buf[HD_];
    if ((d & 31) == 0) red[d >> 5] = ss;
    __syncthreads();
    float tot = red[0] + red[1] + red[2] + red[3];
    float nv = v * rsqrtf(tot * (1.f/HD_) + EPS_) * knw[d];
    buf[d] = nv;
    __syncthreads();
    float outv;
    if (d < 32) {
        float inv = 1.f / powf(10000.f, (float)d * (1.f/32.f));
        float sn, cs;
        sincosf((float)t * inv, &sn, &cs);
        outv = buf[d]*cs - buf[d + 32]*sn;
    } else if (d < 64) {
        int i = d - 32;
        float inv = 1.f / powf(10000.f, (float)i * (1.f/32.f));
        float sn, cs;
        sincosf((float)t * inv, &sn, &cs);
        outv = buf[d - 32]*sn + buf[d]*cs;
    } else {
        outv = nv;
    }
    size_t idx = (size_t)d*KTLD_ + (WIN_ + t);
    hlf hi = __float2half_rn(outv);
    KTh[idx] = hi;
    KTl[idx] = __float2half_rn(outv - __half2float(hi));
}

// ---------------- sw_v: Ccat col 128..255 -> padded Vp hi/lo ----------------
__global__ void vpad_k(const float* __restrict__ ccat, hlf* __restrict__ Vph, hlf* __restrict__ Vpl) {
    int i = blockIdx.x * 256 + threadIdx.x;
    if (i >= T_*HD_) return;
    int t = i >> 7;
    int d = i & 127;
    float v = ccat[(size_t)t*BCATN_ + 128 + d];
    size_t idx = (size_t)(WIN_ + t)*HD_ + d;
    hlf hi = __float2half_rn(v);
    Vph[idx] = hi;
    Vpl[idx] = __float2half_rn(v - __half2float(hi));
}

// ---------------- swin masked softmax: S row (512) -> P hi/lo (band writes only) ----------------
__global__ void swin_softmax_k(const float* __restrict__ S, hlf* __restrict__ Ph, hlf* __restrict__ Pl) {
    int rowid = blockIdx.x;
    int tid = threadIdx.x;               // 128 threads
    int q = rowid & (WIN_-1);
    int blk = (rowid >> 8) & (NBW_-1);
    const float* srow = S + (size_t)rowid * KW_;
    float sv[4];
#pragma unroll
    for (int c = 0; c < 4; c++) {
        int j = tid + c*128;
        bool valid = (j > q) && (j - q <= WIN_) && (blk > 0 || j >= WIN_);
        sv[c] = valid ? srow[j]*SCALE_ : NEG_;
    }
    float m = fmaxf(fmaxf(sv[0], sv[1]), fmaxf(sv[2], sv[3]));
#pragma unroll
    for (int o = 16; o; o >>= 1) m = fmaxf(m, __shfl_xor_sync(0xffffffffu, m, o));
    __shared__ float red[4];
    if ((tid & 31) == 0) red[tid >> 5] = m;
    __syncthreads();
    m = fmaxf(fmaxf(red[0], red[1]), fmaxf(red[2], red[3]));
    float e[4];
    float sum = 0.f;
#pragma unroll
    for (int c = 0; c < 4; c++) { e[c] = expf(sv[c] - m); sum += e[c]; }
#pragma unroll
    for (int o = 16; o; o >>= 1) sum += __shfl_xor_sync(0xffffffffu, sum, o);
    __shared__ float red2[4];
    if ((tid & 31) == 0) red2[tid >> 5] = sum;
    __syncthreads();
    sum = red2[0] + red2[1] + red2[2] + red2[3];
    float inv = 1.f / sum;
#pragma unroll
    for (int c = 0; c < 4; c++) {
        int j = tid + c*128;
        // PV only reads the 384-wide band per 128-row tile; skip out-of-band writes
        bool inband = (q < 128) ? (j < KBAND_) : (j >= 128);
        if (inband) {
            float p = e[c] * inv;
            hlf hi = __float2half_rn(p);
            Ph[(size_t)rowid*KW_ + j] = hi;
            Pl[(size_t)rowid*KW_ + j] = __float2half_rn(p - __half2float(hi));
        }
    }
}

// ---------------- compression ----------------
__global__ void compress64_k(const float* __restrict__ cin, const float* __restrict__ zin,
                             int ld, const float* __restrict__ bias, float* __restrict__ out) {
    int n = blockIdx.x;
    int c = threadIdx.x;  // 64 threads
    float z[MBLK_];
    float mx = -INFINITY;
#pragma unroll
    for (int m = 0; m < MBLK_; m++) {
        float v = zin[(size_t)(n*MBLK_ + m)*ld + c] + bias[m*CI_ + c];
        z[m] = v;
        mx = fmaxf(mx, v);
    }
    float sm = 0.f;
#pragma unroll
    for (int m = 0; m < MBLK_; m++) { float e = expf(z[m] - mx); z[m] = e; sm += e; }
    float acc = 0.f;
#pragma unroll
    for (int m = 0; m < MBLK_; m++) acc += z[m] * cin[(size_t)(n*MBLK_ + m)*ld + c];
    out[n*CI_ + c] = acc / sm;
}

__global__ void compress128_norm_k(const float* __restrict__ cin, const float* __restrict__ zin,
                                   int ld, const float* __restrict__ bias,
                                   const float* __restrict__ knw, float* __restrict__ out) {
    int n = blockIdx.x;
    int c = threadIdx.x;  // 128 threads
    float z[MBLK_];
    float mx = -INFINITY;
#pragma unroll
    for (int m = 0; m < MBLK_; m++) {
        float v = zin[(size_t)(n*MBLK_ + m)*ld + c] + bias[m*HD_ + c];
        z[m] = v;
        mx = fmaxf(mx, v);
    }
    float sm = 0.f;
#pragma unroll
    for (int m = 0; m < MBLK_; m++) { float e = expf(z[m] - mx); z[m] = e; sm += e; }
    float acc = 0.f;
#pragma unroll
    for (int m = 0; m < MBLK_; m++) acc += z[m] * cin[(size_t)(n*MBLK_ + m)*ld + c];
    float o = acc / sm;
    float ss = o*o;
#pragma unroll
    for (int oo = 16; oo; oo >>= 1) ss += __shfl_xor_sync(0xffffffffu, ss, oo);
    __shared__ float red[4];
    if ((c & 31) == 0) red[c >> 5] = ss;
    __syncthreads();
    float tot = red[0] + red[1] + red[2] + red[3];
    out[n*HD_ + c] = o * rsqrtf(tot * (1.f/HD_) + EPS_) * knw[c];
}

// ---------------- index scores + top-64 (JAX tie-break: smallest index) ----------------
__global__ void topk_k(const float* __restrict__ qi, const float* __restrict__ wih, int ldw,
                       const float* __restrict__ kcomp,
                       int* __restrict__ topidx, float* __restrict__ topval) {
    int t = blockIdx.x;
    int tid = threadIdx.x;  // 256 threads
    __shared__ float sc[NB_];
    __shared__ float qis[NIH_*CI_];
    __shared__ float wihs[NIH_];
    if (tid < NIH_*CI_) qis[tid] = qi[(size_t)t*NIH_*CI_ + tid];
    if (tid < NIH_)     wihs[tid] = wih[(size_t)t*ldw + tid];
    __syncthreads();
    int nvalid = (t >= MBLK_) ? ((t - MBLK_)/MBLK_ + 1) : 0;
    if (nvalid > NB_) nvalid = NB_;
    for (int n = tid; n < NB_; n += 256) {
        float s;
        if (n < nvalid) {
            s = 0.f;
            const float* kr = kcomp + n*CI_;
#pragma unroll
            for (int h = 0; h < NIH_; h++) {
                const float* qr = qis + h*CI_;
                float dsum = 0.f;
#pragma unroll 8
                for (int cc = 0; cc < CI_; cc++) dsum += qr[cc]*kr[cc];
                s += wihs[h] * fmaxf(dsum, 0.f);
            }
        } else {
            s = -INFINITY;
        }
        sc[n] = s;
    }
    __syncthreads();
    if (tid < 32) {
        for (int j = 0; j < TOPK_; j++) {
            float bv = -INFINITY;
            int bi = NB_;
            for (int n = tid; n < NB_; n += 32) {
                float v = sc[n];
                if (v > bv || (v == bv && n < bi)) { bv = v; bi = n; }
            }
#pragma unroll
            for (int o = 16; o; o >>= 1) {
                float ov = __shfl_xor_sync(0xffffffffu, bv, o);
                int   oi = __shfl_xor_sync(0xffffffffu, bi, o);
                if (ov > bv || (ov == bv && oi < bi)) { bv = ov; bi = oi; }
            }
            if (tid == 0) {
                if (bi >= NB_) { bi = 0; bv = -INFINITY; }
                else sc[bi] = __int_as_float(0x7fc00000);
                topidx[(size_t)t*TOPK_ + j] = bi;
                topval[(size_t)t*TOPK_ + j] = bv;
            }
            __syncwarp();
        }
    }
}

// ---------------- sparse attention over the 64 selected compressed blocks ----------------
__global__ void sparse_attn_k(const float* __restrict__ qT, const float* __restrict__ ckv,
                              const int* __restrict__ topidx, const float* __restrict__ topval,
                              float* __restrict__ attn) {
    int t = blockIdx.x;
    int tid = threadIdx.x;  // 128 threads, 4 warps
    __shared__ float skv[TOPK_][HD_ + 1];
    __shared__ float qs[NH_][HD_];
    __shared__ float ps[4][TOPK_];
    __shared__ int   sidx[TOPK_];
    __shared__ float svalid[TOPK_];
    __shared__ int   s_any;
    if (tid == 0) s_any = 0;
    __syncthreads();
    if (tid < TOPK_) {
        float v = topval[(size_t)t*TOPK_ + tid];
        int idx = topidx[(size_t)t*TOPK_ + tid];
        bool ok = (v > -1.0e38f);
        sidx[tid] = ok ? idx : 0;
        svalid[tid] = ok ? 1.f : 0.f;
        if (ok) s_any = 1;
    }
    __syncthreads();
    for (int k = 0; k < TOPK_; k++)
        skv[k][tid] = ckv[(size_t)sidx[k]*HD_ + tid];
    for (int i = tid; i < NH_*HD_; i += 128) {
        int hh = i >> 7;
        int dd = i & 127;
        qs[hh][dd] = qT[(size_t)hh*(T_*HD_) + (size_t)t*HD_ + dd];
    }
    __syncthreads();
    int w = tid >> 5;
    int lane = tid & 31;
    int any = s_any;
#pragma unroll
    for (int e = 0; e < 4; e++) {
        int hh = e*4 + w;
        float s0 = 0.f, s1 = 0.f;
        for (int d = 0; d < HD_; d++) {
            float qv = qs[hh][d];
            s0 += qv * skv[lane][d];
            s1 += qv * skv[lane + 32][d];
        }
        s0 = (svalid[lane]      > 0.f) ? s0*SCALE_ : NEG_;
        s1 = (svalid[lane + 32] > 0.f) ? s1*SCALE_ : NEG_;
        float mx = fmaxf(s0, s1);
#pragma unroll
        for (int o = 16; o; o >>= 1) mx = fmaxf(mx, __shfl_xor_sync(0xffffffffu, mx, o));
        float e0 = expf(s0 - mx);
        float e1 = expf(s1 - mx);
        float sum = e0 + e1;
#pragma unroll
        for (int o = 16; o; o >>= 1) sum += __shfl_xor_sync(0xffffffffu, sum, o);
        float inv = any ? (1.f/sum) : 0.f;
        ps[w][lane] = e0*inv;
        ps[w][lane + 32] = e1*inv;
        __syncwarp();
        float o0 = 0.f, o1 = 0.f, o2 = 0.f, o3 = 0.f;
        for (int k = 0; k < TOPK_; k++) {
            float p = ps[w][k];
            o0 += p*skv[k][lane];
            o1 += p*skv[k][lane + 32];
            o2 += p*skv[k][lane + 64];
            o3 += p*skv[k][lane + 96];
        }
        size_t base = (size_t)t*(NH_*HD_) + hh*HD_;
        attn[base + lane]      = o0;
        attn[base + lane + 32] = o1;
        attn[base + lane + 64] = o2;
        attn[base + lane + 96] = o3;
        __syncwarp();
    }
}

// ---------------- launch ----------------
static void cvt(const float* src, hlf* hi, hlf* lo, int n) {
    int n4 = n / 4;
    cvt_hilo_k<<<(n4 + 255)/256, 256>>>(src, hi, lo, n4);
}

extern "C" void kernel_launch(void* const* d_in, const int* in_sizes, int n_in,
                              void* d_out, int out_size) {
    static cudaStream_t sB = 0;
    static cudaEvent_t evRoot = 0, evA = 0, evB = 0;
    if (sB == 0) {
        cudaStreamCreateWithFlags(&sB, cudaStreamNonBlocking);
        cudaEventCreateWithFlags(&evRoot, cudaEventDisableTiming);
        cudaEventCreateWithFlags(&evA, cudaEventDisableTiming);
        cudaEventCreateWithFlags(&evB, cudaEventDisableTiming);
    }

    const float* h_        = (const float*)d_in[0];
    const float* w_qc      = (const float*)d_in[1];
    const float* w_qup     = (const float*)d_in[2];
    const float* kvc_w     = (const float*)d_in[3];
    const float* kvc_wz    = (const float*)d_in[4];
    const float* kvc_bias  = (const float*)d_in[5];
    const float* k_proj_w  = (const float*)d_in[6];
    const float* v_proj_w  = (const float*)d_in[7];
    const float* idx_c_w   = (const float*)d_in[8];
    const float* idx_c_wz  = (const float*)d_in[9];
    const float* idx_c_bias= (const float*)d_in[10];
    const float* w_dq      = (const float*)d_in[11];
    const float* w_iuq     = (const float*)d_in[12];
    const float* w_w       = (const float*)d_in[13];
    const float* q_norm_w  = (const float*)d_in[14];
    const float* k_norm_w  = (const float*)d_in[15];
    const float* group_w   = (const float*)d_in[16];
    const float* final_w   = (const float*)d_in[17];
    float* out = (float*)d_out;

    float *ccat, *scatw, *scat, *q, *qT, *qi, *kcomp, *ckv, *topval, *attn, *S;
    int* topidx;
    hlf *hh, *hl, *hch, *hcl, *qTh, *qTl, *KTh, *KTl, *Vph, *Vpl, *Ph, *Pl;
    hlf *attnh, *attnl;
    hlf *bcath, *bcatl, *wqch, *wqcl, *wquph, *wqupl, *gwh, *gwl, *fwh, *fwl, *wcath, *wcatl;
    cudaGetSymbolAddress((void**)&ccat,   g_ccat);
    cudaGetSymbolAddress((void**)&scatw,  g_scatw);
    cudaGetSymbolAddress((void**)&scat,   g_scat);
    cudaGetSymbolAddress((void**)&q,      g_q);
    cudaGetSymbolAddress((void**)&qT,     g_qT);
    cudaGetSymbolAddress((void**)&qi,     g_qi);
    cudaGetSymbolAddress((void**)&kcomp,  g_kcomp);
    cudaGetSymbolAddress((void**)&ckv,    g_ckv);
    cudaGetSymbolAddress((void**)&topidx, g_topidx);
    cudaGetSymbolAddress((void**)&topval, g_topval);
    cudaGetSymbolAddress((void**)&attn,   g_attn);
    cudaGetSymbolAddress((void**)&S,      g_S);
    cudaGetSymbolAddress((void**)&hh,     g_hh);
    cudaGetSymbolAddress((void**)&hl,     g_hl);
    cudaGetSymbolAddress((void**)&hch,    g_hch);
    cudaGetSymbolAddress((void**)&hcl,    g_hcl);
    cudaGetSymbolAddress((void**)&qTh,    g_qTh);
    cudaGetSymbolAddress((void**)&qTl,    g_qTl);
    cudaGetSymbolAddress((void**)&KTh,    g_KTh);
    cudaGetSymbolAddress((void**)&KTl,    g_KTl);
    cudaGetSymbolAddress((void**)&Vph,    g_Vph);
    cudaGetSymbolAddress((void**)&Vpl,    g_Vpl);
    cudaGetSymbolAddress((void**)&Ph,     g_Ph);
    cudaGetSymbolAddress((void**)&Pl,     g_Pl);
    cudaGetSymbolAddress((void**)&attnh,  g_attnh);
    cudaGetSymbolAddress((void**)&attnl,  g_attnl);
    cudaGetSymbolAddress((void**)&bcath,  g_bcath);
    cudaGetSymbolAddress((void**)&bcatl,  g_bcatl);
    cudaGetSymbolAddress((void**)&wqch,   g_wqch);
    cudaGetSymbolAddress((void**)&wqcl,   g_wqcl);
    cudaGetSymbolAddress((void**)&wquph,  g_wquph);
    cudaGetSymbolAddress((void**)&wqupl,  g_wqupl);
    cudaGetSymbolAddress((void**)&gwh,    g_gwh);
    cudaGetSymbolAddress((void**)&gwl,    g_gwl);
    cudaGetSymbolAddress((void**)&fwh,    g_fwh);
    cudaGetSymbolAddress((void**)&fwl,    g_fwl);
    cudaGetSymbolAddress((void**)&wcath,  g_wcath);
    cudaGetSymbolAddress((void**)&wcatl,  g_wcatl);

    // ===== fork stream B (fp32/FMA score chain) off the capture stream =====
    cudaEventRecord(evRoot, 0);
    cudaStreamWaitEvent(sB, evRoot, 0);

    // stream B: score projections -> compressions -> qi -> topk (FMA-bound)
    pack_scatw_k<<<(HID_*SCATN_ + 255)/256, 256, 0, sB>>>(idx_c_w, idx_c_wz, w_dq, w_w, scatw);
    launch_score(h_, scatw, scat, T_, SCATN_, HID_, HID_, SCATN_, SCATN_, sB);
    compress64_k<<<NB_, 64, 0, sB>>>(scat, scat + 64, SCATN_, idx_c_bias, kcomp);
    launch_score(scat + 128, w_iuq, qi, T_, NIH_*CI_, CI_, SCATN_, NIH_*CI_, NIH_*CI_, sB);
    topk_k<<<T_, 256, 0, sB>>>(qi, scat + 192, SCATN_, kcomp, topidx, topval);

    // stream A (capture stream): tensor chain
    pack_bcat_k<<<(HID_*BCATN_ + 255)/256, 256>>>(k_proj_w, v_proj_w, kvc_w, kvc_wz, bcath, bcatl);
    cvt(h_,    hh,   hl,   T_*HID_);
    cvt(w_qc,  wqch, wqcl, HID_*QC_);
    cvt(w_qup, wquph, wqupl, QC_*NH_*HD_);

    // fused smooth projections (tensor): Ccat = [swk|swv|kc|kz]
    launch_mma_t<0,0>(hh, hl, bcath, bcatl, ccat, (hlf*)0, (hlf*)0,
                      T_, BCATN_, HID_, HID_, BCATN_, BCATN_, 1, 0, 0, 0);

    // output-weight prep + Wcat = stack_g (gw_g @ final_g)
    cvt(group_w, gwh, gwl, G_*(NH_/G_)*HD_*DG_);
    cvt(final_w, fwh, fwl, G_*DG_*HID_);
    launch_mma_t<0,1>(gwh, gwl, fwh, fwl, S /*dummy*/, wcath, wcatl,
                      DG_, HID_, (NH_/G_)*HD_,
                      DG_, HID_, HID_,
                      G_, (long)512*512, (long)512*HID_, (long)512*HID_);

    // q pipeline
    launch_mma_t<0,1>(hh, hl, wqch, wqcl, S /*dummy*/, hch, hcl,
                      T_, QC_, HID_, HID_, QC_, QC_, 1, 0, 0, 0);
    launch_mma_t<0,0>(hch, hcl, wquph, wqupl, q, (hlf*)0, (hlf*)0,
                      T_, NH_*HD_, QC_, QC_, NH_*HD_, NH_*HD_, 1, 0, 0, 0);
    q_transform_k<<<dim3(NH_, T_), 128>>>(q, q_norm_w, qT, qTh, qTl);

    // swin K/V prep + kv compression
    k_transform_k<<<T_, 128>>>(ccat, BCATN_, k_norm_w, KTh, KTl);
    vpad_k<<<(T_*HD_ + 255)/256, 256>>>(ccat, Vph, Vpl);
    compress128_norm_k<<<NB_, 128>>>(ccat + 256, ccat + 384, BCATN_, kvc_bias, k_norm_w, ckv);

    // A has produced qT + ckv — let B run sparse attention while A does swin QK
    cudaEventRecord(evA, 0);
    cudaStreamWaitEvent(sB, evA, 0);
    sparse_attn_k<<<T_, 128, 0, sB>>>(qT, ckv, topidx, topval, attn);
    cudaEventRecord(evB, sB);

    // A: swin QK (band-limited: 3 of 4 column tiles) + masked softmax
    launch_mma_t<1,0>(qTh, qTl, KTh, KTl, S, (hlf*)0, (hlf*)0,
                      WIN_, KBAND_, HD_, HD_, KTLD_, KW_, NH_*NBW_, 0, 0, 0);
    swin_softmax_k<<<NH_*NBW_*WIN_, 128>>>(S, Ph, Pl);

    // join B (PV reads attn written by sparse_attn); PV band-limited K=384
    cudaStreamWaitEvent(0, evB, 0);
    launch_mma_t<2,2>(Ph, Pl, Vph, Vpl, attn, attnh, attnl,
                      WIN_, HD_, KBAND_, KW_, HD_, NH_*HD_, NH_*NBW_, 0, 0, 0);

    // fused output projection (2-pass split): out = attn @ Wcat
    launch_mma_t<0,0,1>(attnh, attnl, wcath, wcatl, out, (hlf*)0, (hlf*)0,
                        T_, HID_, NH_*HD_, NH_*HD_, HID_, HID_, 1, 0, 0, 0);
}

// round 17
// speedup vs baseline: 1.2041x; 1.0366x over previous
#include <cuda_runtime.h>
#include <cuda_fp16.h>
#include <cstdint>
#include <math.h>

#define T_     8192
#define HID_   2048
#define NH_    16
#define HD_    128
#define QC_    512
#define NB_    512
#define MBLK_  16
#define TOPK_  64
#define NIH_   4
#define CI_    64
#define G_     4
#define DG_    512
#define WIN_   256
#define EPS_   1e-6f
#define NEG_   -1e30f
#define SCALE_ 0.08838834764831845f

#define BCATN_ 512   // packed smooth projection width: [swk|swv|kc|kz]
#define SCATN_ 256   // packed fp32 score projection width: [ic|iz|dqb|wih|pad]

#define NBW_   32          // T/WIN sliding-window blocks
#define KW_    (2*WIN_)    // 512 keys per window block
#define KBAND_ 384         // valid key band per 128-query row tile
#define KTLD_  (T_ + WIN_) // 8448 padded key columns

typedef __half hlf;

// ---------------- scratch (device globals; no allocation allowed) ----------------
__device__ float g_ccat[T_*BCATN_];
__device__ float g_scatw[HID_*SCATN_];
__device__ float g_scat[T_*SCATN_];
__device__ float g_q[T_*NH_*HD_];
__device__ float g_qT[NH_*T_*HD_];
__device__ float g_qi[T_*NIH_*CI_];
__device__ float g_kcomp[NB_*CI_];
__device__ float g_ckv[NB_*HD_];
__device__ int   g_topidx[T_*TOPK_];
__device__ float g_topval[T_*TOPK_];
__device__ float g_attn[T_*NH_*HD_];
__device__ float g_S[NH_*NBW_*WIN_*KW_];   // swin scores

// fp16 hi/lo preconverted operands
__device__ hlf g_hh[T_*HID_];
__device__ hlf g_hl[T_*HID_];
__device__ hlf g_hch[T_*QC_];
__device__ hlf g_hcl[T_*QC_];
__device__ hlf g_qTh[NH_*T_*HD_];
__device__ hlf g_qTl[NH_*T_*HD_];
__device__ hlf g_KTh[HD_*KTLD_];           // transposed padded swin K
__device__ hlf g_KTl[HD_*KTLD_];
__device__ hlf g_Vph[KTLD_*HD_];           // padded swin V
__device__ hlf g_Vpl[KTLD_*HD_];
__device__ hlf g_Ph[NH_*NBW_*WIN_*KW_];    // swin probs
__device__ hlf g_Pl[NH_*NBW_*WIN_*KW_];
__device__ hlf g_attnh[T_*NH_*HD_];
__device__ hlf g_attnl[T_*NH_*HD_];
__device__ hlf g_bcath[HID_*BCATN_];
__device__ hlf g_bcatl[HID_*BCATN_];
__device__ hlf g_wqch[HID_*QC_];
__device__ hlf g_wqcl[HID_*QC_];
__device__ hlf g_wquph[QC_*NH_*HD_];
__device__ hlf g_wqupl[QC_*NH_*HD_];
__device__ hlf g_gwh[G_*(NH_/G_)*HD_*DG_];
__device__ hlf g_gwl[G_*(NH_/G_)*HD_*DG_];
__device__ hlf g_fwh[G_*DG_*HID_];
__device__ hlf g_fwl[G_*DG_*HID_];
__device__ hlf g_wcath[HID_*HID_];         // fused (group @ final) weight hi/lo
__device__ hlf g_wcatl[HID_*HID_];

// ---------------- fp32 -> hi/lo fp16 conversion (float4-vectorized) ----------------
__global__ void cvt_hilo_k(const float* __restrict__ src, hlf* __restrict__ hi,
                           hlf* __restrict__ lo, int n4) {
    int i = blockIdx.x * 256 + threadIdx.x;
    if (i >= n4) return;
    float4 v = ((const float4*)src)[i];
    hlf hx = __float2half_rn(v.x);
    hlf hy = __float2half_rn(v.y);
    hlf hz = __float2half_rn(v.z);
    hlf hw = __float2half_rn(v.w);
    __half2 a, b;
    a.x = hx; a.y = hy;
    b.x = hz; b.y = hw;
    ((__half2*)hi)[2*i]     = a;
    ((__half2*)hi)[2*i + 1] = b;
    __half2 c2, d2;
    c2.x = __float2half_rn(v.x - __half2float(hx));
    c2.y = __float2half_rn(v.y - __half2float(hy));
    d2.x = __float2half_rn(v.z - __half2float(hz));
    d2.y = __float2half_rn(v.w - __half2float(hw));
    ((__half2*)lo)[2*i]     = c2;
    ((__half2*)lo)[2*i + 1] = d2;
}

// ================= fp32 SIMT tiled SGEMM (score path; top-k needs true fp32 — FROZEN) =================
template<int BM,int BN,int BK,int TM,int TN>
__global__ void __launch_bounds__((BM/TM)*(BN/TN))
sgemm_k(const float* __restrict__ A, const float* __restrict__ B, float* __restrict__ C,
        int M, int N, int K, int lda, int ldb, int ldc) {
    constexpr int NT = (BM/TM)*(BN/TN);
    __shared__ float As[BK][BM];
    __shared__ float Bs[BK][BN];
    const int tid = threadIdx.x;
    const int bm = blockIdx.y * BM, bn = blockIdx.x * BN;
    const int tx = tid % (BN/TN), ty = tid / (BN/TN);
    float acc[TM][TN];
#pragma unroll
    for (int i = 0; i < TM; i++)
#pragma unroll
        for (int j = 0; j < TN; j++) acc[i][j] = 0.f;

    for (int k0 = 0; k0 < K; k0 += BK) {
        for (int i = tid; i < BM*BK; i += NT) {
            int r = i / BK, c = i % BK;
            As[c][r] = A[(size_t)(bm + r)*lda + k0 + c];
        }
        for (int i = tid; i < BK*BN; i += NT) {
            int r = i / BN, c = i % BN;
            Bs[r][c] = B[(size_t)(k0 + r)*ldb + bn + c];
        }
        __syncthreads();
#pragma unroll
        for (int kk = 0; kk < BK; kk++) {
            float ra[TM], rb[TN];
#pragma unroll
            for (int i = 0; i < TM; i++) ra[i] = As[kk][ty*TM + i];
#pragma unroll
            for (int j = 0; j < TN; j++) rb[j] = Bs[kk][tx*TN + j];
#pragma unroll
            for (int i = 0; i < TM; i++)
#pragma unroll
                for (int j = 0; j < TN; j++) acc[i][j] += ra[i]*rb[j];
        }
        __syncthreads();
    }
#pragma unroll
    for (int i = 0; i < TM; i++) {
        int row = bm + ty*TM + i;
#pragma unroll
        for (int j = 0; j < TN; j++) {
            C[(size_t)row*ldc + bn + tx*TN + j] = acc[i][j];
        }
    }
}

static void launch_score(const float* A, const float* B, float* C,
                         int M, int N, int K, int lda, int ldb, int ldc,
                         cudaStream_t st) {
    dim3 grid((N + 63)/64, (M + 127)/128);
    sgemm_k<128,64,16,8,4><<<grid, 256, 0, st>>>(A, B, C, M, N, K, lda, ldb, ldc);
}

// ================= fp16-split tensor-core GEMM, preconverted hi/lo, cp.async 2-stage =================
// MODE 0: plain batched.  MODE 1: swin QK (band-limited columns).
// MODE 2: swin PV (band-limited K reduction).
// EPI  0: store fp32 C.   EPI 1: store hi/lo only.  EPI 2: read fp32 C, add, store hi/lo only.
// P2   1: skip the Al*Bh pass (2-pass split; calibrated ~2.1e-4 rel err per GEMM).

#define SA_  (128*40)
#define SB_  (32*136)
#define STG_ (2*SA_ + 2*SB_)
#define SMEMB_ (2*STG_*2)

__device__ __forceinline__ unsigned int smem_u32(const void* p) {
    return (unsigned int)__cvta_generic_to_shared(p);
}

__device__ __forceinline__ void cpa16(unsigned int dst, const void* src) {
    asm volatile("cp.async.cg.shared.global [%0], [%1], 16;" :: "r"(dst), "l"(src));
}

__device__ __forceinline__ void ldm4(unsigned int* r, unsigned int addr) {
    asm volatile("ldmatrix.sync.aligned.m8n8.x4.shared.b16 {%0,%1,%2,%3}, [%4];"
        : "=r"(r[0]), "=r"(r[1]), "=r"(r[2]), "=r"(r[3]) : "r"(addr));
}

__device__ __forceinline__ void ldm4t(unsigned int* r, unsigned int addr) {
    asm volatile("ldmatrix.sync.aligned.m8n8.x4.trans.shared.b16 {%0,%1,%2,%3}, [%4];"
        : "=r"(r[0]), "=r"(r[1]), "=r"(r[2]), "=r"(r[3]) : "r"(addr));
}

__device__ __forceinline__ void mma_f16(float* c, const unsigned int* a,
                                        unsigned int b0, unsigned int b1) {
    asm volatile("mma.sync.aligned.m16n8k16.row.col.f32.f16.f16.f32 "
        "{%0,%1,%2,%3}, {%4,%5,%6,%7}, {%8,%9}, {%0,%1,%2,%3};"
        : "+f"(c[0]), "+f"(c[1]), "+f"(c[2]), "+f"(c[3])
        : "r"(a[0]), "r"(a[1]), "r"(a[2]), "r"(a[3]), "r"(b0), "r"(b1));
}

template<int MODE, int EPI, int P2 = 0>
__global__ void __launch_bounds__(256, 1)
mma2_k(const hlf* __restrict__ Ah, const hlf* __restrict__ Al,
       const hlf* __restrict__ Bh, const hlf* __restrict__ Bl,
       float* __restrict__ C, hlf* __restrict__ Ch, hlf* __restrict__ Cl,
       int K, int lda, int ldb, int ldc,
       long aOff, long bOff, long cOff) {
    long z = blockIdx.z;
    long ao, bo, co;
    if (MODE == 0) { ao = z*aOff; bo = z*bOff; co = z*cOff; }
    else if (MODE == 1) {  // QK: A=qT [h][t][d], B=KT [d][pad+t], C=S
        ao = z * (long)(WIN_*HD_);
        bo = (z & (NBW_-1)) * (long)WIN_;
        co = z * (long)(WIN_*KW_);
    } else {               // PV: A=P, B=Vp [pad+t][d], C=attn
        ao = z * (long)(WIN_*KW_);
        bo = (z & (NBW_-1)) * (long)(WIN_*HD_);
        co = (z & (NBW_-1)) * (long)(WIN_*NH_*HD_) + (z >> 5) * (long)HD_;
    }
    Ah += ao; Al += ao;
    Bh += bo; Bl += bo;
    C  += co;
    if (EPI != 0) { Ch += co; Cl += co; }
    if (MODE == 2 && blockIdx.y != 0) {   // band-limited PV: row tile 1 reads k in [128, 512)
        Ah += 128; Al += 128;
        Bh += (size_t)128 * ldb; Bl += (size_t)128 * ldb;
    }
    extern __shared__ hlf sm[];
    const int tid  = threadIdx.x;
    const int bm   = blockIdx.y * 128;
    int bn = blockIdx.x * 128;
    if (MODE == 1 && bm != 0) bn += 128;  // band-limited QK: row tile 1 covers cols [128, 512)
    const int warp = tid >> 5;
    const int lane = tid & 31;
    const int wm   = (warp & 1) * 64;
    const int wn   = (warp >> 1) * 32;
    const int lrow = lane & 15;
    const int lb8  = (lane >> 4) << 3;

    float acc[4][4][4];
#pragma unroll
    for (int mi = 0; mi < 4; mi++)
#pragma unroll
        for (int nj = 0; nj < 4; nj++)
#pragma unroll
            for (int e = 0; e < 4; e++) acc[mi][nj][e] = 0.f;

    const int nst = K >> 5;

    auto load_stage = [&](int st, int k0) {
        hlf* sa_h = sm + st*STG_;
        hlf* sa_l = sa_h + SA_;
        hlf* sb_h = sa_l + SA_;
        hlf* sb_l = sb_h + SB_;
#pragma unroll
        for (int j = 0; j < 2; j++) {
            int ci = tid + j*256;
            int r = ci >> 2;
            int col = (ci & 3) << 3;
            cpa16(smem_u32(sa_h + r*40 + col), Ah + (size_t)(bm + r)*lda + k0 + col);
            cpa16(smem_u32(sa_l + r*40 + col), Al + (size_t)(bm + r)*lda + k0 + col);
        }
#pragma unroll
        for (int j = 0; j < 2; j++) {
            int ci = tid + j*256;
            int r = ci >> 4;
            int col = (ci & 15) << 3;
            cpa16(smem_u32(sb_h + r*136 + col), Bh + (size_t)(k0 + r)*ldb + bn + col);
            cpa16(smem_u32(sb_l + r*136 + col), Bl + (size_t)(k0 + r)*ldb + bn + col);
        }
    };

    load_stage(0, 0);
    asm volatile("cp.async.commit_group;");

    for (int s = 0; s < nst; s++) {
        if (s + 1 < nst) load_stage((s + 1) & 1, (s + 1) << 5);
        asm volatile("cp.async.commit_group;");
        asm volatile("cp.async.wait_group 1;");
        __syncthreads();

        hlf* sa_h = sm + (s & 1)*STG_;
        hlf* sa_l = sa_h + SA_;
        hlf* sb_h = sa_l + SA_;
        hlf* sb_l = sb_h + SB_;

#pragma unroll
        for (int kk = 0; kk < 32; kk += 16) {
            unsigned int ah[4][4], al[4][4], bh[2][4], bl[2][4];
#pragma unroll
            for (int mi = 0; mi < 4; mi++) {
                ldm4(ah[mi], smem_u32(sa_h + (wm + mi*16 + lrow)*40 + kk + lb8));
                if (!P2) ldm4(al[mi], smem_u32(sa_l + (wm + mi*16 + lrow)*40 + kk + lb8));
            }
#pragma unroll
            for (int nh = 0; nh < 2; nh++) {
                ldm4t(bh[nh], smem_u32(sb_h + (kk + lrow)*136 + wn + nh*16 + lb8));
                ldm4t(bl[nh], smem_u32(sb_l + (kk + lrow)*136 + wn + nh*16 + lb8));
            }
#pragma unroll
            for (int mi = 0; mi < 4; mi++) {
#pragma unroll
                for (int nj = 0; nj < 4; nj++) {
                    int nh = nj >> 1;
                    int p = (nj & 1) << 1;
                    mma_f16(acc[mi][nj], ah[mi], bh[nh][p], bh[nh][p+1]);
                    mma_f16(acc[mi][nj], ah[mi], bl[nh][p], bl[nh][p+1]);
                    if (!P2) mma_f16(acc[mi][nj], al[mi], bh[nh][p], bh[nh][p+1]);
                }
            }
        }
        __syncthreads();
    }

    const int cr = lane >> 2;
    const int cc = (lane & 3) << 1;
#pragma unroll
    for (int mi = 0; mi < 4; mi++) {
#pragma unroll
        for (int nj = 0; nj < 4; nj++) {
            size_t r0 = (size_t)(bm + wm + mi*16 + cr);
            int col = bn + wn + nj*8 + cc;
            float2 v0; v0.x = acc[mi][nj][0]; v0.y = acc[mi][nj][1];
            float2 v1; v1.x = acc[mi][nj][2]; v1.y = acc[mi][nj][3];
            if (EPI == 2) {
                float2 o0 = *(float2*)(C + r0*ldc + col);
                float2 o1 = *(float2*)(C + (r0 + 8)*ldc + col);
                v0.x += o0.x; v0.y += o0.y;
                v1.x += o1.x; v1.y += o1.y;
            }
            if (EPI == 0) {
                *(float2*)(C + r0*ldc + col)       = v0;
                *(float2*)(C + (r0 + 8)*ldc + col) = v1;
            } else {
                __half2 h2, l2;
                h2.x = __float2half_rn(v0.x);
                h2.y = __float2half_rn(v0.y);
                l2.x = __float2half_rn(v0.x - __half2float(h2.x));
                l2.y = __float2half_rn(v0.y - __half2float(h2.y));
                *(__half2*)(Ch + r0*ldc + col) = h2;
                *(__half2*)(Cl + r0*ldc + col) = l2;
                h2.x = __float2half_rn(v1.x);
                h2.y = __float2half_rn(v1.y);
                l2.x = __float2half_rn(v1.x - __half2float(h2.x));
                l2.y = __float2half_rn(v1.y - __half2float(h2.y));
                *(__half2*)(Ch + (r0 + 8)*ldc + col) = h2;
                *(__half2*)(Cl + (r0 + 8)*ldc + col) = l2;
            }
        }
    }
}

template<int MODE, int EPI, int P2 = 0>
static void launch_mma_t(const hlf* Ah, const hlf* Al, const hlf* Bh, const hlf* Bl,
                         float* C, hlf* Ch, hlf* Cl,
                         int M, int N, int K, int lda, int ldb, int ldc,
                         int batch, long aOff, long bOff, long cOff) {
    cudaFuncSetAttribute(mma2_k<MODE,EPI,P2>, cudaFuncAttributeMaxDynamicSharedMemorySize, SMEMB_);
    dim3 grid(N / 128, M / 128, batch);
    mma2_k<MODE,EPI,P2><<<grid, 256, SMEMB_>>>(Ah, Al, Bh, Bl, C, Ch, Cl,
                                               K, lda, ldb, ldc, aOff, bOff, cOff);
}

// ---------------- pack fused smooth weights -> hi/lo fp16 [HID][512] ----------------
__global__ void pack_bcat_k(const float* __restrict__ kp, const float* __restrict__ vp,
                            const float* __restrict__ kw, const float* __restrict__ kz,
                            hlf* __restrict__ oh, hlf* __restrict__ ol) {
    int i = blockIdx.x * 256 + threadIdx.x;
    if (i >= HID_ * BCATN_) return;
    int r = i / BCATN_;
    int c = i % BCATN_;
    float v;
    if      (c < 128) v = kp[r*128 + c];
    else if (c < 256) v = vp[r*128 + c - 128];
    else if (c < 384) v = kw[r*128 + c - 256];
    else              v = kz[r*128 + c - 384];
    hlf h = __float2half_rn(v);
    oh[i] = h;
    ol[i] = __float2half_rn(v - __half2float(h));
}

// ---------------- pack fp32 score weights into ScatW [HID][256] (zero-padded) ----------------
__global__ void pack_scatw_k(const float* __restrict__ iw, const float* __restrict__ iz,
                             const float* __restrict__ dq, const float* __restrict__ ww,
                             float* __restrict__ out) {
    int i = blockIdx.x * 256 + threadIdx.x;
    if (i >= HID_ * SCATN_) return;
    int r = i / SCATN_;
    int c = i % SCATN_;
    float v;
    if      (c < 64)  v = iw[r*64 + c];
    else if (c < 128) v = iz[r*64 + c - 64];
    else if (c < 192) v = dq[r*64 + c - 128];
    else if (c < 196) v = ww[r*4  + c - 192];
    else              v = 0.f;
    out[i] = v;
}

// ---------------- q transform: rope+rmsnorm; writes qT [h][t][d] fp32 + hi/lo fp16 ----------------
__global__ void q_transform_k(const float* __restrict__ q, const float* __restrict__ qnw,
                              float* __restrict__ qT, hlf* __restrict__ qTh, hlf* __restrict__ qTl) {
    int t = blockIdx.y;
    int h = blockIdx.x;
    int d = threadIdx.x;  // 128 threads
    const float* row = q + ((size_t)t*NH_ + h)*HD_;
    float v = row[d];
    float nb = (d < 64) ? row[(d < 32) ? d + 32 : d - 32] : 0.f;
    float ss = v*v;
#pragma unroll
    for (int o = 16; o; o >>= 1) ss += __shfl_xor_sync(0xffffffffu, ss, o);
    __shared__ float red[4];
    if ((d & 31) == 0) red[d >> 5] = ss;
    __syncthreads();
    float tot = red[0] + red[1] + red[2] + red[3];
    float r = rsqrtf(tot * (1.f/HD_) + EPS_);
    float outv;
    if (d < 32) {
        float inv = 1.f / powf(10000.f, (float)d * (1.f/32.f));
        float sn, cs;
        sincosf((float)t * inv, &sn, &cs);
        outv = v*cs - nb*sn;
    } else if (d < 64) {
        int i = d - 32;
        float inv = 1.f / powf(10000.f, (float)i * (1.f/32.f));
        float sn, cs;
        sincosf((float)t * inv, &sn, &cs);
        outv = nb*sn + v*cs;
    } else {
        outv = v;
    }
    outv = outv * r * qnw[d];
    size_t idx = (size_t)h*(T_*HD_) + (size_t)t*HD_ + d;
    qT[idx] = outv;
    hlf hi = __float2half_rn(outv);
    qTh[idx] = hi;
    qTl[idx] = __float2half_rn(outv - __half2float(hi));
}

// ---------------- sw_k transform: rmsnorm+rope -> transposed padded KT hi/lo ----------------
__global__ void k_transform_k(const float* __restrict__ kx, int ld, const float* __restrict__ knw,
                              hlf* __restrict__ KTh, hlf* __restrict__ KTl) {
    int t = blockIdx.x;
    int d = threadIdx.x;  // 128 threads
    const float* row = kx + (size_t)t*ld;
    float v = row[d];
    float ss = v*v;
#pragma unroll
    for (int o = 16; o; o >>= 1) ss += __shfl_xor_sync(0xffffffffu, ss, o);
    __shared__ float red[4];
    __shared__ float buf[HD_];
    if ((d & 31) == 0) red[d >> 5] = ss;
    __syncthreads();
    float tot = red[0] + red[1] + red[2] + red[3];
    float nv = v * rsqrtf(tot * (1.f/HD_) + EPS_) * knw[d];
    buf[d] = nv;
    __syncthreads();
    float outv;
    if (d < 32) {
        float inv = 1.f / powf(10000.f, (float)d * (1.f/32.f));
        float sn, cs;
        sincosf((float)t * inv, &sn, &cs);
        outv = buf[d]*cs - buf[d + 32]*sn;
    } else if (d < 64) {
        int i = d - 32;
        float inv = 1.f / powf(10000.f, (float)i * (1.f/32.f));
        float sn, cs;
        sincosf((float)t * inv, &sn, &cs);
        outv = buf[d - 32]*sn + buf[d]*cs;
    } else {
        outv = nv;
    }
    size_t idx = (size_t)d*KTLD_ + (WIN_ + t);
    hlf hi = __float2half_rn(outv);
    KTh[idx] = hi;
    KTl[idx] = __float2half_rn(outv - __half2float(hi));
}

// ---------------- sw_v: Ccat col 128..255 -> padded Vp hi/lo ----------------
__global__ void vpad_k(const float* __restrict__ ccat, hlf* __restrict__ Vph, hlf* __restrict__ Vpl) {
    int i = blockIdx.x * 256 + threadIdx.x;
    if (i >= T_*HD_) return;
    int t = i >> 7;
    int d = i & 127;
    float v = ccat[(size_t)t*BCATN_ + 128 + d];
    size_t idx = (size_t)(WIN_ + t)*HD_ + d;
    hlf hi = __float2half_rn(v);
    Vph[idx] = hi;
    Vpl[idx] = __float2half_rn(v - __half2float(hi));
}

// ---------------- swin masked softmax: S row (512) -> P hi/lo (band writes only) ----------------
__global__ void swin_softmax_k(const float* __restrict__ S, hlf* __restrict__ Ph, hlf* __restrict__ Pl) {
    int rowid = blockIdx.x;
    int tid = threadIdx.x;               // 128 threads
    int q = rowid & (WIN_-1);
    int blk = (rowid >> 8) & (NBW_-1);
    const float* srow = S + (size_t)rowid * KW_;
    float sv[4];
#pragma unroll
    for (int c = 0; c < 4; c++) {
        int j = tid + c*128;
        bool valid = (j > q) && (j - q <= WIN_) && (blk > 0 || j >= WIN_);
        sv[c] = valid ? srow[j]*SCALE_ : NEG_;
    }
    float m = fmaxf(fmaxf(sv[0], sv[1]), fmaxf(sv[2], sv[3]));
#pragma unroll
    for (int o = 16; o; o >>= 1) m = fmaxf(m, __shfl_xor_sync(0xffffffffu, m, o));
    __shared__ float red[4];
    if ((tid & 31) == 0) red[tid >> 5] = m;
    __syncthreads();
    m = fmaxf(fmaxf(red[0], red[1]), fmaxf(red[2], red[3]));
    float e[4];
    float sum = 0.f;
#pragma unroll
    for (int c = 0; c < 4; c++) { e[c] = expf(sv[c] - m); sum += e[c]; }
#pragma unroll
    for (int o = 16; o; o >>= 1) sum += __shfl_xor_sync(0xffffffffu, sum, o);
    __shared__ float red2[4];
    if ((tid & 31) == 0) red2[tid >> 5] = sum;
    __syncthreads();
    sum = red2[0] + red2[1] + red2[2] + red2[3];
    float inv = 1.f / sum;
#pragma unroll
    for (int c = 0; c < 4; c++) {
        int j = tid + c*128;
        bool inband = (q < 128) ? (j < KBAND_) : (j >= 128);
        if (inband) {
            float p = e[c] * inv;
            hlf hi = __float2half_rn(p);
            Ph[(size_t)rowid*KW_ + j] = hi;
            Pl[(size_t)rowid*KW_ + j] = __float2half_rn(p - __half2float(hi));
        }
    }
}

// ---------------- compression ----------------
__global__ void compress64_k(const float* __restrict__ cin, const float* __restrict__ zin,
                             int ld, const float* __restrict__ bias, float* __restrict__ out) {
    int n = blockIdx.x;
    int c = threadIdx.x;  // 64 threads
    float z[MBLK_];
    float mx = -INFINITY;
#pragma unroll
    for (int m = 0; m < MBLK_; m++) {
        float v = zin[(size_t)(n*MBLK_ + m)*ld + c] + bias[m*CI_ + c];
        z[m] = v;
        mx = fmaxf(mx, v);
    }
    float sm = 0.f;
#pragma unroll
    for (int m = 0; m < MBLK_; m++) { float e = expf(z[m] - mx); z[m] = e; sm += e; }
    float acc = 0.f;
#pragma unroll
    for (int m = 0; m < MBLK_; m++) acc += z[m] * cin[(size_t)(n*MBLK_ + m)*ld + c];
    out[n*CI_ + c] = acc / sm;
}

__global__ void compress128_norm_k(const float* __restrict__ cin, const float* __restrict__ zin,
                                   int ld, const float* __restrict__ bias,
                                   const float* __restrict__ knw, float* __restrict__ out) {
    int n = blockIdx.x;
    int c = threadIdx.x;  // 128 threads
    float z[MBLK_];
    float mx = -INFINITY;
#pragma unroll
    for (int m = 0; m < MBLK_; m++) {
        float v = zin[(size_t)(n*MBLK_ + m)*ld + c] + bias[m*HD_ + c];
        z[m] = v;
        mx = fmaxf(mx, v);
    }
    float sm = 0.f;
#pragma unroll
    for (int m = 0; m < MBLK_; m++) { float e = expf(z[m] - mx); z[m] = e; sm += e; }
    float acc = 0.f;
#pragma unroll
    for (int m = 0; m < MBLK_; m++) acc += z[m] * cin[(size_t)(n*MBLK_ + m)*ld + c];
    float o = acc / sm;
    float ss = o*o;
#pragma unroll
    for (int oo = 16; oo; oo >>= 1) ss += __shfl_xor_sync(0xffffffffu, ss, oo);
    __shared__ float red[4];
    if ((c & 31) == 0) red[c >> 5] = ss;
    __syncthreads();
    float tot = red[0] + red[1] + red[2] + red[3];
    out[n*HD_ + c] = o * rsqrtf(tot * (1.f/HD_) + EPS_) * knw[c];
}

// ---------------- index scores + top-64 (JAX tie-break: smallest index) ----------------
__global__ void topk_k(const float* __restrict__ qi, const float* __restrict__ wih, int ldw,
                       const float* __restrict__ kcomp,
                       int* __restrict__ topidx, float* __restrict__ topval) {
    int t = blockIdx.x;
    int tid = threadIdx.x;  // 256 threads
    __shared__ float sc[NB_];
    __shared__ float qis[NIH_*CI_];
    __shared__ float wihs[NIH_];
    if (tid < NIH_*CI_) qis[tid] = qi[(size_t)t*NIH_*CI_ + tid];
    if (tid < NIH_)     wihs[tid] = wih[(size_t)t*ldw + tid];
    __syncthreads();
    int nvalid = (t >= MBLK_) ? ((t - MBLK_)/MBLK_ + 1) : 0;
    if (nvalid > NB_) nvalid = NB_;
    for (int n = tid; n < NB_; n += 256) {
        float s;
        if (n < nvalid) {
            s = 0.f;
            const float* kr = kcomp + n*CI_;
#pragma unroll
            for (int h = 0; h < NIH_; h++) {
                const float* qr = qis + h*CI_;
                float dsum = 0.f;
#pragma unroll 8
                for (int cc = 0; cc < CI_; cc++) dsum += qr[cc]*kr[cc];
                s += wihs[h] * fmaxf(dsum, 0.f);
            }
        } else {
            s = -INFINITY;
        }
        sc[n] = s;
    }
    __syncthreads();
    if (tid < 32) {
        for (int j = 0; j < TOPK_; j++) {
            float bv = -INFINITY;
            int bi = NB_;
            for (int n = tid; n < NB_; n += 32) {
                float v = sc[n];
                if (v > bv || (v == bv && n < bi)) { bv = v; bi = n; }
            }
#pragma unroll
            for (int o = 16; o; o >>= 1) {
                float ov = __shfl_xor_sync(0xffffffffu, bv, o);
                int   oi = __shfl_xor_sync(0xffffffffu, bi, o);
                if (ov > bv || (ov == bv && oi < bi)) { bv = ov; bi = oi; }
            }
            if (tid == 0) {
                if (bi >= NB_) { bi = 0; bv = -INFINITY; }
                else sc[bi] = __int_as_float(0x7fc00000);
                topidx[(size_t)t*TOPK_ + j] = bi;
                topval[(size_t)t*TOPK_ + j] = bv;
            }
            __syncwarp();
        }
    }
}

// ---------------- sparse attention over the 64 selected compressed blocks ----------------
__global__ void sparse_attn_k(const float* __restrict__ qT, const float* __restrict__ ckv,
                              const int* __restrict__ topidx, const float* __restrict__ topval,
                              float* __restrict__ attn) {
    int t = blockIdx.x;
    int tid = threadIdx.x;  // 128 threads, 4 warps
    __shared__ float skv[TOPK_][HD_ + 1];
    __shared__ float qs[NH_][HD_];
    __shared__ float ps[4][TOPK_];
    __shared__ int   sidx[TOPK_];
    __shared__ float svalid[TOPK_];
    __shared__ int   s_any;
    if (tid == 0) s_any = 0;
    __syncthreads();
    if (tid < TOPK_) {
        float v = topval[(size_t)t*TOPK_ + tid];
        int idx = topidx[(size_t)t*TOPK_ + tid];
        bool ok = (v > -1.0e38f);
        sidx[tid] = ok ? idx : 0;
        svalid[tid] = ok ? 1.f : 0.f;
        if (ok) s_any = 1;
    }
    __syncthreads();
    for (int k = 0; k < TOPK_; k++)
        skv[k][tid] = ckv[(size_t)sidx[k]*HD_ + tid];
    for (int i = tid; i < NH_*HD_; i += 128) {
        int hh = i >> 7;
        int dd = i & 127;
        qs[hh][dd] = qT[(size_t)hh*(T_*HD_) + (size_t)t*HD_ + dd];
    }
    __syncthreads();
    int w = tid >> 5;
    int lane = tid & 31;
    int any = s_any;
#pragma unroll
    for (int e = 0; e < 4; e++) {
        int hh = e*4 + w;
        float s0 = 0.f, s1 = 0.f;
        for (int d = 0; d < HD_; d++) {
            float qv = qs[hh][d];
            s0 += qv * skv[lane][d];
            s1 += qv * skv[lane + 32][d];
        }
        s0 = (svalid[lane]      > 0.f) ? s0*SCALE_ : NEG_;
        s1 = (svalid[lane + 32] > 0.f) ? s1*SCALE_ : NEG_;
        float mx = fmaxf(s0, s1);
#pragma unroll
        for (int o = 16; o; o >>= 1) mx = fmaxf(mx, __shfl_xor_sync(0xffffffffu, mx, o));
        float e0 = expf(s0 - mx);
        float e1 = expf(s1 - mx);
        float sum = e0 + e1;
#pragma unroll
        for (int o = 16; o; o >>= 1) sum += __shfl_xor_sync(0xffffffffu, sum, o);
        float inv = any ? (1.f/sum) : 0.f;
        ps[w][lane] = e0*inv;
        ps[w][lane + 32] = e1*inv;
        __syncwarp();
        float o0 = 0.f, o1 = 0.f, o2 = 0.f, o3 = 0.f;
        for (int k = 0; k < TOPK_; k++) {
            float p = ps[w][k];
            o0 += p*skv[k][lane];
            o1 += p*skv[k][lane + 32];
            o2 += p*skv[k][lane + 64];
            o3 += p*skv[k][lane + 96];
        }
        size_t base = (size_t)t*(NH_*HD_) + hh*HD_;
        attn[base + lane]      = o0;
        attn[base + lane + 32] = o1;
        attn[base + lane + 64] = o2;
        attn[base + lane + 96] = o3;
        __syncwarp();
    }
}

// ---------------- launch ----------------
static void cvt(const float* src, hlf* hi, hlf* lo, int n) {
    int n4 = n / 4;
    cvt_hilo_k<<<(n4 + 255)/256, 256>>>(src, hi, lo, n4);
}

extern "C" void kernel_launch(void* const* d_in, const int* in_sizes, int n_in,
                              void* d_out, int out_size) {
    static cudaStream_t sB = 0;
    static cudaEvent_t evRoot = 0, evA = 0, evB = 0;
    if (sB == 0) {
        cudaStreamCreateWithFlags(&sB, cudaStreamNonBlocking);
        cudaEventCreateWithFlags(&evRoot, cudaEventDisableTiming);
        cudaEventCreateWithFlags(&evA, cudaEventDisableTiming);
        cudaEventCreateWithFlags(&evB, cudaEventDisableTiming);
    }

    const float* h_        = (const float*)d_in[0];
    const float* w_qc      = (const float*)d_in[1];
    const float* w_qup     = (const float*)d_in[2];
    const float* kvc_w     = (const float*)d_in[3];
    const float* kvc_wz    = (const float*)d_in[4];
    const float* kvc_bias  = (const float*)d_in[5];
    const float* k_proj_w  = (const float*)d_in[6];
    const float* v_proj_w  = (const float*)d_in[7];
    const float* idx_c_w   = (const float*)d_in[8];
    const float* idx_c_wz  = (const float*)d_in[9];
    const float* idx_c_bias= (const float*)d_in[10];
    const float* w_dq      = (const float*)d_in[11];
    const float* w_iuq     = (const float*)d_in[12];
    const float* w_w       = (const float*)d_in[13];
    const float* q_norm_w  = (const float*)d_in[14];
    const float* k_norm_w  = (const float*)d_in[15];
    const float* group_w   = (const float*)d_in[16];
    const float* final_w   = (const float*)d_in[17];
    float* out = (float*)d_out;

    float *ccat, *scatw, *scat, *q, *qT, *qi, *kcomp, *ckv, *topval, *attn, *S;
    int* topidx;
    hlf *hh, *hl, *hch, *hcl, *qTh, *qTl, *KTh, *KTl, *Vph, *Vpl, *Ph, *Pl;
    hlf *attnh, *attnl;
    hlf *bcath, *bcatl, *wqch, *wqcl, *wquph, *wqupl, *gwh, *gwl, *fwh, *fwl, *wcath, *wcatl;
    cudaGetSymbolAddress((void**)&ccat,   g_ccat);
    cudaGetSymbolAddress((void**)&scatw,  g_scatw);
    cudaGetSymbolAddress((void**)&scat,   g_scat);
    cudaGetSymbolAddress((void**)&q,      g_q);
    cudaGetSymbolAddress((void**)&qT,     g_qT);
    cudaGetSymbolAddress((void**)&qi,     g_qi);
    cudaGetSymbolAddress((void**)&kcomp,  g_kcomp);
    cudaGetSymbolAddress((void**)&ckv,    g_ckv);
    cudaGetSymbolAddress((void**)&topidx, g_topidx);
    cudaGetSymbolAddress((void**)&topval, g_topval);
    cudaGetSymbolAddress((void**)&attn,   g_attn);
    cudaGetSymbolAddress((void**)&S,      g_S);
    cudaGetSymbolAddress((void**)&hh,     g_hh);
    cudaGetSymbolAddress((void**)&hl,     g_hl);
    cudaGetSymbolAddress((void**)&hch,    g_hch);
    cudaGetSymbolAddress((void**)&hcl,    g_hcl);
    cudaGetSymbolAddress((void**)&qTh,    g_qTh);
    cudaGetSymbolAddress((void**)&qTl,    g_qTl);
    cudaGetSymbolAddress((void**)&KTh,    g_KTh);
    cudaGetSymbolAddress((void**)&KTl,    g_KTl);
    cudaGetSymbolAddress((void**)&Vph,    g_Vph);
    cudaGetSymbolAddress((void**)&Vpl,    g_Vpl);
    cudaGetSymbolAddress((void**)&Ph,     g_Ph);
    cudaGetSymbolAddress((void**)&Pl,     g_Pl);
    cudaGetSymbolAddress((void**)&attnh,  g_attnh);
    cudaGetSymbolAddress((void**)&attnl,  g_attnl);
    cudaGetSymbolAddress((void**)&bcath,  g_bcath);
    cudaGetSymbolAddress((void**)&bcatl,  g_bcatl);
    cudaGetSymbolAddress((void**)&wqch,   g_wqch);
    cudaGetSymbolAddress((void**)&wqcl,   g_wqcl);
    cudaGetSymbolAddress((void**)&wquph,  g_wquph);
    cudaGetSymbolAddress((void**)&wqupl,  g_wqupl);
    cudaGetSymbolAddress((void**)&gwh,    g_gwh);
    cudaGetSymbolAddress((void**)&gwl,    g_gwl);
    cudaGetSymbolAddress((void**)&fwh,    g_fwh);
    cudaGetSymbolAddress((void**)&fwl,    g_fwl);
    cudaGetSymbolAddress((void**)&wcath,  g_wcath);
    cudaGetSymbolAddress((void**)&wcatl,  g_wcatl);

    // ===== fork stream B (fp32/FMA score chain) off the capture stream =====
    cudaEventRecord(evRoot, 0);
    cudaStreamWaitEvent(sB, evRoot, 0);

    // stream B: score projections -> compressions -> qi -> topk (FMA-bound)
    pack_scatw_k<<<(HID_*SCATN_ + 255)/256, 256, 0, sB>>>(idx_c_w, idx_c_wz, w_dq, w_w, scatw);
    launch_score(h_, scatw, scat, T_, SCATN_, HID_, HID_, SCATN_, SCATN_, sB);
    compress64_k<<<NB_, 64, 0, sB>>>(scat, scat + 64, SCATN_, idx_c_bias, kcomp);
    launch_score(scat + 128, w_iuq, qi, T_, NIH_*CI_, CI_, SCATN_, NIH_*CI_, NIH_*CI_, sB);
    topk_k<<<T_, 256, 0, sB>>>(qi, scat + 192, SCATN_, kcomp, topidx, topval);

    // stream A (capture stream): tensor chain
    pack_bcat_k<<<(HID_*BCATN_ + 255)/256, 256>>>(k_proj_w, v_proj_w, kvc_w, kvc_wz, bcath, bcatl);
    cvt(h_,    hh,   hl,   T_*HID_);
    cvt(w_qc,  wqch, wqcl, HID_*QC_);
    cvt(w_qup, wquph, wqupl, QC_*NH_*HD_);

    // fused smooth projections (tensor, 2-pass): Ccat = [swk|swv|kc|kz]
    launch_mma_t<0,0,1>(hh, hl, bcath, bcatl, ccat, (hlf*)0, (hlf*)0,
                        T_, BCATN_, HID_, HID_, BCATN_, BCATN_, 1, 0, 0, 0);

    // output-weight prep + Wcat = stack_g (gw_g @ final_g) (2-pass)
    cvt(group_w, gwh, gwl, G_*(NH_/G_)*HD_*DG_);
    cvt(final_w, fwh, fwl, G_*DG_*HID_);
    launch_mma_t<0,1,1>(gwh, gwl, fwh, fwl, S /*dummy*/, wcath, wcatl,
                        DG_, HID_, (NH_/G_)*HD_,
                        DG_, HID_, HID_,
                        G_, (long)512*512, (long)512*HID_, (long)512*HID_);

    // q pipeline (2-pass)
    launch_mma_t<0,1,1>(hh, hl, wqch, wqcl, S /*dummy*/, hch, hcl,
                        T_, QC_, HID_, HID_, QC_, QC_, 1, 0, 0, 0);
    launch_mma_t<0,0,1>(hch, hcl, wquph, wqupl, q, (hlf*)0, (hlf*)0,
                        T_, NH_*HD_, QC_, QC_, NH_*HD_, NH_*HD_, 1, 0, 0, 0);
    q_transform_k<<<dim3(NH_, T_), 128>>>(q, q_norm_w, qT, qTh, qTl);

    // swin K/V prep + kv compression
    k_transform_k<<<T_, 128>>>(ccat, BCATN_, k_norm_w, KTh, KTl);
    vpad_k<<<(T_*HD_ + 255)/256, 256>>>(ccat, Vph, Vpl);
    compress128_norm_k<<<NB_, 128>>>(ccat + 256, ccat + 384, BCATN_, kvc_bias, k_norm_w, ckv);

    // A has produced qT + ckv — let B run sparse attention while A does swin QK
    cudaEventRecord(evA, 0);
    cudaStreamWaitEvent(sB, evA, 0);
    sparse_attn_k<<<T_, 128, 0, sB>>>(qT, ckv, topidx, topval, attn);
    cudaEventRecord(evB, sB);

    // A: swin QK (band-limited, 2-pass) + masked softmax
    launch_mma_t<1,0,1>(qTh, qTl, KTh, KTl, S, (hlf*)0, (hlf*)0,
                        WIN_, KBAND_, HD_, HD_, KTLD_, KW_, NH_*NBW_, 0, 0, 0);
    swin_softmax_k<<<NH_*NBW_*WIN_, 128>>>(S, Ph, Pl);

    // join B (PV reads attn written by sparse_attn); PV band-limited K=384, 2-pass
    cudaStreamWaitEvent(0, evB, 0);
    launch_mma_t<2,2,1>(Ph, Pl, Vph, Vpl, attn, attnh, attnl,
                        WIN_, HD_, KBAND_, KW_, HD_, NH_*HD_, NH_*NBW_, 0, 0, 0);

    // fused output projection (2-pass): out = attn @ Wcat
    launch_mma_t<0,0,1>(attnh, attnl, wcath, wcatl, out, (hlf*)0, (hlf*)0,
                        T_, HID_, NH_*HD_, NH_*HD_, HID_, HID_, 1, 0, 0, 0);
}